// round 11
// baseline (speedup 1.0000x reference)
#include <cuda_runtime.h>
#include <cuda_bf16.h>
#include <cstdint>

#define Bv 4
#define Hh 16
#define Ss 1024
#define Dd 1024
#define HDd 64
#define NP 257
#define NPP 384
#define NROW (Bv*Ss)    // 4096
#define BHS (Bv*Hh*Ss)  // 65536

// ---------------- scratch (device globals: allocation-free) ----------------
__device__ __nv_bfloat16 g_qh[BHS * HDd];
__device__ __nv_bfloat16 g_ql[BHS * HDd];
__device__ __nv_bfloat16 g_kh[BHS * HDd];
__device__ __nv_bfloat16 g_kl[BHS * HDd];
__device__ __nv_bfloat16 g_vh[BHS * HDd];
__device__ __nv_bfloat16 g_vl[BHS * HDd];
__device__ __nv_bfloat16 g_rvh[272 * 64];
__device__ __nv_bfloat16 g_rvl[272 * 64];
__device__ __nv_bfloat16 g_rkh[NPP * 64];
__device__ __nv_bfloat16 g_rkl[NPP * 64];
__device__ __nv_bfloat16 g_xh[(size_t)NROW * Dd];
__device__ __nv_bfloat16 g_xl[(size_t)NROW * Dd];
__device__ __nv_bfloat16 g_wsp[8][(size_t)Dd * Dd];   // q,k,v,o hi/lo: [2z]=hi,[2z+1]=lo

// ====================== PTX helpers (family-portable only) ======================
__device__ __forceinline__ uint32_t smem_u32(const void* p) {
    uint32_t a;
    asm("{ .reg .u64 t; cvta.to.shared.u64 t, %1; cvt.u32.u64 %0, t; }" : "=r"(a) : "l"(p));
    return a;
}

#define LDMX4(r0, r1, r2, r3, addr) \
    asm volatile("ldmatrix.sync.aligned.m8n8.x4.shared.b16 {%0,%1,%2,%3}, [%4];" \
                 : "=r"(r0), "=r"(r1), "=r"(r2), "=r"(r3) : "r"(addr))

#define LDMX2(r0, r1, addr) \
    asm volatile("ldmatrix.sync.aligned.m8n8.x2.shared.b16 {%0,%1}, [%2];" \
                 : "=r"(r0), "=r"(r1) : "r"(addr))

#define LDMX4T(r0, r1, r2, r3, addr) \
    asm volatile("ldmatrix.sync.aligned.m8n8.x4.trans.shared.b16 {%0,%1,%2,%3}, [%4];" \
                 : "=r"(r0), "=r"(r1), "=r"(r2), "=r"(r3) : "r"(addr))

#define MMA16816(c, a, b) \
    asm volatile("mma.sync.aligned.m16n8k16.row.col.f32.bf16.bf16.f32 " \
                 "{%0,%1,%2,%3}, {%4,%5,%6,%7}, {%8,%9}, {%0,%1,%2,%3};" \
                 : "+f"((c)[0]), "+f"((c)[1]), "+f"((c)[2]), "+f"((c)[3]) \
                 : "r"((a)[0]), "r"((a)[1]), "r"((a)[2]), "r"((a)[3]), \
                   "r"((b)[0]), "r"((b)[1]))

#define CP_ASYNC16(s, g) \
    asm volatile("cp.async.cg.shared.global [%0], [%1], 16;" :: "r"(s), "l"(g))
#define CP_COMMIT() asm volatile("cp.async.commit_group;" ::: "memory")
#define CP_WAIT(n)  asm volatile("cp.async.wait_group %0;" :: "n"(n) : "memory")

// ---------------------------------------------------------------------------
// splits
// ---------------------------------------------------------------------------
__global__ void split_bf16_kernel(const float* __restrict__ in,
                                  __nv_bfloat16* __restrict__ hi,
                                  __nv_bfloat16* __restrict__ lo, int n4)
{
    int i = blockIdx.x * 512 + threadIdx.x;
#pragma unroll
    for (int rep = 0; rep < 2; rep++, i += 256) {
        if (i >= n4) return;
        float4 v = ((const float4*)in)[i];
        float vv[4] = {v.x, v.y, v.z, v.w};
        __nv_bfloat16 h[4], l[4];
#pragma unroll
        for (int j = 0; j < 4; j++) {
            h[j] = __float2bfloat16(vv[j]);
            l[j] = __float2bfloat16(vv[j] - __bfloat162float(h[j]));
        }
        ((__nv_bfloat162*)hi)[i * 2 + 0] = __nv_bfloat162(h[0], h[1]);
        ((__nv_bfloat162*)hi)[i * 2 + 1] = __nv_bfloat162(h[2], h[3]);
        ((__nv_bfloat162*)lo)[i * 2 + 0] = __nv_bfloat162(l[0], l[1]);
        ((__nv_bfloat162*)lo)[i * 2 + 1] = __nv_bfloat162(l[2], l[3]);
    }
}

__global__ void split_w_kernel(const float* __restrict__ W0, const float* __restrict__ W1,
                               const float* __restrict__ W2, const float* __restrict__ W3)
{
    int z = blockIdx.y;
    const float* in = (z == 0 ? W0 : z == 1 ? W1 : z == 2 ? W2 : W3);
    __nv_bfloat16* hi = g_wsp[2 * z];
    __nv_bfloat16* lo = g_wsp[2 * z + 1];
    int i = blockIdx.x * 512 + threadIdx.x;
#pragma unroll
    for (int rep = 0; rep < 2; rep++, i += 256) {
        float4 v = ((const float4*)in)[i];
        float vv[4] = {v.x, v.y, v.z, v.w};
        __nv_bfloat16 h[4], l[4];
#pragma unroll
        for (int j = 0; j < 4; j++) {
            h[j] = __float2bfloat16(vv[j]);
            l[j] = __float2bfloat16(vv[j] - __bfloat162float(h[j]));
        }
        ((__nv_bfloat162*)hi)[i * 2 + 0] = __nv_bfloat162(h[0], h[1]);
        ((__nv_bfloat162*)hi)[i * 2 + 1] = __nv_bfloat162(h[2], h[3]);
        ((__nv_bfloat162*)lo)[i * 2 + 0] = __nv_bfloat162(l[0], l[1]);
        ((__nv_bfloat162*)lo)[i * 2 + 1] = __nv_bfloat162(l[2], l[3]);
    }
}

__global__ void rel_prep(const float* __restrict__ rel_k, const float* __restrict__ rel_v)
{
    int idx = blockIdx.x * 256 + threadIdx.x;
    if (idx < NPP * 64) {
        int p = idx >> 6, d = idx & 63;
        float v = (p < NP) ? rel_k[p * 64 + d] : 0.f;
        __nv_bfloat16 h = __float2bfloat16(v);
        g_rkh[idx] = h;
        g_rkl[idx] = __float2bfloat16(v - __bfloat162float(h));
    }
    if (idx < 272 * 64) {
        int p = idx >> 6, d = idx & 63;
        float v = (p < NP) ? rel_v[p * 64 + d] : 0.f;
        __nv_bfloat16 h = __float2bfloat16(v);
        g_rvh[idx] = h;
        g_rvl[idx] = __float2bfloat16(v - __bfloat162float(h));
    }
}

// ---------------------------------------------------------------------------
// GEMM body: CTA tile 128x256, BK=32, 8 warps (wm2 x wn4, each 64x64),
// double-buffered, 1 barrier/chunk, 1 CTA/SM.
// ---------------------------------------------------------------------------
#define SPB 80
#define A_MAT (128 * SPB)           // 10240
#define B_MAT (256 * SPB)           // 20480
#define BUF_SM (2 * A_MAT + 2 * B_MAT)  // 61440
#define GEMM_SMEM (2 * BUF_SM)          // 122880

__device__ __forceinline__ void gemm_body(
    char* sm,
    const __nv_bfloat16* __restrict__ Ah_, const __nv_bfloat16* __restrict__ Al_,
    const __nv_bfloat16* __restrict__ Bh_, const __nv_bfloat16* __restrict__ Bl_,
    const float* __restrict__ bias, float* __restrict__ Cf,
    __nv_bfloat16* __restrict__ Ch, __nv_bfloat16* __restrict__ Cl, int headed)
{
    const uint32_t sb = smem_u32(sm);
    const int t    = threadIdx.x;
    const int wid  = t >> 5;
    const int lane = t & 31;
    const int m0 = blockIdx.y * 128;
    const int n0 = blockIdx.x * 256;
    const int wm = wid >> 2;        // 0..1 -> 64 m rows
    const int wn = wid & 3;         // 0..3 -> 64 n rows

    const char* gb0 = (const char*)(Ah_ + (size_t)m0 * 1024);
    const char* gb1 = (const char*)(Al_ + (size_t)m0 * 1024);
    const char* gb2 = (const char*)(Bh_ + (size_t)n0 * 1024);
    const char* gb3 = (const char*)(Bl_ + (size_t)n0 * 1024);

    // 48KB per chunk = 3072 x 16B; 12 iterations x 256 threads
    auto issue = [&](int chunk, int buf) {
#pragma unroll
        for (int it = 0; it < 12; it++) {
            int id = t + it * 256;
            uint32_t sa;
            const char* g;
            if (id < 1024) {            // A hi/lo: 2 x 128 rows x 4
                int mat = id >> 9;
                int row = (id >> 2) & 127;
                int c16 = id & 3;
                g = (mat == 0 ? gb0 : gb1) + (size_t)row * 2048 + chunk * 64 + c16 * 16;
                sa = sb + buf * BUF_SM + mat * A_MAT + row * SPB + c16 * 16;
            } else {                    // B hi/lo: 2 x 256 rows x 4
                int idb = id - 1024;
                int mat = idb >> 10;
                int row = (idb >> 2) & 255;
                int c16 = idb & 3;
                g = (mat == 0 ? gb2 : gb3) + (size_t)row * 2048 + chunk * 64 + c16 * 16;
                sa = sb + buf * BUF_SM + 2 * A_MAT + mat * B_MAT + row * SPB + c16 * 16;
            }
            CP_ASYNC16(sa, g);
        }
        CP_COMMIT();
    };

    float acc[4][8][4];
#pragma unroll
    for (int i = 0; i < 4; i++)
#pragma unroll
        for (int j = 0; j < 8; j++)
#pragma unroll
            for (int r = 0; r < 4; r++) acc[i][j][r] = 0.f;

    issue(0, 0);
    for (int c = 0; c < 32; c++) {
        const int buf = c & 1;
        CP_WAIT(0);
        __syncthreads();
        if (c + 1 < 32) issue(c + 1, buf ^ 1);

        const uint32_t Ahb = sb + buf * BUF_SM;
        const uint32_t Alb = Ahb + A_MAT;
        const uint32_t Bhb = Ahb + 2 * A_MAT;
        const uint32_t Blb = Bhb + B_MAT;

#pragma unroll
        for (int s = 0; s < 2; s++) {
            uint32_t ah[4][4], al[4][4];
            const int arow = wm * 64 + (lane & 15);
            const int acolB = (((lane >> 4) << 3) + s * 16) * 2;
#pragma unroll
            for (int mf = 0; mf < 4; mf++) {
                uint32_t ad = Ahb + (uint32_t)(arow + mf * 16) * SPB + acolB;
                LDMX4(ah[mf][0], ah[mf][1], ah[mf][2], ah[mf][3], ad);
                ad = Alb + (uint32_t)(arow + mf * 16) * SPB + acolB;
                LDMX4(al[mf][0], al[mf][1], al[mf][2], al[mf][3], ad);
            }
            uint32_t bh[8][2], bl[8][2];
            const int brow = wn * 64 + (lane & 7) + ((lane >> 4) << 3);
            const int bcolB = ((((lane >> 3) & 1) << 3) + s * 16) * 2;
#pragma unroll
            for (int g = 0; g < 4; g++) {
                uint32_t r0, r1, r2, r3;
                uint32_t bd = Bhb + (uint32_t)(brow + g * 16) * SPB + bcolB;
                LDMX4(r0, r1, r2, r3, bd);
                bh[g * 2][0] = r0; bh[g * 2][1] = r1;
                bh[g * 2 + 1][0] = r2; bh[g * 2 + 1][1] = r3;
                bd = Blb + (uint32_t)(brow + g * 16) * SPB + bcolB;
                LDMX4(r0, r1, r2, r3, bd);
                bl[g * 2][0] = r0; bl[g * 2][1] = r1;
                bl[g * 2 + 1][0] = r2; bl[g * 2 + 1][1] = r3;
            }
#pragma unroll
            for (int mf = 0; mf < 4; mf++)
#pragma unroll
                for (int nf = 0; nf < 8; nf++) {
                    MMA16816(acc[mf][nf], ah[mf], bh[nf]);
                    MMA16816(acc[mf][nf], ah[mf], bl[nf]);
                    MMA16816(acc[mf][nf], al[mf], bh[nf]);
                }
        }
    }

#pragma unroll
    for (int mf = 0; mf < 4; mf++) {
#pragma unroll
        for (int nf = 0; nf < 8; nf++) {
            int m = m0 + wm * 64 + mf * 16 + (lane >> 2);
            int n = n0 + wn * 64 + nf * 8 + (lane & 3) * 2;
            float p0 = acc[mf][nf][0] + bias[n];
            float p1 = acc[mf][nf][1] + bias[n + 1];
            float p2 = acc[mf][nf][2] + bias[n];
            float p3 = acc[mf][nf][3] + bias[n + 1];
            size_t off0, off1;
            if (headed) {
                int h = n >> 6, d = n & 63;
                int bb = m >> 10, s1 = m & 1023;
                off0 = ((((size_t)bb * Hh + h) << 10) + s1) * HDd + d;
                off1 = ((((size_t)bb * Hh + h) << 10) + s1 + 8) * HDd + d;
            } else {
                off0 = (size_t)m * 1024 + n;
                off1 = (size_t)(m + 8) * 1024 + n;
            }
            if (Cf) {
                *(float2*)(Cf + off0) = make_float2(p0, p1);
                *(float2*)(Cf + off1) = make_float2(p2, p3);
            }
            if (Ch) {
                __nv_bfloat16 h0 = __float2bfloat16(p0), h1 = __float2bfloat16(p1);
                __nv_bfloat16 h2 = __float2bfloat16(p2), h3 = __float2bfloat16(p3);
                *(__nv_bfloat162*)(Ch + off0) = __nv_bfloat162(h0, h1);
                *(__nv_bfloat162*)(Ch + off1) = __nv_bfloat162(h2, h3);
                __nv_bfloat16 l0 = __float2bfloat16(p0 - __bfloat162float(h0));
                __nv_bfloat16 l1 = __float2bfloat16(p1 - __bfloat162float(h1));
                __nv_bfloat16 l2 = __float2bfloat16(p2 - __bfloat162float(h2));
                __nv_bfloat16 l3 = __float2bfloat16(p3 - __bfloat162float(h3));
                *(__nv_bfloat162*)(Cl + off0) = __nv_bfloat162(l0, l1);
                *(__nv_bfloat162*)(Cl + off1) = __nv_bfloat162(l2, l3);
            }
        }
    }
}

__global__ __launch_bounds__(256, 1)
void gemm_qkv(const float* __restrict__ bq, const float* __restrict__ bk,
              const float* __restrict__ bv)
{
    extern __shared__ char sm[];
    int z = blockIdx.z;
    const float* bias = (z == 0 ? bq : z == 1 ? bk : bv);
    __nv_bfloat16* Ch = (z == 0 ? g_qh : z == 1 ? g_kh : g_vh);
    __nv_bfloat16* Cl = (z == 0 ? g_ql : z == 1 ? g_kl : g_vl);
    gemm_body(sm, g_xh, g_xl, g_wsp[2 * z], g_wsp[2 * z + 1], bias,
              nullptr, Ch, Cl, 1);
}

__global__ __launch_bounds__(256, 1)
void gemm_mma(const __nv_bfloat16* __restrict__ Ah_, const __nv_bfloat16* __restrict__ Al_,
              const __nv_bfloat16* __restrict__ Bh_, const __nv_bfloat16* __restrict__ Bl_,
              const float* __restrict__ bias, float* __restrict__ Cf)
{
    extern __shared__ char sm[];
    gemm_body(sm, Ah_, Al_, Bh_, Bl_, bias, Cf, nullptr, nullptr, 0);
}

// ---------------------------------------------------------------------------
// MMA attention core (unchanged from R10).
// ---------------------------------------------------------------------------
#define SSP  4112u
#define WRP  1104u
#define Q_OFF   0u
#define KV_OFF  9216u
#define KV_BUF  18432u
#define SS_OFF  64512u
#define WR_OFF  196096u
#define ATTN_SMEM 231424

__global__ __launch_bounds__(512, 1)
void attn_mma()
{
    extern __shared__ char sm[];
    const uint32_t sb = smem_u32(sm);
    const int t = threadIdx.x, lane = t & 31, wid = t >> 5;
    const int bh = blockIdx.y;
    const int i0 = blockIdx.x * 32;

    auto issue_tile = [&](const __nv_bfloat16* sh, const __nv_bfloat16* sl,
                          size_t row0, int nrows, uint32_t dst) {
#pragma unroll
        for (int it = 0; it < 2; it++) {
            int id = t + it * 512;
            if (id < nrows * 16) {
                int sel = id / (nrows * 8);
                int rid = id % (nrows * 8);
                int row = rid >> 3, c16 = rid & 7;
                const __nv_bfloat16* s = (sel ? sl : sh) + (row0 + row) * 64 + c16 * 8;
                CP_ASYNC16(dst + (uint32_t)sel * (nrows * 144) + row * 144 + c16 * 16, s);
            }
        }
        CP_COMMIT();
    };

    const size_t bhrow = (size_t)bh * 1024;

    issue_tile(g_qh, g_ql, bhrow + i0, 32, sb + Q_OFF);
    issue_tile(g_kh, g_kl, bhrow, 64, sb + KV_OFF);
    issue_tile(g_kh, g_kl, bhrow + 64, 64, sb + KV_OFF + KV_BUF);

    // ========= unified scores (g<16) + bias window (g>=16) pipeline ========
    {
        const int wq = wid >> 3;
        const int wk = wid & 7;
        uint32_t qhf[4][4], qlf[4][4];

        for (int g = 0; g < 21; g++) {
            if (g < 20) { CP_WAIT(1); } else { CP_WAIT(0); }
            __syncthreads();
            if (g + 2 < 21) {
                int tt = g + 2;
                uint32_t dst = sb + KV_OFF + (uint32_t)(tt % 3) * KV_BUF;
                if (tt < 16) issue_tile(g_kh, g_kl, bhrow + (size_t)tt * 64, 64, dst);
                else         issue_tile(g_rkh, g_rkl, (size_t)(tt - 16) * 64, 64, dst);
            }

            if (g == 0) {
#pragma unroll
                for (int s = 0; s < 4; s++) {
                    uint32_t a = sb + Q_OFF + (uint32_t)(wq * 16 + (lane & 15)) * 144
                               + (((lane >> 4) << 3) + s * 16) * 2;
                    LDMX4(qhf[s][0], qhf[s][1], qhf[s][2], qhf[s][3], a);
                    LDMX4(qlf[s][0], qlf[s][1], qlf[s][2], qlf[s][3], a + 4608);
                }
            }

            float a1[4] = {0.f,0.f,0.f,0.f}, a2[4] = {0.f,0.f,0.f,0.f}, a3[4] = {0.f,0.f,0.f,0.f};
            const uint32_t kb = sb + KV_OFF + (uint32_t)(g % 3) * KV_BUF;
#pragma unroll
            for (int s = 0; s < 4; s++) {
                uint32_t addr = kb + (uint32_t)(wk * 8 + (lane & 7)) * 144
                              + ((((lane >> 3) & 1) * 8) + s * 16) * 2;
                uint32_t bh2[2], bl2[2];
                LDMX2(bh2[0], bh2[1], addr);
                LDMX2(bl2[0], bl2[1], addr + 9216);
                MMA16816(a1, qhf[s], bh2);
                MMA16816(a2, qhf[s], bl2);
                MMA16816(a3, qlf[s], bh2);
            }
            int row = wq * 16 + (lane >> 2);
            if (g < 16) {
                int col = g * 64 + wk * 8 + (lane & 3) * 2;
                *(float2*)(sm + SS_OFF + (uint32_t)row * SSP + col * 4) =
                    make_float2(a1[0] + a2[0] + a3[0], a1[1] + a2[1] + a3[1]);
                *(float2*)(sm + SS_OFF + (uint32_t)(row + 8) * SSP + col * 4) =
                    make_float2(a1[2] + a2[2] + a3[2], a1[3] + a2[3] + a3[3]);
            } else {
                int col = (g - 16) * 64 + wk * 8 + (lane & 3) * 2;
                if (col <= 274) {
                    *(float2*)(sm + WR_OFF + (uint32_t)row * WRP + col * 4) =
                        make_float2(a1[0] + a2[0] + a3[0], a1[1] + a2[1] + a3[1]);
                    *(float2*)(sm + WR_OFF + (uint32_t)(row + 8) * WRP + col * 4) =
                        make_float2(a1[2] + a2[2] + a3[2], a1[3] + a2[3] + a3[3]);
                }
            }
        }
    }
    __syncthreads();

    // prefetch v tile 0 -> buf 2 (overlaps softmax)
    issue_tile(g_vh, g_vl, bhrow, 64, sb + KV_OFF + 2u * KV_BUF);

    // ================= softmax (fused bias, reg-resident), 2 rows/warp =====
    for (int rr = 0; rr < 2; rr++) {
        const int row = wid * 2 + rr;
        const int i = i0 + row;
        const float* rp = (const float*)(sm + SS_OFF + (uint32_t)row * SSP);
        const float* qwr = (const float*)(sm + WR_OFF + (uint32_t)row * WRP);
        float tmp[32];
#pragma unroll
        for (int kk = 0; kk < 32; kk++) {
            int j = lane + kk * 32;
            int rel = j - i;
            rel = rel < -128 ? -128 : (rel > 128 ? 128 : rel);
            tmp[kk] = (rp[j] + qwr[rel + 128]) * 0.125f;
        }
        float mx = -1e30f;
#pragma unroll
        for (int kk = 0; kk < 32; kk++) mx = fmaxf(mx, tmp[kk]);
#pragma unroll
        for (int o = 16; o > 0; o >>= 1) mx = fmaxf(mx, __shfl_xor_sync(0xffffffffu, mx, o));
        float sum = 0.f;
#pragma unroll
        for (int kk = 0; kk < 32; kk++) { tmp[kk] = __expf(tmp[kk] - mx); sum += tmp[kk]; }
#pragma unroll
        for (int o = 16; o > 0; o >>= 1) sum += __shfl_xor_sync(0xffffffffu, sum, o);
        const float inv = 1.f / sum;

        __syncwarp();
        uint32_t* wrz = (uint32_t*)(sm + WR_OFF + (uint32_t)row * WRP);
        for (int idx = lane; idx < 276; idx += 32) wrz[idx] = 0u;
        __syncwarp();

        __nv_bfloat16* wh_ = (__nv_bfloat16*)wrz;
        __nv_bfloat16* wl_ = wh_ + 280;
        float s0 = 0.f, s2 = 0.f;
#pragma unroll
        for (int kk = 0; kk < 32; kk++) {
            int j = lane + kk * 32;
            float w = tmp[kk] * inv;
            __nv_bfloat16 h = __float2bfloat16(w);
            __nv_bfloat16 l = __float2bfloat16(w - __bfloat162float(h));
            *(__nv_bfloat16*)(sm + SS_OFF + (uint32_t)row * SSP + j * 2) = h;
            *(__nv_bfloat16*)(sm + SS_OFF + (uint32_t)row * SSP + 2064 + j * 2) = l;
            int dlt = j - i;
            if (dlt <= -128)      s0 += w;
            else if (dlt >= 128)  s2 += w;
            else { wh_[dlt + 128] = h; wl_[dlt + 128] = l; }
        }
#pragma unroll
        for (int o = 16; o > 0; o >>= 1) s0 += __shfl_xor_sync(0xffffffffu, s0, o);
#pragma unroll
        for (int o = 16; o > 0; o >>= 1) s2 += __shfl_xor_sync(0xffffffffu, s2, o);
        __syncwarp();
        if (lane == 0) {
            __nv_bfloat16 h0 = __float2bfloat16(s0);
            wh_[0] = h0; wl_[0] = __float2bfloat16(s0 - __bfloat162float(h0));
            __nv_bfloat16 h2 = __float2bfloat16(s2);
            wh_[256] = h2; wl_[256] = __float2bfloat16(s2 - __bfloat162float(h2));
        }
    }

    // ================= PV: warp (wm2, wn4 n16, ws2 k-split) ================
    const int wm = wid >> 3;
    const int wn = (wid >> 1) & 3;
    const int ws = wid & 1;

    auto issue_pv = [&](int tt) {
        uint32_t dst = sb + KV_OFF + (uint32_t)((tt + 2) % 3) * KV_BUF;
        if (tt < 16) issue_tile(g_vh, g_vl, bhrow + (size_t)tt * 64, 64, dst);
        else         issue_tile(g_rvh, g_rvl, (size_t)(tt - 16) * 64,
                                (tt == 20) ? 16 : 64, dst);
    };

    float o1[2][4] = {{0.f,0.f,0.f,0.f},{0.f,0.f,0.f,0.f}};
    float o2[2][4] = {{0.f,0.f,0.f,0.f},{0.f,0.f,0.f,0.f}};
    float o3[2][4] = {{0.f,0.f,0.f,0.f},{0.f,0.f,0.f,0.f}};

    for (int vt = 0; vt < 21; vt++) {
        if (vt == 0 || vt == 20) { CP_WAIT(0); } else { CP_WAIT(1); }
        __syncthreads();
        if (vt == 0)            { issue_pv(1); issue_pv(2); }
        else if (vt + 2 <= 20)  issue_pv(vt + 2);

        const uint32_t vb = sb + KV_OFF + (uint32_t)((vt + 2) % 3) * KV_BUF;
        const int nsi = (vt == 20) ? ((ws == 0) ? 1 : 0) : 2;
        const uint32_t nrowsB = (vt == 20) ? 16u : 64u;
#pragma unroll 2
        for (int si = 0; si < nsi; si++) {
            const int s = (vt == 20) ? 0 : (ws * 2 + si);
            uint32_t awh[4], awl[4];
            if (vt < 16) {
                uint32_t aaddr = sb + SS_OFF + (uint32_t)(wm * 16 + (lane & 15)) * SSP
                               + (((lane >> 4) << 3) + vt * 64 + s * 16) * 2;
                LDMX4(awh[0], awh[1], awh[2], awh[3], aaddr);
                LDMX4(awl[0], awl[1], awl[2], awl[3], aaddr + 2064);
            } else {
                uint32_t abase = sb + WR_OFF + (uint32_t)(wm * 16 + (lane & 15)) * WRP;
                uint32_t acol = (((lane >> 4) << 3) + (vt - 16) * 64 + s * 16) * 2;
                LDMX4(awh[0], awh[1], awh[2], awh[3], abase + acol);
                LDMX4(awl[0], awl[1], awl[2], awl[3], abase + 560 + acol);
            }
            uint32_t baddr = vb + (uint32_t)(s * 16 + (lane & 7) + ((lane >> 3) & 1) * 8) * 144
                           + (uint32_t)(wn * 16 + ((lane >> 4) << 3)) * 2;
            uint32_t bvh[4], bvl[4];
            LDMX4T(bvh[0], bvh[1], bvh[2], bvh[3], baddr);
            LDMX4T(bvl[0], bvl[1], bvl[2], bvl[3], baddr + nrowsB * 144u);
#pragma unroll
            for (int nf = 0; nf < 2; nf++) {
                MMA16816(o1[nf], awh, (&bvh[nf * 2]));
                MMA16816(o2[nf], awh, (&bvl[nf * 2]));
                MMA16816(o3[nf], awl, (&bvh[nf * 2]));
            }
        }
    }

    float of[2][4];
#pragma unroll
    for (int nf = 0; nf < 2; nf++)
#pragma unroll
        for (int r = 0; r < 4; r++)
            of[nf][r] = o1[nf][r] + o2[nf][r] + o3[nf][r];

    __syncthreads();
    float* red = (float*)(sm + KV_OFF);
    const int widx = wm * 4 + wn;
    if (ws == 1) {
#pragma unroll
        for (int nf = 0; nf < 2; nf++)
            *(float4*)&red[((widx * 2 + nf) * 32 + lane) * 4] =
                make_float4(of[nf][0], of[nf][1], of[nf][2], of[nf][3]);
    }
    __syncthreads();
    if (ws == 0) {
        const int bb = bh >> 4, h = bh & 15;
        int row = i0 + wm * 16 + (lane >> 2);
#pragma unroll
        for (int nf = 0; nf < 2; nf++) {
            float4 v = *(const float4*)&red[((widx * 2 + nf) * 32 + lane) * 4];
            float f0 = of[nf][0] + v.x, f1 = of[nf][1] + v.y;
            float f2 = of[nf][2] + v.z, f3 = of[nf][3] + v.w;
            int d = h * 64 + wn * 16 + nf * 8 + (lane & 3) * 2;
            size_t off0 = ((size_t)bb * 1024 + row) * 1024 + d;
            size_t off1 = off0 + 8 * 1024;
            __nv_bfloat16 h0 = __float2bfloat16(f0), h1 = __float2bfloat16(f1);
            __nv_bfloat16 h2 = __float2bfloat16(f2), h3 = __float2bfloat16(f3);
            *(__nv_bfloat162*)(g_xh + off0) = __nv_bfloat162(h0, h1);
            *(__nv_bfloat162*)(g_xh + off1) = __nv_bfloat162(h2, h3);
            __nv_bfloat16 l0 = __float2bfloat16(f0 - __bfloat162float(h0));
            __nv_bfloat16 l1 = __float2bfloat16(f1 - __bfloat162float(h1));
            __nv_bfloat16 l2 = __float2bfloat16(f2 - __bfloat162float(h2));
            __nv_bfloat16 l3 = __float2bfloat16(f3 - __bfloat162float(h3));
            *(__nv_bfloat162*)(g_xl + off0) = __nv_bfloat162(l0, l1);
            *(__nv_bfloat162*)(g_xl + off1) = __nv_bfloat162(l2, l3);
        }
    }
}

// ---------------------------------------------------------------------------
extern "C" void kernel_launch(void* const* d_in, const int* in_sizes, int n_in,
                              void* d_out, int out_size)
{
    const float* x     = (const float*)d_in[0];
    const float* Wq    = (const float*)d_in[1];
    const float* bq    = (const float*)d_in[2];
    const float* Wk    = (const float*)d_in[3];
    const float* bk    = (const float*)d_in[4];
    const float* Wv    = (const float*)d_in[5];
    const float* bv    = (const float*)d_in[6];
    const float* Wo    = (const float*)d_in[7];
    const float* bo    = (const float*)d_in[8];
    const float* rel_k = (const float*)d_in[9];
    const float* rel_v = (const float*)d_in[10];

    __nv_bfloat16 *xh, *xl, *woh, *wol;
    cudaGetSymbolAddress((void**)&xh,  g_xh);
    cudaGetSymbolAddress((void**)&xl,  g_xl);
    cudaGetSymbolAddress((void**)&woh, g_wsp);
    wol = woh + 7 * (size_t)Dd * Dd;
    woh = woh + 6 * (size_t)Dd * Dd;

    cudaFuncSetAttribute(gemm_qkv, cudaFuncAttributeMaxDynamicSharedMemorySize, GEMM_SMEM);
    cudaFuncSetAttribute(gemm_mma, cudaFuncAttributeMaxDynamicSharedMemorySize, GEMM_SMEM);
    cudaFuncSetAttribute(attn_mma, cudaFuncAttributeMaxDynamicSharedMemorySize, ATTN_SMEM);

    dim3 blk(256);

    // prep: x split, weight splits, rel tables
    split_bf16_kernel<<<2048, blk>>>(x, xh, xl, (NROW * Dd) / 4);
    split_w_kernel<<<dim3(512, 4), blk>>>(Wq, Wk, Wv, Wo);
    rel_prep<<<96, blk>>>(rel_k, rel_v);

    // merged QKV projections (384 CTAs, 128x256 tiles)
    gemm_qkv<<<dim3(Dd / 256, NROW / 128, 3), blk, GEMM_SMEM>>>(bq, bk, bv);

    // attention core
    attn_mma<<<dim3(Ss / 32, Bv * Hh), 512, ATTN_SMEM>>>();

    // output projection -> d_out (128 CTAs)
    gemm_mma<<<dim3(Dd / 256, NROW / 128), blk, GEMM_SMEM>>>(xh, xl, woh, wol, bo, (float*)d_out);
}

// round 12
// speedup vs baseline: 1.0271x; 1.0271x over previous
#include <cuda_runtime.h>
#include <cuda_bf16.h>
#include <cstdint>

#define Bv 4
#define Hh 16
#define Ss 1024
#define Dd 1024
#define HDd 64
#define NP 257
#define NPP 384
#define NROW (Bv*Ss)    // 4096
#define BHS (Bv*Hh*Ss)  // 65536

// ---------------- scratch (device globals: allocation-free) ----------------
__device__ __nv_bfloat16 g_qh[BHS * HDd];
__device__ __nv_bfloat16 g_ql[BHS * HDd];
__device__ __nv_bfloat16 g_kh[BHS * HDd];
__device__ __nv_bfloat16 g_kl[BHS * HDd];
__device__ __nv_bfloat16 g_vh[BHS * HDd];
__device__ __nv_bfloat16 g_vl[BHS * HDd];
__device__ __nv_bfloat16 g_rvh[272 * 64];
__device__ __nv_bfloat16 g_rvl[272 * 64];
__device__ __nv_bfloat16 g_rkh[NPP * 64];
__device__ __nv_bfloat16 g_rkl[NPP * 64];
__device__ __nv_bfloat16 g_xh[(size_t)NROW * Dd];
__device__ __nv_bfloat16 g_xl[(size_t)NROW * Dd];
__device__ __nv_bfloat16 g_wsp[8][(size_t)Dd * Dd];   // q,k,v,o hi/lo: [2z]=hi,[2z+1]=lo

// ====================== PTX helpers (family-portable only) ======================
__device__ __forceinline__ uint32_t smem_u32(const void* p) {
    uint32_t a;
    asm("{ .reg .u64 t; cvta.to.shared.u64 t, %1; cvt.u32.u64 %0, t; }" : "=r"(a) : "l"(p));
    return a;
}

#define LDMX4(r0, r1, r2, r3, addr) \
    asm volatile("ldmatrix.sync.aligned.m8n8.x4.shared.b16 {%0,%1,%2,%3}, [%4];" \
                 : "=r"(r0), "=r"(r1), "=r"(r2), "=r"(r3) : "r"(addr))

#define LDMX2(r0, r1, addr) \
    asm volatile("ldmatrix.sync.aligned.m8n8.x2.shared.b16 {%0,%1}, [%2];" \
                 : "=r"(r0), "=r"(r1) : "r"(addr))

#define LDMX4T(r0, r1, r2, r3, addr) \
    asm volatile("ldmatrix.sync.aligned.m8n8.x4.trans.shared.b16 {%0,%1,%2,%3}, [%4];" \
                 : "=r"(r0), "=r"(r1), "=r"(r2), "=r"(r3) : "r"(addr))

#define MMA16816(c, a, b) \
    asm volatile("mma.sync.aligned.m16n8k16.row.col.f32.bf16.bf16.f32 " \
                 "{%0,%1,%2,%3}, {%4,%5,%6,%7}, {%8,%9}, {%0,%1,%2,%3};" \
                 : "+f"((c)[0]), "+f"((c)[1]), "+f"((c)[2]), "+f"((c)[3]) \
                 : "r"((a)[0]), "r"((a)[1]), "r"((a)[2]), "r"((a)[3]), \
                   "r"((b)[0]), "r"((b)[1]))

#define CP_ASYNC16(s, g) \
    asm volatile("cp.async.cg.shared.global [%0], [%1], 16;" :: "r"(s), "l"(g))
#define CP_COMMIT() asm volatile("cp.async.commit_group;" ::: "memory")
#define CP_WAIT(n)  asm volatile("cp.async.wait_group %0;" :: "n"(n) : "memory")

// ---------------------------------------------------------------------------
// splits
// ---------------------------------------------------------------------------
__global__ void split_bf16_kernel(const float* __restrict__ in,
                                  __nv_bfloat16* __restrict__ hi,
                                  __nv_bfloat16* __restrict__ lo, int n4)
{
    int i = blockIdx.x * 512 + threadIdx.x;
#pragma unroll
    for (int rep = 0; rep < 2; rep++, i += 256) {
        if (i >= n4) return;
        float4 v = ((const float4*)in)[i];
        float vv[4] = {v.x, v.y, v.z, v.w};
        __nv_bfloat16 h[4], l[4];
#pragma unroll
        for (int j = 0; j < 4; j++) {
            h[j] = __float2bfloat16(vv[j]);
            l[j] = __float2bfloat16(vv[j] - __bfloat162float(h[j]));
        }
        ((__nv_bfloat162*)hi)[i * 2 + 0] = __nv_bfloat162(h[0], h[1]);
        ((__nv_bfloat162*)hi)[i * 2 + 1] = __nv_bfloat162(h[2], h[3]);
        ((__nv_bfloat162*)lo)[i * 2 + 0] = __nv_bfloat162(l[0], l[1]);
        ((__nv_bfloat162*)lo)[i * 2 + 1] = __nv_bfloat162(l[2], l[3]);
    }
}

__global__ void split_w_kernel(const float* __restrict__ W0, const float* __restrict__ W1,
                               const float* __restrict__ W2, const float* __restrict__ W3)
{
    int z = blockIdx.y;
    const float* in = (z == 0 ? W0 : z == 1 ? W1 : z == 2 ? W2 : W3);
    __nv_bfloat16* hi = g_wsp[2 * z];
    __nv_bfloat16* lo = g_wsp[2 * z + 1];
    int i = blockIdx.x * 512 + threadIdx.x;
#pragma unroll
    for (int rep = 0; rep < 2; rep++, i += 256) {
        float4 v = ((const float4*)in)[i];
        float vv[4] = {v.x, v.y, v.z, v.w};
        __nv_bfloat16 h[4], l[4];
#pragma unroll
        for (int j = 0; j < 4; j++) {
            h[j] = __float2bfloat16(vv[j]);
            l[j] = __float2bfloat16(vv[j] - __bfloat162float(h[j]));
        }
        ((__nv_bfloat162*)hi)[i * 2 + 0] = __nv_bfloat162(h[0], h[1]);
        ((__nv_bfloat162*)hi)[i * 2 + 1] = __nv_bfloat162(h[2], h[3]);
        ((__nv_bfloat162*)lo)[i * 2 + 0] = __nv_bfloat162(l[0], l[1]);
        ((__nv_bfloat162*)lo)[i * 2 + 1] = __nv_bfloat162(l[2], l[3]);
    }
}

__global__ void rel_prep(const float* __restrict__ rel_k, const float* __restrict__ rel_v)
{
    int idx = blockIdx.x * 256 + threadIdx.x;
    if (idx < NPP * 64) {
        int p = idx >> 6, d = idx & 63;
        float v = (p < NP) ? rel_k[p * 64 + d] : 0.f;
        __nv_bfloat16 h = __float2bfloat16(v);
        g_rkh[idx] = h;
        g_rkl[idx] = __float2bfloat16(v - __bfloat162float(h));
    }
    if (idx < 272 * 64) {
        int p = idx >> 6, d = idx & 63;
        float v = (p < NP) ? rel_v[p * 64 + d] : 0.f;
        __nv_bfloat16 h = __float2bfloat16(v);
        g_rvh[idx] = h;
        g_rvl[idx] = __float2bfloat16(v - __bfloat162float(h));
    }
}

// ---------------------------------------------------------------------------
// GEMM body (R10 proven config): 128x128 tile, BK=32, 8 warps (wm2 x wn4,
// each 64x32), double buffer, 1 barrier/chunk, 2 CTAs/SM.
// ---------------------------------------------------------------------------
#define SPB 80
#define MAT_SM (128 * SPB)
#define BUF_SM (4 * MAT_SM)
#define GEMM_SMEM (2 * BUF_SM)

__device__ __forceinline__ void gemm_body(
    char* sm,
    const __nv_bfloat16* __restrict__ Ah_, const __nv_bfloat16* __restrict__ Al_,
    const __nv_bfloat16* __restrict__ Bh_, const __nv_bfloat16* __restrict__ Bl_,
    const float* __restrict__ bias, float* __restrict__ Cf,
    __nv_bfloat16* __restrict__ Ch, __nv_bfloat16* __restrict__ Cl, int headed)
{
    const uint32_t sb = smem_u32(sm);
    const int t    = threadIdx.x;
    const int wid  = t >> 5;
    const int lane = t & 31;
    const int m0 = blockIdx.y * 128;
    const int n0 = blockIdx.x * 128;
    const int wm = wid >> 2;
    const int wn = wid & 3;

    const char* gb0 = (const char*)(Ah_ + (size_t)m0 * 1024);
    const char* gb1 = (const char*)(Al_ + (size_t)m0 * 1024);
    const char* gb2 = (const char*)(Bh_ + (size_t)n0 * 1024);
    const char* gb3 = (const char*)(Bl_ + (size_t)n0 * 1024);

    auto issue = [&](int chunk, int buf) {
#pragma unroll
        for (int it = 0; it < 8; it++) {
            int id  = t + it * 256;
            int mat = id >> 9;
            int row = (id >> 2) & 127;
            int c16 = id & 3;
            const char* g = (mat == 0 ? gb0 : mat == 1 ? gb1 : mat == 2 ? gb2 : gb3);
            uint32_t sa = sb + buf * BUF_SM + mat * MAT_SM + row * SPB + c16 * 16;
            CP_ASYNC16(sa, g + (size_t)row * 2048 + chunk * 64 + c16 * 16);
        }
        CP_COMMIT();
    };

    float acc[4][4][4];
#pragma unroll
    for (int i = 0; i < 4; i++)
#pragma unroll
        for (int j = 0; j < 4; j++)
#pragma unroll
            for (int r = 0; r < 4; r++) acc[i][j][r] = 0.f;

    issue(0, 0);
    for (int c = 0; c < 32; c++) {
        const int buf = c & 1;
        CP_WAIT(0);
        __syncthreads();
        if (c + 1 < 32) issue(c + 1, buf ^ 1);

        const uint32_t Ahb = sb + buf * BUF_SM;
        const uint32_t Alb = Ahb + MAT_SM;
        const uint32_t Bhb = Ahb + 2 * MAT_SM;
        const uint32_t Blb = Ahb + 3 * MAT_SM;

#pragma unroll
        for (int s = 0; s < 2; s++) {
            uint32_t ah[4][4], al[4][4];
            const int arow = wm * 64 + (lane & 15);
            const int acolB = (((lane >> 4) << 3) + s * 16) * 2;
#pragma unroll
            for (int mf = 0; mf < 4; mf++) {
                uint32_t ad = Ahb + (uint32_t)(arow + mf * 16) * SPB + acolB;
                LDMX4(ah[mf][0], ah[mf][1], ah[mf][2], ah[mf][3], ad);
                ad = Alb + (uint32_t)(arow + mf * 16) * SPB + acolB;
                LDMX4(al[mf][0], al[mf][1], al[mf][2], al[mf][3], ad);
            }
            uint32_t bh[4][2], bl[4][2];
            const int brow = wn * 32 + (lane & 7) + ((lane >> 4) << 3);
            const int bcolB = ((((lane >> 3) & 1) << 3) + s * 16) * 2;
#pragma unroll
            for (int g = 0; g < 2; g++) {
                uint32_t r0, r1, r2, r3;
                uint32_t bd = Bhb + (uint32_t)(brow + g * 16) * SPB + bcolB;
                LDMX4(r0, r1, r2, r3, bd);
                bh[g * 2][0] = r0; bh[g * 2][1] = r1;
                bh[g * 2 + 1][0] = r2; bh[g * 2 + 1][1] = r3;
                bd = Blb + (uint32_t)(brow + g * 16) * SPB + bcolB;
                LDMX4(r0, r1, r2, r3, bd);
                bl[g * 2][0] = r0; bl[g * 2][1] = r1;
                bl[g * 2 + 1][0] = r2; bl[g * 2 + 1][1] = r3;
            }
#pragma unroll
            for (int mf = 0; mf < 4; mf++)
#pragma unroll
                for (int nf = 0; nf < 4; nf++) {
                    MMA16816(acc[mf][nf], ah[mf], bh[nf]);
                    MMA16816(acc[mf][nf], ah[mf], bl[nf]);
                    MMA16816(acc[mf][nf], al[mf], bh[nf]);
                }
        }
    }

#pragma unroll
    for (int mf = 0; mf < 4; mf++) {
#pragma unroll
        for (int nf = 0; nf < 4; nf++) {
            int m = m0 + wm * 64 + mf * 16 + (lane >> 2);
            int n = n0 + wn * 32 + nf * 8 + (lane & 3) * 2;
            float p0 = acc[mf][nf][0] + bias[n];
            float p1 = acc[mf][nf][1] + bias[n + 1];
            float p2 = acc[mf][nf][2] + bias[n];
            float p3 = acc[mf][nf][3] + bias[n + 1];
            size_t off0, off1;
            if (headed) {
                int h = n >> 6, d = n & 63;
                int bb = m >> 10, s1 = m & 1023;
                off0 = ((((size_t)bb * Hh + h) << 10) + s1) * HDd + d;
                off1 = ((((size_t)bb * Hh + h) << 10) + s1 + 8) * HDd + d;
            } else {
                off0 = (size_t)m * 1024 + n;
                off1 = (size_t)(m + 8) * 1024 + n;
            }
            if (Cf) {
                *(float2*)(Cf + off0) = make_float2(p0, p1);
                *(float2*)(Cf + off1) = make_float2(p2, p3);
            }
            if (Ch) {
                __nv_bfloat16 h0 = __float2bfloat16(p0), h1 = __float2bfloat16(p1);
                __nv_bfloat16 h2 = __float2bfloat16(p2), h3 = __float2bfloat16(p3);
                *(__nv_bfloat162*)(Ch + off0) = __nv_bfloat162(h0, h1);
                *(__nv_bfloat162*)(Ch + off1) = __nv_bfloat162(h2, h3);
                __nv_bfloat16 l0 = __float2bfloat16(p0 - __bfloat162float(h0));
                __nv_bfloat16 l1 = __float2bfloat16(p1 - __bfloat162float(h1));
                __nv_bfloat16 l2 = __float2bfloat16(p2 - __bfloat162float(h2));
                __nv_bfloat16 l3 = __float2bfloat16(p3 - __bfloat162float(h3));
                *(__nv_bfloat162*)(Cl + off0) = __nv_bfloat162(l0, l1);
                *(__nv_bfloat162*)(Cl + off1) = __nv_bfloat162(l2, l3);
            }
        }
    }
}

__global__ __launch_bounds__(256, 2)
void gemm_qkv(const float* __restrict__ bq, const float* __restrict__ bk,
              const float* __restrict__ bv)
{
    extern __shared__ char sm[];
    int z = blockIdx.z;
    const float* bias = (z == 0 ? bq : z == 1 ? bk : bv);
    __nv_bfloat16* Ch = (z == 0 ? g_qh : z == 1 ? g_kh : g_vh);
    __nv_bfloat16* Cl = (z == 0 ? g_ql : z == 1 ? g_kl : g_vl);
    gemm_body(sm, g_xh, g_xl, g_wsp[2 * z], g_wsp[2 * z + 1], bias,
              nullptr, Ch, Cl, 1);
}

__global__ __launch_bounds__(256, 2)
void gemm_mma(const __nv_bfloat16* __restrict__ Ah_, const __nv_bfloat16* __restrict__ Al_,
              const __nv_bfloat16* __restrict__ Bh_, const __nv_bfloat16* __restrict__ Bl_,
              const float* __restrict__ bias, float* __restrict__ Cf)
{
    extern __shared__ char sm[];
    gemm_body(sm, Ah_, Al_, Bh_, Bl_, bias, Cf, nullptr, nullptr, 0);
}

// ---------------------------------------------------------------------------
// MMA attention core. PV re-tiled to (wm2, wn2 n=32, ws4 k-split):
// fragment LDS per tile 64KB -> 48KB at identical MMA count.
// ---------------------------------------------------------------------------
#define SSP  4112u
#define WRP  1104u
#define Q_OFF   0u
#define KV_OFF  9216u
#define KV_BUF  18432u
#define SS_OFF  64512u
#define WR_OFF  196096u
#define ATTN_SMEM 231424

__global__ __launch_bounds__(512, 1)
void attn_mma()
{
    extern __shared__ char sm[];
    const uint32_t sb = smem_u32(sm);
    const int t = threadIdx.x, lane = t & 31, wid = t >> 5;
    const int bh = blockIdx.y;
    const int i0 = blockIdx.x * 32;

    auto issue_tile = [&](const __nv_bfloat16* sh, const __nv_bfloat16* sl,
                          size_t row0, int nrows, uint32_t dst) {
#pragma unroll
        for (int it = 0; it < 2; it++) {
            int id = t + it * 512;
            if (id < nrows * 16) {
                int sel = id / (nrows * 8);
                int rid = id % (nrows * 8);
                int row = rid >> 3, c16 = rid & 7;
                const __nv_bfloat16* s = (sel ? sl : sh) + (row0 + row) * 64 + c16 * 8;
                CP_ASYNC16(dst + (uint32_t)sel * (nrows * 144) + row * 144 + c16 * 16, s);
            }
        }
        CP_COMMIT();
    };

    const size_t bhrow = (size_t)bh * 1024;

    issue_tile(g_qh, g_ql, bhrow + i0, 32, sb + Q_OFF);
    issue_tile(g_kh, g_kl, bhrow, 64, sb + KV_OFF);
    issue_tile(g_kh, g_kl, bhrow + 64, 64, sb + KV_OFF + KV_BUF);

    // ========= unified scores (g<16) + bias window (g>=16) pipeline ========
    {
        const int wq = wid >> 3;
        const int wk = wid & 7;
        uint32_t qhf[4][4], qlf[4][4];

        for (int g = 0; g < 21; g++) {
            if (g < 20) { CP_WAIT(1); } else { CP_WAIT(0); }
            __syncthreads();
            if (g + 2 < 21) {
                int tt = g + 2;
                uint32_t dst = sb + KV_OFF + (uint32_t)(tt % 3) * KV_BUF;
                if (tt < 16) issue_tile(g_kh, g_kl, bhrow + (size_t)tt * 64, 64, dst);
                else         issue_tile(g_rkh, g_rkl, (size_t)(tt - 16) * 64, 64, dst);
            }

            if (g == 0) {
#pragma unroll
                for (int s = 0; s < 4; s++) {
                    uint32_t a = sb + Q_OFF + (uint32_t)(wq * 16 + (lane & 15)) * 144
                               + (((lane >> 4) << 3) + s * 16) * 2;
                    LDMX4(qhf[s][0], qhf[s][1], qhf[s][2], qhf[s][3], a);
                    LDMX4(qlf[s][0], qlf[s][1], qlf[s][2], qlf[s][3], a + 4608);
                }
            }

            float a1[4] = {0.f,0.f,0.f,0.f}, a2[4] = {0.f,0.f,0.f,0.f}, a3[4] = {0.f,0.f,0.f,0.f};
            const uint32_t kb = sb + KV_OFF + (uint32_t)(g % 3) * KV_BUF;
#pragma unroll
            for (int s = 0; s < 4; s++) {
                uint32_t addr = kb + (uint32_t)(wk * 8 + (lane & 7)) * 144
                              + ((((lane >> 3) & 1) * 8) + s * 16) * 2;
                uint32_t bh2[2], bl2[2];
                LDMX2(bh2[0], bh2[1], addr);
                LDMX2(bl2[0], bl2[1], addr + 9216);
                MMA16816(a1, qhf[s], bh2);
                MMA16816(a2, qhf[s], bl2);
                MMA16816(a3, qlf[s], bh2);
            }
            int row = wq * 16 + (lane >> 2);
            if (g < 16) {
                int col = g * 64 + wk * 8 + (lane & 3) * 2;
                *(float2*)(sm + SS_OFF + (uint32_t)row * SSP + col * 4) =
                    make_float2(a1[0] + a2[0] + a3[0], a1[1] + a2[1] + a3[1]);
                *(float2*)(sm + SS_OFF + (uint32_t)(row + 8) * SSP + col * 4) =
                    make_float2(a1[2] + a2[2] + a3[2], a1[3] + a2[3] + a3[3]);
            } else {
                int col = (g - 16) * 64 + wk * 8 + (lane & 3) * 2;
                if (col <= 274) {
                    *(float2*)(sm + WR_OFF + (uint32_t)row * WRP + col * 4) =
                        make_float2(a1[0] + a2[0] + a3[0], a1[1] + a2[1] + a3[1]);
                    *(float2*)(sm + WR_OFF + (uint32_t)(row + 8) * WRP + col * 4) =
                        make_float2(a1[2] + a2[2] + a3[2], a1[3] + a2[3] + a3[3]);
                }
            }
        }
    }
    __syncthreads();

    // prefetch v tile 0 -> buf 2 (overlaps softmax)
    issue_tile(g_vh, g_vl, bhrow, 64, sb + KV_OFF + 2u * KV_BUF);

    // ================= softmax (fused bias, reg-resident), 2 rows/warp =====
    for (int rr = 0; rr < 2; rr++) {
        const int row = wid * 2 + rr;
        const int i = i0 + row;
        const float* rp = (const float*)(sm + SS_OFF + (uint32_t)row * SSP);
        const float* qwr = (const float*)(sm + WR_OFF + (uint32_t)row * WRP);
        float tmp[32];
#pragma unroll
        for (int kk = 0; kk < 32; kk++) {
            int j = lane + kk * 32;
            int rel = j - i;
            rel = rel < -128 ? -128 : (rel > 128 ? 128 : rel);
            tmp[kk] = (rp[j] + qwr[rel + 128]) * 0.125f;
        }
        float mx = -1e30f;
#pragma unroll
        for (int kk = 0; kk < 32; kk++) mx = fmaxf(mx, tmp[kk]);
#pragma unroll
        for (int o = 16; o > 0; o >>= 1) mx = fmaxf(mx, __shfl_xor_sync(0xffffffffu, mx, o));
        float sum = 0.f;
#pragma unroll
        for (int kk = 0; kk < 32; kk++) { tmp[kk] = __expf(tmp[kk] - mx); sum += tmp[kk]; }
#pragma unroll
        for (int o = 16; o > 0; o >>= 1) sum += __shfl_xor_sync(0xffffffffu, sum, o);
        const float inv = 1.f / sum;

        __syncwarp();
        uint32_t* wrz = (uint32_t*)(sm + WR_OFF + (uint32_t)row * WRP);
        for (int idx = lane; idx < 276; idx += 32) wrz[idx] = 0u;
        __syncwarp();

        __nv_bfloat16* wh_ = (__nv_bfloat16*)wrz;
        __nv_bfloat16* wl_ = wh_ + 280;
        float s0 = 0.f, s2 = 0.f;
#pragma unroll
        for (int kk = 0; kk < 32; kk++) {
            int j = lane + kk * 32;
            float w = tmp[kk] * inv;
            __nv_bfloat16 h = __float2bfloat16(w);
            __nv_bfloat16 l = __float2bfloat16(w - __bfloat162float(h));
            *(__nv_bfloat16*)(sm + SS_OFF + (uint32_t)row * SSP + j * 2) = h;
            *(__nv_bfloat16*)(sm + SS_OFF + (uint32_t)row * SSP + 2064 + j * 2) = l;
            int dlt = j - i;
            if (dlt <= -128)      s0 += w;
            else if (dlt >= 128)  s2 += w;
            else { wh_[dlt + 128] = h; wl_[dlt + 128] = l; }
        }
#pragma unroll
        for (int o = 16; o > 0; o >>= 1) s0 += __shfl_xor_sync(0xffffffffu, s0, o);
#pragma unroll
        for (int o = 16; o > 0; o >>= 1) s2 += __shfl_xor_sync(0xffffffffu, s2, o);
        __syncwarp();
        if (lane == 0) {
            __nv_bfloat16 h0 = __float2bfloat16(s0);
            wh_[0] = h0; wl_[0] = __float2bfloat16(s0 - __bfloat162float(h0));
            __nv_bfloat16 h2 = __float2bfloat16(s2);
            wh_[256] = h2; wl_[256] = __float2bfloat16(s2 - __bfloat162float(h2));
        }
    }

    // ================= PV: warp (wm2, wn2 n32, ws4 k-split) ================
    const int wm = wid >> 3;            // 0..1
    const int wn = (wid >> 2) & 1;      // 0..1 -> n offset wn*32
    const int ws = wid & 3;             // 0..3 -> one s-step per tile

    auto issue_pv = [&](int tt) {
        uint32_t dst = sb + KV_OFF + (uint32_t)((tt + 2) % 3) * KV_BUF;
        if (tt < 16) issue_tile(g_vh, g_vl, bhrow + (size_t)tt * 64, 64, dst);
        else         issue_tile(g_rvh, g_rvl, (size_t)(tt - 16) * 64,
                                (tt == 20) ? 16 : 64, dst);
    };

    float o1[4][4], o2[4][4], o3[4][4];
#pragma unroll
    for (int nf = 0; nf < 4; nf++)
#pragma unroll
        for (int r = 0; r < 4; r++) { o1[nf][r] = 0.f; o2[nf][r] = 0.f; o3[nf][r] = 0.f; }

    for (int vt = 0; vt < 21; vt++) {
        if (vt == 0 || vt == 20) { CP_WAIT(0); } else { CP_WAIT(1); }
        __syncthreads();
        if (vt == 0)            { issue_pv(1); issue_pv(2); }
        else if (vt + 2 <= 20)  issue_pv(vt + 2);

        const bool active = (vt < 20) || (ws == 0);
        if (active) {
            const uint32_t vb = sb + KV_OFF + (uint32_t)((vt + 2) % 3) * KV_BUF;
            const int s = (vt == 20) ? 0 : ws;
            const uint32_t nrowsB = (vt == 20) ? 16u : 64u;

            uint32_t awh[4], awl[4];
            if (vt < 16) {
                uint32_t aaddr = sb + SS_OFF + (uint32_t)(wm * 16 + (lane & 15)) * SSP
                               + (((lane >> 4) << 3) + vt * 64 + s * 16) * 2;
                LDMX4(awh[0], awh[1], awh[2], awh[3], aaddr);
                LDMX4(awl[0], awl[1], awl[2], awl[3], aaddr + 2064);
            } else {
                uint32_t abase = sb + WR_OFF + (uint32_t)(wm * 16 + (lane & 15)) * WRP;
                uint32_t acol = (((lane >> 4) << 3) + (vt - 16) * 64 + s * 16) * 2;
                LDMX4(awh[0], awh[1], awh[2], awh[3], abase + acol);
                LDMX4(awl[0], awl[1], awl[2], awl[3], abase + 560 + acol);
            }
            uint32_t brow = (uint32_t)(s * 16 + (lane & 7) + ((lane >> 3) & 1) * 8);
            uint32_t bcol = (uint32_t)(wn * 32 + ((lane >> 4) << 3)) * 2;
            uint32_t bvh[8], bvl[8];
            LDMX4T(bvh[0], bvh[1], bvh[2], bvh[3], vb + brow * 144 + bcol);
            LDMX4T(bvh[4], bvh[5], bvh[6], bvh[7], vb + brow * 144 + bcol + 32);
            LDMX4T(bvl[0], bvl[1], bvl[2], bvl[3], vb + nrowsB * 144u + brow * 144 + bcol);
            LDMX4T(bvl[4], bvl[5], bvl[6], bvl[7], vb + nrowsB * 144u + brow * 144 + bcol + 32);
#pragma unroll
            for (int nf = 0; nf < 4; nf++) {
                MMA16816(o1[nf], awh, (&bvh[nf * 2]));
                MMA16816(o2[nf], awh, (&bvl[nf * 2]));
                MMA16816(o3[nf], awl, (&bvh[nf * 2]));
            }
        }
    }

    // merge chains
    float of[4][4];
#pragma unroll
    for (int nf = 0; nf < 4; nf++)
#pragma unroll
        for (int r = 0; r < 4; r++)
            of[nf][r] = o1[nf][r] + o2[nf][r] + o3[nf][r];

    // 4-way cross-warp k-reduction over ws; emit split bf16 directly
    __syncthreads();                     // all PV buffer reads complete
    float* red = (float*)(sm + KV_OFF);  // 24KB scratch: [widx4][ws-1:3][nf4][lane32] float4
    const int widx = wm * 2 + wn;
    if (ws != 0) {
#pragma unroll
        for (int nf = 0; nf < 4; nf++)
            *(float4*)&red[((((widx * 3 + (ws - 1)) * 4) + nf) * 32 + lane) * 4] =
                make_float4(of[nf][0], of[nf][1], of[nf][2], of[nf][3]);
    }
    __syncthreads();
    if (ws == 0) {
        const int bb = bh >> 4, h = bh & 15;
        int row = i0 + wm * 16 + (lane >> 2);
#pragma unroll
        for (int nf = 0; nf < 4; nf++) {
            float f0 = of[nf][0], f1 = of[nf][1], f2 = of[nf][2], f3 = of[nf][3];
#pragma unroll
            for (int e = 0; e < 3; e++) {
                float4 v = *(const float4*)&red[((((widx * 3 + e) * 4) + nf) * 32 + lane) * 4];
                f0 += v.x; f1 += v.y; f2 += v.z; f3 += v.w;
            }
            int d = h * 64 + wn * 32 + nf * 8 + (lane & 3) * 2;
            size_t off0 = ((size_t)bb * 1024 + row) * 1024 + d;
            size_t off1 = off0 + 8 * 1024;
            __nv_bfloat16 h0 = __float2bfloat16(f0), h1 = __float2bfloat16(f1);
            __nv_bfloat16 h2 = __float2bfloat16(f2), h3 = __float2bfloat16(f3);
            *(__nv_bfloat162*)(g_xh + off0) = __nv_bfloat162(h0, h1);
            *(__nv_bfloat162*)(g_xh + off1) = __nv_bfloat162(h2, h3);
            __nv_bfloat16 l0 = __float2bfloat16(f0 - __bfloat162float(h0));
            __nv_bfloat16 l1 = __float2bfloat16(f1 - __bfloat162float(h1));
            __nv_bfloat16 l2 = __float2bfloat16(f2 - __bfloat162float(h2));
            __nv_bfloat16 l3 = __float2bfloat16(f3 - __bfloat162float(h3));
            *(__nv_bfloat162*)(g_xl + off0) = __nv_bfloat162(l0, l1);
            *(__nv_bfloat162*)(g_xl + off1) = __nv_bfloat162(l2, l3);
        }
    }
}

// ---------------------------------------------------------------------------
extern "C" void kernel_launch(void* const* d_in, const int* in_sizes, int n_in,
                              void* d_out, int out_size)
{
    const float* x     = (const float*)d_in[0];
    const float* Wq    = (const float*)d_in[1];
    const float* bq    = (const float*)d_in[2];
    const float* Wk    = (const float*)d_in[3];
    const float* bk    = (const float*)d_in[4];
    const float* Wv    = (const float*)d_in[5];
    const float* bv    = (const float*)d_in[6];
    const float* Wo    = (const float*)d_in[7];
    const float* bo    = (const float*)d_in[8];
    const float* rel_k = (const float*)d_in[9];
    const float* rel_v = (const float*)d_in[10];

    __nv_bfloat16 *xh, *xl, *woh, *wol;
    cudaGetSymbolAddress((void**)&xh,  g_xh);
    cudaGetSymbolAddress((void**)&xl,  g_xl);
    cudaGetSymbolAddress((void**)&woh, g_wsp);
    wol = woh + 7 * (size_t)Dd * Dd;
    woh = woh + 6 * (size_t)Dd * Dd;

    cudaFuncSetAttribute(gemm_qkv, cudaFuncAttributeMaxDynamicSharedMemorySize, GEMM_SMEM);
    cudaFuncSetAttribute(gemm_mma, cudaFuncAttributeMaxDynamicSharedMemorySize, GEMM_SMEM);
    cudaFuncSetAttribute(attn_mma, cudaFuncAttributeMaxDynamicSharedMemorySize, ATTN_SMEM);

    dim3 blk(256);

    // prep: x split, weight splits, rel tables
    split_bf16_kernel<<<2048, blk>>>(x, xh, xl, (NROW * Dd) / 4);
    split_w_kernel<<<dim3(512, 4), blk>>>(Wq, Wk, Wv, Wo);
    rel_prep<<<96, blk>>>(rel_k, rel_v);

    // merged QKV projections (768 CTAs, 128x128 tiles)
    gemm_qkv<<<dim3(Dd / 128, NROW / 128, 3), blk, GEMM_SMEM>>>(bq, bk, bv);

    // attention core
    attn_mma<<<dim3(Ss / 32, Bv * Hh), 512, ATTN_SMEM>>>();

    // output projection -> d_out
    gemm_mma<<<dim3(Dd / 128, NROW / 128), blk, GEMM_SMEM>>>(xh, xl, woh, wol, bo, (float*)d_out);
}

// round 13
// speedup vs baseline: 1.0693x; 1.0412x over previous
#include <cuda_runtime.h>
#include <cuda_bf16.h>
#include <cstdint>

#define Bv 4
#define Hh 16
#define Ss 1024
#define Dd 1024
#define HDd 64
#define NP 257
#define NROW (Bv*Ss)    // 4096
#define BHS (Bv*Hh*Ss)  // 65536

// ---------------- scratch (device globals: allocation-free) ----------------
__device__ __nv_bfloat16 g_qh[BHS * HDd];
__device__ __nv_bfloat16 g_ql[BHS * HDd];
__device__ __nv_bfloat16 g_kh[BHS * HDd];
__device__ __nv_bfloat16 g_kl[BHS * HDd];
__device__ __nv_bfloat16 g_vh[BHS * HDd];
__device__ __nv_bfloat16 g_vl[BHS * HDd];
__device__ __nv_bfloat16 g_rvh[256 * 64];
__device__ __nv_bfloat16 g_rvl[256 * 64];
__device__ __nv_bfloat16 g_rkh[256 * 64];
__device__ __nv_bfloat16 g_rkl[256 * 64];
__device__ __nv_bfloat16 g_xh[(size_t)NROW * Dd];
__device__ __nv_bfloat16 g_xl[(size_t)NROW * Dd];
__device__ __nv_bfloat16 g_wsp[8][(size_t)Dd * Dd];   // q,k,v,o hi/lo: [2z]=hi,[2z+1]=lo

// ====================== PTX helpers (family-portable only) ======================
__device__ __forceinline__ uint32_t smem_u32(const void* p) {
    uint32_t a;
    asm("{ .reg .u64 t; cvta.to.shared.u64 t, %1; cvt.u32.u64 %0, t; }" : "=r"(a) : "l"(p));
    return a;
}

#define LDMX4(r0, r1, r2, r3, addr) \
    asm volatile("ldmatrix.sync.aligned.m8n8.x4.shared.b16 {%0,%1,%2,%3}, [%4];" \
                 : "=r"(r0), "=r"(r1), "=r"(r2), "=r"(r3) : "r"(addr))

#define LDMX2(r0, r1, addr) \
    asm volatile("ldmatrix.sync.aligned.m8n8.x2.shared.b16 {%0,%1}, [%2];" \
                 : "=r"(r0), "=r"(r1) : "r"(addr))

#define LDMX4T(r0, r1, r2, r3, addr) \
    asm volatile("ldmatrix.sync.aligned.m8n8.x4.trans.shared.b16 {%0,%1,%2,%3}, [%4];" \
                 : "=r"(r0), "=r"(r1), "=r"(r2), "=r"(r3) : "r"(addr))

#define MMA16816(c, a, b) \
    asm volatile("mma.sync.aligned.m16n8k16.row.col.f32.bf16.bf16.f32 " \
                 "{%0,%1,%2,%3}, {%4,%5,%6,%7}, {%8,%9}, {%0,%1,%2,%3};" \
                 : "+f"((c)[0]), "+f"((c)[1]), "+f"((c)[2]), "+f"((c)[3]) \
                 : "r"((a)[0]), "r"((a)[1]), "r"((a)[2]), "r"((a)[3]), \
                   "r"((b)[0]), "r"((b)[1]))

#define CP_ASYNC16(s, g) \
    asm volatile("cp.async.cg.shared.global [%0], [%1], 16;" :: "r"(s), "l"(g))
#define CP_COMMIT() asm volatile("cp.async.commit_group;" ::: "memory")
#define CP_WAIT(n)  asm volatile("cp.async.wait_group %0;" :: "n"(n) : "memory")

// ---------------------------------------------------------------------------
// splits
// ---------------------------------------------------------------------------
__global__ void split_bf16_kernel(const float* __restrict__ in,
                                  __nv_bfloat16* __restrict__ hi,
                                  __nv_bfloat16* __restrict__ lo, int n4)
{
    int i = blockIdx.x * 512 + threadIdx.x;
#pragma unroll
    for (int rep = 0; rep < 2; rep++, i += 256) {
        if (i >= n4) return;
        float4 v = ((const float4*)in)[i];
        float vv[4] = {v.x, v.y, v.z, v.w};
        __nv_bfloat16 h[4], l[4];
#pragma unroll
        for (int j = 0; j < 4; j++) {
            h[j] = __float2bfloat16(vv[j]);
            l[j] = __float2bfloat16(vv[j] - __bfloat162float(h[j]));
        }
        ((__nv_bfloat162*)hi)[i * 2 + 0] = __nv_bfloat162(h[0], h[1]);
        ((__nv_bfloat162*)hi)[i * 2 + 1] = __nv_bfloat162(h[2], h[3]);
        ((__nv_bfloat162*)lo)[i * 2 + 0] = __nv_bfloat162(l[0], l[1]);
        ((__nv_bfloat162*)lo)[i * 2 + 1] = __nv_bfloat162(l[2], l[3]);
    }
}

__global__ void split_w_kernel(const float* __restrict__ W0, const float* __restrict__ W1,
                               const float* __restrict__ W2, const float* __restrict__ W3)
{
    int z = blockIdx.y;
    const float* in = (z == 0 ? W0 : z == 1 ? W1 : z == 2 ? W2 : W3);
    __nv_bfloat16* hi = g_wsp[2 * z];
    __nv_bfloat16* lo = g_wsp[2 * z + 1];
    int i = blockIdx.x * 512 + threadIdx.x;
#pragma unroll
    for (int rep = 0; rep < 2; rep++, i += 256) {
        float4 v = ((const float4*)in)[i];
        float vv[4] = {v.x, v.y, v.z, v.w};
        __nv_bfloat16 h[4], l[4];
#pragma unroll
        for (int j = 0; j < 4; j++) {
            h[j] = __float2bfloat16(vv[j]);
            l[j] = __float2bfloat16(vv[j] - __bfloat162float(h[j]));
        }
        ((__nv_bfloat162*)hi)[i * 2 + 0] = __nv_bfloat162(h[0], h[1]);
        ((__nv_bfloat162*)hi)[i * 2 + 1] = __nv_bfloat162(h[2], h[3]);
        ((__nv_bfloat162*)lo)[i * 2 + 0] = __nv_bfloat162(l[0], l[1]);
        ((__nv_bfloat162*)lo)[i * 2 + 1] = __nv_bfloat162(l[2], l[3]);
    }
}

// rel tables: buckets 0..255 only (bucket 256 handled by exact fp32 fixups)
__global__ void rel_prep(const float* __restrict__ rel_k, const float* __restrict__ rel_v)
{
    int idx = blockIdx.x * 256 + threadIdx.x;
    if (idx < 256 * 64) {
        float v = rel_k[idx];
        __nv_bfloat16 h = __float2bfloat16(v);
        g_rkh[idx] = h;
        g_rkl[idx] = __float2bfloat16(v - __bfloat162float(h));
        v = rel_v[idx];
        h = __float2bfloat16(v);
        g_rvh[idx] = h;
        g_rvl[idx] = __float2bfloat16(v - __bfloat162float(h));
    }
}

// ---------------------------------------------------------------------------
// GEMM body (R10 proven config): 128x128 tile, BK=32, 8 warps, 2 CTAs/SM.
// ---------------------------------------------------------------------------
#define SPB 80
#define MAT_SM (128 * SPB)
#define BUF_SM (4 * MAT_SM)
#define GEMM_SMEM (2 * BUF_SM)

__device__ __forceinline__ void gemm_body(
    char* sm,
    const __nv_bfloat16* __restrict__ Ah_, const __nv_bfloat16* __restrict__ Al_,
    const __nv_bfloat16* __restrict__ Bh_, const __nv_bfloat16* __restrict__ Bl_,
    const float* __restrict__ bias, float* __restrict__ Cf,
    __nv_bfloat16* __restrict__ Ch, __nv_bfloat16* __restrict__ Cl, int headed)
{
    const uint32_t sb = smem_u32(sm);
    const int t    = threadIdx.x;
    const int wid  = t >> 5;
    const int lane = t & 31;
    const int m0 = blockIdx.y * 128;
    const int n0 = blockIdx.x * 128;
    const int wm = wid >> 2;
    const int wn = wid & 3;

    const char* gb0 = (const char*)(Ah_ + (size_t)m0 * 1024);
    const char* gb1 = (const char*)(Al_ + (size_t)m0 * 1024);
    const char* gb2 = (const char*)(Bh_ + (size_t)n0 * 1024);
    const char* gb3 = (const char*)(Bl_ + (size_t)n0 * 1024);

    auto issue = [&](int chunk, int buf) {
#pragma unroll
        for (int it = 0; it < 8; it++) {
            int id  = t + it * 256;
            int mat = id >> 9;
            int row = (id >> 2) & 127;
            int c16 = id & 3;
            const char* g = (mat == 0 ? gb0 : mat == 1 ? gb1 : mat == 2 ? gb2 : gb3);
            uint32_t sa = sb + buf * BUF_SM + mat * MAT_SM + row * SPB + c16 * 16;
            CP_ASYNC16(sa, g + (size_t)row * 2048 + chunk * 64 + c16 * 16);
        }
        CP_COMMIT();
    };

    float acc[4][4][4];
#pragma unroll
    for (int i = 0; i < 4; i++)
#pragma unroll
        for (int j = 0; j < 4; j++)
#pragma unroll
            for (int r = 0; r < 4; r++) acc[i][j][r] = 0.f;

    issue(0, 0);
    for (int c = 0; c < 32; c++) {
        const int buf = c & 1;
        CP_WAIT(0);
        __syncthreads();
        if (c + 1 < 32) issue(c + 1, buf ^ 1);

        const uint32_t Ahb = sb + buf * BUF_SM;
        const uint32_t Alb = Ahb + MAT_SM;
        const uint32_t Bhb = Ahb + 2 * MAT_SM;
        const uint32_t Blb = Ahb + 3 * MAT_SM;

#pragma unroll
        for (int s = 0; s < 2; s++) {
            uint32_t ah[4][4], al[4][4];
            const int arow = wm * 64 + (lane & 15);
            const int acolB = (((lane >> 4) << 3) + s * 16) * 2;
#pragma unroll
            for (int mf = 0; mf < 4; mf++) {
                uint32_t ad = Ahb + (uint32_t)(arow + mf * 16) * SPB + acolB;
                LDMX4(ah[mf][0], ah[mf][1], ah[mf][2], ah[mf][3], ad);
                ad = Alb + (uint32_t)(arow + mf * 16) * SPB + acolB;
                LDMX4(al[mf][0], al[mf][1], al[mf][2], al[mf][3], ad);
            }
            uint32_t bh[4][2], bl[4][2];
            const int brow = wn * 32 + (lane & 7) + ((lane >> 4) << 3);
            const int bcolB = ((((lane >> 3) & 1) << 3) + s * 16) * 2;
#pragma unroll
            for (int g = 0; g < 2; g++) {
                uint32_t r0, r1, r2, r3;
                uint32_t bd = Bhb + (uint32_t)(brow + g * 16) * SPB + bcolB;
                LDMX4(r0, r1, r2, r3, bd);
                bh[g * 2][0] = r0; bh[g * 2][1] = r1;
                bh[g * 2 + 1][0] = r2; bh[g * 2 + 1][1] = r3;
                bd = Blb + (uint32_t)(brow + g * 16) * SPB + bcolB;
                LDMX4(r0, r1, r2, r3, bd);
                bl[g * 2][0] = r0; bl[g * 2][1] = r1;
                bl[g * 2 + 1][0] = r2; bl[g * 2 + 1][1] = r3;
            }
#pragma unroll
            for (int mf = 0; mf < 4; mf++)
#pragma unroll
                for (int nf = 0; nf < 4; nf++) {
                    MMA16816(acc[mf][nf], ah[mf], bh[nf]);
                    MMA16816(acc[mf][nf], ah[mf], bl[nf]);
                    MMA16816(acc[mf][nf], al[mf], bh[nf]);
                }
        }
    }

#pragma unroll
    for (int mf = 0; mf < 4; mf++) {
#pragma unroll
        for (int nf = 0; nf < 4; nf++) {
            int m = m0 + wm * 64 + mf * 16 + (lane >> 2);
            int n = n0 + wn * 32 + nf * 8 + (lane & 3) * 2;
            float p0 = acc[mf][nf][0] + bias[n];
            float p1 = acc[mf][nf][1] + bias[n + 1];
            float p2 = acc[mf][nf][2] + bias[n];
            float p3 = acc[mf][nf][3] + bias[n + 1];
            size_t off0, off1;
            if (headed) {
                int h = n >> 6, d = n & 63;
                int bb = m >> 10, s1 = m & 1023;
                off0 = ((((size_t)bb * Hh + h) << 10) + s1) * HDd + d;
                off1 = ((((size_t)bb * Hh + h) << 10) + s1 + 8) * HDd + d;
            } else {
                off0 = (size_t)m * 1024 + n;
                off1 = (size_t)(m + 8) * 1024 + n;
            }
            if (Cf) {
                *(float2*)(Cf + off0) = make_float2(p0, p1);
                *(float2*)(Cf + off1) = make_float2(p2, p3);
            }
            if (Ch) {
                __nv_bfloat16 h0 = __float2bfloat16(p0), h1 = __float2bfloat16(p1);
                __nv_bfloat16 h2 = __float2bfloat16(p2), h3 = __float2bfloat16(p3);
                *(__nv_bfloat162*)(Ch + off0) = __nv_bfloat162(h0, h1);
                *(__nv_bfloat162*)(Ch + off1) = __nv_bfloat162(h2, h3);
                __nv_bfloat16 l0 = __float2bfloat16(p0 - __bfloat162float(h0));
                __nv_bfloat16 l1 = __float2bfloat16(p1 - __bfloat162float(h1));
                __nv_bfloat16 l2 = __float2bfloat16(p2 - __bfloat162float(h2));
                __nv_bfloat16 l3 = __float2bfloat16(p3 - __bfloat162float(h3));
                *(__nv_bfloat162*)(Cl + off0) = __nv_bfloat162(l0, l1);
                *(__nv_bfloat162*)(Cl + off1) = __nv_bfloat162(l2, l3);
            }
        }
    }
}

__global__ __launch_bounds__(256, 2)
void gemm_qkv(const float* __restrict__ bq, const float* __restrict__ bk,
              const float* __restrict__ bv)
{
    extern __shared__ char sm[];
    int z = blockIdx.z;
    const float* bias = (z == 0 ? bq : z == 1 ? bk : bv);
    __nv_bfloat16* Ch = (z == 0 ? g_qh : z == 1 ? g_kh : g_vh);
    __nv_bfloat16* Cl = (z == 0 ? g_ql : z == 1 ? g_kl : g_vl);
    gemm_body(sm, g_xh, g_xl, g_wsp[2 * z], g_wsp[2 * z + 1], bias,
              nullptr, Ch, Cl, 1);
}

__global__ __launch_bounds__(256, 2)
void gemm_mma(const __nv_bfloat16* __restrict__ Ah_, const __nv_bfloat16* __restrict__ Al_,
              const __nv_bfloat16* __restrict__ Bh_, const __nv_bfloat16* __restrict__ Bl_,
              const float* __restrict__ bias, float* __restrict__ Cf)
{
    extern __shared__ char sm[];
    gemm_body(sm, Ah_, Al_, Bh_, Bl_, bias, Cf, nullptr, nullptr, 0);
}

// ---------------------------------------------------------------------------
// MMA attention core: uniform 20-tile pipelines; bucket-256 via exact fixups.
// ---------------------------------------------------------------------------
#define SSP  4112u
#define WRP  1104u
#define Q_OFF   0u
#define KV_OFF  9216u
#define KV_BUF  18432u
#define SS_OFF  64512u
#define WR_OFF  196096u
#define ATTN_SMEM 231424

__global__ __launch_bounds__(512, 1)
void attn_mma(const float* __restrict__ rel_k, const float* __restrict__ rel_v)
{
    extern __shared__ char sm[];
    const uint32_t sb = smem_u32(sm);
    const int t = threadIdx.x, lane = t & 31, wid = t >> 5;
    const int bh = blockIdx.y;
    const int i0 = blockIdx.x * 32;

    auto issue_tile = [&](const __nv_bfloat16* sh, const __nv_bfloat16* sl,
                          size_t row0, uint32_t dst) {
#pragma unroll
        for (int it = 0; it < 2; it++) {
            int id = t + it * 512;
            int sel = id >> 9;
            int rid = id & 511;
            int row = rid >> 3, c16 = rid & 7;
            const __nv_bfloat16* s = (sel ? sl : sh) + (row0 + row) * 64 + c16 * 8;
            CP_ASYNC16(dst + (uint32_t)sel * (64 * 144) + row * 144 + c16 * 16, s);
        }
        CP_COMMIT();
    };
    auto issue_q = [&]() {
#pragma unroll
        for (int it = 0; it < 1; it++) {
            int id = t;
            int sel = id >> 8;
            int rid = id & 255;
            int row = rid >> 3, c16 = rid & 7;
            const __nv_bfloat16* s = (sel ? g_ql : g_qh)
                                   + ((size_t)bh * 1024 + i0 + row) * 64 + c16 * 8;
            CP_ASYNC16(sb + Q_OFF + (uint32_t)sel * (32 * 144) + row * 144 + c16 * 16, s);
        }
        CP_COMMIT();
    };

    const size_t bhrow = (size_t)bh * 1024;

    issue_q();
    issue_tile(g_kh, g_kl, bhrow, sb + KV_OFF);
    issue_tile(g_kh, g_kl, bhrow + 64, sb + KV_OFF + KV_BUF);

    // ========= unified scores (g<16) + bias window (g>=16), 20 tiles =======
    {
        const int wq = wid >> 3;
        const int wk = wid & 7;
        uint32_t qhf[4][4], qlf[4][4];

        for (int g = 0; g < 20; g++) {
            if (g < 19) { CP_WAIT(1); } else { CP_WAIT(0); }
            __syncthreads();
            if (g + 2 < 20) {
                int tt = g + 2;
                uint32_t dst = sb + KV_OFF + (uint32_t)(tt % 3) * KV_BUF;
                if (tt < 16) issue_tile(g_kh, g_kl, bhrow + (size_t)tt * 64, dst);
                else         issue_tile(g_rkh, g_rkl, (size_t)(tt - 16) * 64, dst);
            }

            if (g == 0) {
#pragma unroll
                for (int s = 0; s < 4; s++) {
                    uint32_t a = sb + Q_OFF + (uint32_t)(wq * 16 + (lane & 15)) * 144
                               + (((lane >> 4) << 3) + s * 16) * 2;
                    LDMX4(qhf[s][0], qhf[s][1], qhf[s][2], qhf[s][3], a);
                    LDMX4(qlf[s][0], qlf[s][1], qlf[s][2], qlf[s][3], a + 4608);
                }
            }

            float a1[4] = {0.f,0.f,0.f,0.f}, a2[4] = {0.f,0.f,0.f,0.f}, a3[4] = {0.f,0.f,0.f,0.f};
            const uint32_t kb = sb + KV_OFF + (uint32_t)(g % 3) * KV_BUF;
#pragma unroll
            for (int s = 0; s < 4; s++) {
                uint32_t addr = kb + (uint32_t)(wk * 8 + (lane & 7)) * 144
                              + ((((lane >> 3) & 1) * 8) + s * 16) * 2;
                uint32_t bh2[2], bl2[2];
                LDMX2(bh2[0], bh2[1], addr);
                LDMX2(bl2[0], bl2[1], addr + 9216);
                MMA16816(a1, qhf[s], bh2);
                MMA16816(a2, qhf[s], bl2);
                MMA16816(a3, qlf[s], bh2);
            }
            int row = wq * 16 + (lane >> 2);
            if (g < 16) {
                int col = g * 64 + wk * 8 + (lane & 3) * 2;
                *(float2*)(sm + SS_OFF + (uint32_t)row * SSP + col * 4) =
                    make_float2(a1[0] + a2[0] + a3[0], a1[1] + a2[1] + a3[1]);
                *(float2*)(sm + SS_OFF + (uint32_t)(row + 8) * SSP + col * 4) =
                    make_float2(a1[2] + a2[2] + a3[2], a1[3] + a2[3] + a3[3]);
            } else {
                int col = (g - 16) * 64 + wk * 8 + (lane & 3) * 2;
                *(float2*)(sm + WR_OFF + (uint32_t)row * WRP + col * 4) =
                    make_float2(a1[0] + a2[0] + a3[0], a1[1] + a2[1] + a3[1]);
                *(float2*)(sm + WR_OFF + (uint32_t)(row + 8) * WRP + col * 4) =
                    make_float2(a1[2] + a2[2] + a3[2], a1[3] + a2[3] + a3[3]);
            }
        }
    }
    __syncthreads();

    // prefetch v tile 0 -> buf 2 (overlaps softmax)
    issue_tile(g_vh, g_vl, bhrow, sb + KV_OFF + 2u * KV_BUF);

    // ================= softmax (fused bias, reg-resident), 2 rows/warp =====
    float* s2f = (float*)(sm + Q_OFF);   // Q region dead after scores phase
    const float* rk256 = rel_k + 256 * 64;
    for (int rr = 0; rr < 2; rr++) {
        const int row = wid * 2 + rr;
        const int i = i0 + row;
        const float* rp = (const float*)(sm + SS_OFF + (uint32_t)row * SSP);
        const float* qwr = (const float*)(sm + WR_OFF + (uint32_t)row * WRP);

        // exact fixup: v256 = q_row . rel_k[256]
        float v256;
        {
            uint32_t qb = sb + Q_OFF + (uint32_t)row * 144;
            __nv_bfloat16 qh0, ql0, qh1, ql1;
            asm volatile("ld.shared.b16 %0, [%1];" : "=h"(*(uint16_t*)&qh0) : "r"(qb + lane * 2));
            asm volatile("ld.shared.b16 %0, [%1];" : "=h"(*(uint16_t*)&ql0) : "r"(qb + 4608 + lane * 2));
            asm volatile("ld.shared.b16 %0, [%1];" : "=h"(*(uint16_t*)&qh1) : "r"(qb + (lane + 32) * 2));
            asm volatile("ld.shared.b16 %0, [%1];" : "=h"(*(uint16_t*)&ql1) : "r"(qb + 4608 + (lane + 32) * 2));
            v256 = (__bfloat162float(qh0) + __bfloat162float(ql0)) * rk256[lane]
                 + (__bfloat162float(qh1) + __bfloat162float(ql1)) * rk256[lane + 32];
#pragma unroll
            for (int o = 16; o > 0; o >>= 1) v256 += __shfl_xor_sync(0xffffffffu, v256, o);
        }

        float tmp[32];
#pragma unroll
        for (int kk = 0; kk < 32; kk++) {
            int j = lane + kk * 32;
            int rel = j - i;
            rel = rel < -128 ? -128 : (rel > 128 ? 128 : rel);
            float b = (rel == 128) ? v256 : qwr[rel + 128];
            tmp[kk] = (rp[j] + b) * 0.125f;
        }
        float mx = -1e30f;
#pragma unroll
        for (int kk = 0; kk < 32; kk++) mx = fmaxf(mx, tmp[kk]);
#pragma unroll
        for (int o = 16; o > 0; o >>= 1) mx = fmaxf(mx, __shfl_xor_sync(0xffffffffu, mx, o));
        float sum = 0.f;
#pragma unroll
        for (int kk = 0; kk < 32; kk++) { tmp[kk] = __expf(tmp[kk] - mx); sum += tmp[kk]; }
#pragma unroll
        for (int o = 16; o > 0; o >>= 1) sum += __shfl_xor_sync(0xffffffffu, sum, o);
        const float inv = 1.f / sum;

        __syncwarp();
        uint32_t* wrz = (uint32_t*)(sm + WR_OFF + (uint32_t)row * WRP);
        for (int idx = lane; idx < 276; idx += 32) wrz[idx] = 0u;
        __syncwarp();

        __nv_bfloat16* wh_ = (__nv_bfloat16*)wrz;
        __nv_bfloat16* wl_ = wh_ + 280;
        float s0 = 0.f, s2 = 0.f;
#pragma unroll
        for (int kk = 0; kk < 32; kk++) {
            int j = lane + kk * 32;
            float w = tmp[kk] * inv;
            __nv_bfloat16 h = __float2bfloat16(w);
            __nv_bfloat16 l = __float2bfloat16(w - __bfloat162float(h));
            *(__nv_bfloat16*)(sm + SS_OFF + (uint32_t)row * SSP + j * 2) = h;
            *(__nv_bfloat16*)(sm + SS_OFF + (uint32_t)row * SSP + 2064 + j * 2) = l;
            int dlt = j - i;
            if (dlt <= -128)      s0 += w;
            else if (dlt >= 128)  s2 += w;
            else { wh_[dlt + 128] = h; wl_[dlt + 128] = l; }
        }
#pragma unroll
        for (int o = 16; o > 0; o >>= 1) s0 += __shfl_xor_sync(0xffffffffu, s0, o);
#pragma unroll
        for (int o = 16; o > 0; o >>= 1) s2 += __shfl_xor_sync(0xffffffffu, s2, o);
        __syncwarp();
        if (lane == 0) {
            __nv_bfloat16 h0 = __float2bfloat16(s0);
            wh_[0] = h0; wl_[0] = __float2bfloat16(s0 - __bfloat162float(h0));
            s2f[row] = s2;
        }
    }

    // ================= PV: 20 uniform tiles, warp (wm2, wn2 n32, ws4) ======
    const int wm = wid >> 3;
    const int wn = (wid >> 2) & 1;
    const int ws = wid & 3;

    auto issue_pv = [&](int tt) {
        uint32_t dst = sb + KV_OFF + (uint32_t)((tt + 2) % 3) * KV_BUF;
        if (tt < 16) issue_tile(g_vh, g_vl, bhrow + (size_t)tt * 64, dst);
        else         issue_tile(g_rvh, g_rvl, (size_t)(tt - 16) * 64, dst);
    };

    float o1[4][4], o2[4][4], o3[4][4];
#pragma unroll
    for (int nf = 0; nf < 4; nf++)
#pragma unroll
        for (int r = 0; r < 4; r++) { o1[nf][r] = 0.f; o2[nf][r] = 0.f; o3[nf][r] = 0.f; }

    for (int vt = 0; vt < 20; vt++) {
        if (vt == 0 || vt == 19) { CP_WAIT(0); } else { CP_WAIT(1); }
        __syncthreads();
        if (vt == 0)            { issue_pv(1); issue_pv(2); }
        else if (vt + 2 <= 19)  issue_pv(vt + 2);

        const uint32_t vb = sb + KV_OFF + (uint32_t)((vt + 2) % 3) * KV_BUF;
        uint32_t awh[4], awl[4];
        if (vt < 16) {
            uint32_t aaddr = sb + SS_OFF + (uint32_t)(wm * 16 + (lane & 15)) * SSP
                           + (((lane >> 4) << 3) + vt * 64 + ws * 16) * 2;
            LDMX4(awh[0], awh[1], awh[2], awh[3], aaddr);
            LDMX4(awl[0], awl[1], awl[2], awl[3], aaddr + 2064);
        } else {
            uint32_t abase = sb + WR_OFF + (uint32_t)(wm * 16 + (lane & 15)) * WRP;
            uint32_t acol = (((lane >> 4) << 3) + (vt - 16) * 64 + ws * 16) * 2;
            LDMX4(awh[0], awh[1], awh[2], awh[3], abase + acol);
            LDMX4(awl[0], awl[1], awl[2], awl[3], abase + 560 + acol);
        }
        uint32_t brow = (uint32_t)(ws * 16 + (lane & 7) + ((lane >> 3) & 1) * 8);
        uint32_t bcol = (uint32_t)(wn * 32 + ((lane >> 4) << 3)) * 2;
        uint32_t bvh[8], bvl[8];
        LDMX4T(bvh[0], bvh[1], bvh[2], bvh[3], vb + brow * 144 + bcol);
        LDMX4T(bvh[4], bvh[5], bvh[6], bvh[7], vb + brow * 144 + bcol + 32);
        LDMX4T(bvl[0], bvl[1], bvl[2], bvl[3], vb + 64u * 144u + brow * 144 + bcol);
        LDMX4T(bvl[4], bvl[5], bvl[6], bvl[7], vb + 64u * 144u + brow * 144 + bcol + 32);
#pragma unroll
        for (int nf = 0; nf < 4; nf++) {
            MMA16816(o1[nf], awh, (&bvh[nf * 2]));
            MMA16816(o2[nf], awh, (&bvl[nf * 2]));
            MMA16816(o3[nf], awl, (&bvh[nf * 2]));
        }
    }

    // merge chains
    float of[4][4];
#pragma unroll
    for (int nf = 0; nf < 4; nf++)
#pragma unroll
        for (int r = 0; r < 4; r++)
            of[nf][r] = o1[nf][r] + o2[nf][r] + o3[nf][r];

    // 4-way cross-warp k-reduction over ws; bucket-256 fixup; emit split bf16
    __syncthreads();
    float* red = (float*)(sm + KV_OFF);
    const int widx = wm * 2 + wn;
    if (ws != 0) {
#pragma unroll
        for (int nf = 0; nf < 4; nf++)
            *(float4*)&red[((((widx * 3 + (ws - 1)) * 4) + nf) * 32 + lane) * 4] =
                make_float4(of[nf][0], of[nf][1], of[nf][2], of[nf][3]);
    }
    __syncthreads();
    if (ws == 0) {
        const int bb = bh >> 4, h = bh & 15;
        const int rloc = wm * 16 + (lane >> 2);
        const int row = i0 + rloc;
        const float s2a = s2f[rloc], s2b = s2f[rloc + 8];
        const float* rv256 = rel_v + 256 * 64;
#pragma unroll
        for (int nf = 0; nf < 4; nf++) {
            float f0 = of[nf][0], f1 = of[nf][1], f2 = of[nf][2], f3 = of[nf][3];
#pragma unroll
            for (int e = 0; e < 3; e++) {
                float4 v = *(const float4*)&red[((((widx * 3 + e) * 4) + nf) * 32 + lane) * 4];
                f0 += v.x; f1 += v.y; f2 += v.z; f3 += v.w;
            }
            int dd = wn * 32 + nf * 8 + (lane & 3) * 2;
            float2 rv = *(const float2*)(rv256 + dd);
            f0 += s2a * rv.x; f1 += s2a * rv.y;
            f2 += s2b * rv.x; f3 += s2b * rv.y;
            int d = h * 64 + dd;
            size_t off0 = ((size_t)bb * 1024 + row) * 1024 + d;
            size_t off1 = off0 + 8 * 1024;
            __nv_bfloat16 h0 = __float2bfloat16(f0), h1 = __float2bfloat16(f1);
            __nv_bfloat16 h2 = __float2bfloat16(f2), h3 = __float2bfloat16(f3);
            *(__nv_bfloat162*)(g_xh + off0) = __nv_bfloat162(h0, h1);
            *(__nv_bfloat162*)(g_xh + off1) = __nv_bfloat162(h2, h3);
            __nv_bfloat16 l0 = __float2bfloat16(f0 - __bfloat162float(h0));
            __nv_bfloat16 l1 = __float2bfloat16(f1 - __bfloat162float(h1));
            __nv_bfloat16 l2 = __float2bfloat16(f2 - __bfloat162float(h2));
            __nv_bfloat16 l3 = __float2bfloat16(f3 - __bfloat162float(h3));
            *(__nv_bfloat162*)(g_xl + off0) = __nv_bfloat162(l0, l1);
            *(__nv_bfloat162*)(g_xl + off1) = __nv_bfloat162(l2, l3);
        }
    }
}

// ---------------------------------------------------------------------------
extern "C" void kernel_launch(void* const* d_in, const int* in_sizes, int n_in,
                              void* d_out, int out_size)
{
    const float* x     = (const float*)d_in[0];
    const float* Wq    = (const float*)d_in[1];
    const float* bq    = (const float*)d_in[2];
    const float* Wk    = (const float*)d_in[3];
    const float* bk    = (const float*)d_in[4];
    const float* Wv    = (const float*)d_in[5];
    const float* bv    = (const float*)d_in[6];
    const float* Wo    = (const float*)d_in[7];
    const float* bo    = (const float*)d_in[8];
    const float* rel_k = (const float*)d_in[9];
    const float* rel_v = (const float*)d_in[10];

    __nv_bfloat16 *xh, *xl, *woh, *wol;
    cudaGetSymbolAddress((void**)&xh,  g_xh);
    cudaGetSymbolAddress((void**)&xl,  g_xl);
    cudaGetSymbolAddress((void**)&woh, g_wsp);
    wol = woh + 7 * (size_t)Dd * Dd;
    woh = woh + 6 * (size_t)Dd * Dd;

    cudaFuncSetAttribute(gemm_qkv, cudaFuncAttributeMaxDynamicSharedMemorySize, GEMM_SMEM);
    cudaFuncSetAttribute(gemm_mma, cudaFuncAttributeMaxDynamicSharedMemorySize, GEMM_SMEM);
    cudaFuncSetAttribute(attn_mma, cudaFuncAttributeMaxDynamicSharedMemorySize, ATTN_SMEM);

    dim3 blk(256);

    // prep: x split, weight splits, rel tables
    split_bf16_kernel<<<2048, blk>>>(x, xh, xl, (NROW * Dd) / 4);
    split_w_kernel<<<dim3(512, 4), blk>>>(Wq, Wk, Wv, Wo);
    rel_prep<<<64, blk>>>(rel_k, rel_v);

    // merged QKV projections
    gemm_qkv<<<dim3(Dd / 128, NROW / 128, 3), blk, GEMM_SMEM>>>(bq, bk, bv);

    // attention core
    attn_mma<<<dim3(Ss / 32, Bv * Hh), 512, ATTN_SMEM>>>(rel_k, rel_v);

    // output projection -> d_out
    gemm_mma<<<dim3(Dd / 128, NROW / 128), blk, GEMM_SMEM>>>(xh, xl, woh, wol, bo, (float*)d_out);
}

// round 14
// speedup vs baseline: 1.0858x; 1.0154x over previous
#include <cuda_runtime.h>
#include <cuda_bf16.h>
#include <cstdint>

#define Bv 4
#define Hh 16
#define Ss 1024
#define Dd 1024
#define HDd 64
#define NP 257
#define NROW (Bv*Ss)    // 4096
#define BHS (Bv*Hh*Ss)  // 65536

// ---------------- scratch (device globals: allocation-free) ----------------
__device__ __nv_bfloat16 g_qh[BHS * HDd];
__device__ __nv_bfloat16 g_ql[BHS * HDd];
__device__ __nv_bfloat16 g_kh[BHS * HDd];
__device__ __nv_bfloat16 g_kl[BHS * HDd];
__device__ __nv_bfloat16 g_vh[BHS * HDd];
__device__ __nv_bfloat16 g_vl[BHS * HDd];
__device__ __nv_bfloat16 g_rvh[256 * 64];
__device__ __nv_bfloat16 g_rvl[256 * 64];
__device__ __nv_bfloat16 g_rkh[256 * 64];
__device__ __nv_bfloat16 g_rkl[256 * 64];
__device__ __nv_bfloat16 g_xh[(size_t)NROW * Dd];
__device__ __nv_bfloat16 g_xl[(size_t)NROW * Dd];
__device__ __nv_bfloat16 g_wsp[8][(size_t)Dd * Dd];   // q,k,v,o hi/lo: [2z]=hi,[2z+1]=lo

// ====================== PTX helpers (family-portable only) ======================
__device__ __forceinline__ uint32_t smem_u32(const void* p) {
    uint32_t a;
    asm("{ .reg .u64 t; cvta.to.shared.u64 t, %1; cvt.u32.u64 %0, t; }" : "=r"(a) : "l"(p));
    return a;
}

#define LDMX4(r0, r1, r2, r3, addr) \
    asm volatile("ldmatrix.sync.aligned.m8n8.x4.shared.b16 {%0,%1,%2,%3}, [%4];" \
                 : "=r"(r0), "=r"(r1), "=r"(r2), "=r"(r3) : "r"(addr))

#define LDMX2(r0, r1, addr) \
    asm volatile("ldmatrix.sync.aligned.m8n8.x2.shared.b16 {%0,%1}, [%2];" \
                 : "=r"(r0), "=r"(r1) : "r"(addr))

#define LDMX4T(r0, r1, r2, r3, addr) \
    asm volatile("ldmatrix.sync.aligned.m8n8.x4.trans.shared.b16 {%0,%1,%2,%3}, [%4];" \
                 : "=r"(r0), "=r"(r1), "=r"(r2), "=r"(r3) : "r"(addr))

#define MMA16816(c, a, b) \
    asm volatile("mma.sync.aligned.m16n8k16.row.col.f32.bf16.bf16.f32 " \
                 "{%0,%1,%2,%3}, {%4,%5,%6,%7}, {%8,%9}, {%0,%1,%2,%3};" \
                 : "+f"((c)[0]), "+f"((c)[1]), "+f"((c)[2]), "+f"((c)[3]) \
                 : "r"((a)[0]), "r"((a)[1]), "r"((a)[2]), "r"((a)[3]), \
                   "r"((b)[0]), "r"((b)[1]))

#define CP_ASYNC16(s, g) \
    asm volatile("cp.async.cg.shared.global [%0], [%1], 16;" :: "r"(s), "l"(g))
#define CP_COMMIT() asm volatile("cp.async.commit_group;" ::: "memory")
#define CP_WAIT(n)  asm volatile("cp.async.wait_group %0;" :: "n"(n) : "memory")

// ---------------------------------------------------------------------------
// unified prep: blocks [0,2048) x-split, [2048,4096) weight splits, [4096,4160) rel
// ---------------------------------------------------------------------------
__device__ __forceinline__ void split4(const float* __restrict__ in,
                                       __nv_bfloat16* __restrict__ hi,
                                       __nv_bfloat16* __restrict__ lo, int i)
{
    float4 v = ((const float4*)in)[i];
    float vv[4] = {v.x, v.y, v.z, v.w};
    __nv_bfloat16 h[4], l[4];
#pragma unroll
    for (int j = 0; j < 4; j++) {
        h[j] = __float2bfloat16(vv[j]);
        l[j] = __float2bfloat16(vv[j] - __bfloat162float(h[j]));
    }
    ((__nv_bfloat162*)hi)[i * 2 + 0] = __nv_bfloat162(h[0], h[1]);
    ((__nv_bfloat162*)hi)[i * 2 + 1] = __nv_bfloat162(h[2], h[3]);
    ((__nv_bfloat162*)lo)[i * 2 + 0] = __nv_bfloat162(l[0], l[1]);
    ((__nv_bfloat162*)lo)[i * 2 + 1] = __nv_bfloat162(l[2], l[3]);
}

__global__ void prep_all(const float* __restrict__ x,
                         const float* __restrict__ W0, const float* __restrict__ W1,
                         const float* __restrict__ W2, const float* __restrict__ W3,
                         const float* __restrict__ rel_k, const float* __restrict__ rel_v)
{
    int b = blockIdx.x, t = threadIdx.x;
    if (b < 2048) {
        int i = b * 512 + t;
        split4(x, g_xh, g_xl, i);
        split4(x, g_xh, g_xl, i + 256);
    } else if (b < 4096) {
        int z = (b - 2048) >> 9;
        const float* in = (z == 0 ? W0 : z == 1 ? W1 : z == 2 ? W2 : W3);
        int i = ((b - 2048) & 511) * 512 + t;
        split4(in, g_wsp[2 * z], g_wsp[2 * z + 1], i);
        split4(in, g_wsp[2 * z], g_wsp[2 * z + 1], i + 256);
    } else {
        int idx = (b - 4096) * 256 + t;
        float v = rel_k[idx];
        __nv_bfloat16 h = __float2bfloat16(v);
        g_rkh[idx] = h;
        g_rkl[idx] = __float2bfloat16(v - __bfloat162float(h));
        v = rel_v[idx];
        h = __float2bfloat16(v);
        g_rvh[idx] = h;
        g_rvl[idx] = __float2bfloat16(v - __bfloat162float(h));
    }
}

// ---------------------------------------------------------------------------
// GEMM body (R10 proven config): 128x128 tile, BK=32, 8 warps, 2 CTAs/SM.
// ---------------------------------------------------------------------------
#define SPB 80
#define MAT_SM (128 * SPB)
#define BUF_SM (4 * MAT_SM)
#define GEMM_SMEM (2 * BUF_SM)

__device__ __forceinline__ void gemm_body(
    char* sm,
    const __nv_bfloat16* __restrict__ Ah_, const __nv_bfloat16* __restrict__ Al_,
    const __nv_bfloat16* __restrict__ Bh_, const __nv_bfloat16* __restrict__ Bl_,
    const float* __restrict__ bias, float* __restrict__ Cf,
    __nv_bfloat16* __restrict__ Ch, __nv_bfloat16* __restrict__ Cl, int headed)
{
    const uint32_t sb = smem_u32(sm);
    const int t    = threadIdx.x;
    const int wid  = t >> 5;
    const int lane = t & 31;
    const int m0 = blockIdx.y * 128;
    const int n0 = blockIdx.x * 128;
    const int wm = wid >> 2;
    const int wn = wid & 3;

    const char* gb0 = (const char*)(Ah_ + (size_t)m0 * 1024);
    const char* gb1 = (const char*)(Al_ + (size_t)m0 * 1024);
    const char* gb2 = (const char*)(Bh_ + (size_t)n0 * 1024);
    const char* gb3 = (const char*)(Bl_ + (size_t)n0 * 1024);

    auto issue = [&](int chunk, int buf) {
#pragma unroll
        for (int it = 0; it < 8; it++) {
            int id  = t + it * 256;
            int mat = id >> 9;
            int row = (id >> 2) & 127;
            int c16 = id & 3;
            const char* g = (mat == 0 ? gb0 : mat == 1 ? gb1 : mat == 2 ? gb2 : gb3);
            uint32_t sa = sb + buf * BUF_SM + mat * MAT_SM + row * SPB + c16 * 16;
            CP_ASYNC16(sa, g + (size_t)row * 2048 + chunk * 64 + c16 * 16);
        }
        CP_COMMIT();
    };

    float acc[4][4][4];
#pragma unroll
    for (int i = 0; i < 4; i++)
#pragma unroll
        for (int j = 0; j < 4; j++)
#pragma unroll
            for (int r = 0; r < 4; r++) acc[i][j][r] = 0.f;

    issue(0, 0);
    for (int c = 0; c < 32; c++) {
        const int buf = c & 1;
        CP_WAIT(0);
        __syncthreads();
        if (c + 1 < 32) issue(c + 1, buf ^ 1);

        const uint32_t Ahb = sb + buf * BUF_SM;
        const uint32_t Alb = Ahb + MAT_SM;
        const uint32_t Bhb = Ahb + 2 * MAT_SM;
        const uint32_t Blb = Ahb + 3 * MAT_SM;

#pragma unroll
        for (int s = 0; s < 2; s++) {
            uint32_t ah[4][4], al[4][4];
            const int arow = wm * 64 + (lane & 15);
            const int acolB = (((lane >> 4) << 3) + s * 16) * 2;
#pragma unroll
            for (int mf = 0; mf < 4; mf++) {
                uint32_t ad = Ahb + (uint32_t)(arow + mf * 16) * SPB + acolB;
                LDMX4(ah[mf][0], ah[mf][1], ah[mf][2], ah[mf][3], ad);
                ad = Alb + (uint32_t)(arow + mf * 16) * SPB + acolB;
                LDMX4(al[mf][0], al[mf][1], al[mf][2], al[mf][3], ad);
            }
            uint32_t bh[4][2], bl[4][2];
            const int brow = wn * 32 + (lane & 7) + ((lane >> 4) << 3);
            const int bcolB = ((((lane >> 3) & 1) << 3) + s * 16) * 2;
#pragma unroll
            for (int g = 0; g < 2; g++) {
                uint32_t r0, r1, r2, r3;
                uint32_t bd = Bhb + (uint32_t)(brow + g * 16) * SPB + bcolB;
                LDMX4(r0, r1, r2, r3, bd);
                bh[g * 2][0] = r0; bh[g * 2][1] = r1;
                bh[g * 2 + 1][0] = r2; bh[g * 2 + 1][1] = r3;
                bd = Blb + (uint32_t)(brow + g * 16) * SPB + bcolB;
                LDMX4(r0, r1, r2, r3, bd);
                bl[g * 2][0] = r0; bl[g * 2][1] = r1;
                bl[g * 2 + 1][0] = r2; bl[g * 2 + 1][1] = r3;
            }
#pragma unroll
            for (int mf = 0; mf < 4; mf++)
#pragma unroll
                for (int nf = 0; nf < 4; nf++) {
                    MMA16816(acc[mf][nf], ah[mf], bh[nf]);
                    MMA16816(acc[mf][nf], ah[mf], bl[nf]);
                    MMA16816(acc[mf][nf], al[mf], bh[nf]);
                }
        }
    }

#pragma unroll
    for (int mf = 0; mf < 4; mf++) {
#pragma unroll
        for (int nf = 0; nf < 4; nf++) {
            int m = m0 + wm * 64 + mf * 16 + (lane >> 2);
            int n = n0 + wn * 32 + nf * 8 + (lane & 3) * 2;
            float p0 = acc[mf][nf][0] + bias[n];
            float p1 = acc[mf][nf][1] + bias[n + 1];
            float p2 = acc[mf][nf][2] + bias[n];
            float p3 = acc[mf][nf][3] + bias[n + 1];
            size_t off0, off1;
            if (headed) {
                int h = n >> 6, d = n & 63;
                int bb = m >> 10, s1 = m & 1023;
                off0 = ((((size_t)bb * Hh + h) << 10) + s1) * HDd + d;
                off1 = ((((size_t)bb * Hh + h) << 10) + s1 + 8) * HDd + d;
            } else {
                off0 = (size_t)m * 1024 + n;
                off1 = (size_t)(m + 8) * 1024 + n;
            }
            if (Cf) {
                *(float2*)(Cf + off0) = make_float2(p0, p1);
                *(float2*)(Cf + off1) = make_float2(p2, p3);
            }
            if (Ch) {
                __nv_bfloat16 h0 = __float2bfloat16(p0), h1 = __float2bfloat16(p1);
                __nv_bfloat16 h2 = __float2bfloat16(p2), h3 = __float2bfloat16(p3);
                *(__nv_bfloat162*)(Ch + off0) = __nv_bfloat162(h0, h1);
                *(__nv_bfloat162*)(Ch + off1) = __nv_bfloat162(h2, h3);
                __nv_bfloat16 l0 = __float2bfloat16(p0 - __bfloat162float(h0));
                __nv_bfloat16 l1 = __float2bfloat16(p1 - __bfloat162float(h1));
                __nv_bfloat16 l2 = __float2bfloat16(p2 - __bfloat162float(h2));
                __nv_bfloat16 l3 = __float2bfloat16(p3 - __bfloat162float(h3));
                *(__nv_bfloat162*)(Cl + off0) = __nv_bfloat162(l0, l1);
                *(__nv_bfloat162*)(Cl + off1) = __nv_bfloat162(l2, l3);
            }
        }
    }
}

__global__ __launch_bounds__(256, 2)
void gemm_qkv(const float* __restrict__ bq, const float* __restrict__ bk,
              const float* __restrict__ bv)
{
    extern __shared__ char sm[];
    int z = blockIdx.z;
    const float* bias = (z == 0 ? bq : z == 1 ? bk : bv);
    __nv_bfloat16* Ch = (z == 0 ? g_qh : z == 1 ? g_kh : g_vh);
    __nv_bfloat16* Cl = (z == 0 ? g_ql : z == 1 ? g_kl : g_vl);
    gemm_body(sm, g_xh, g_xl, g_wsp[2 * z], g_wsp[2 * z + 1], bias,
              nullptr, Ch, Cl, 1);
}

__global__ __launch_bounds__(256, 2)
void gemm_mma(const __nv_bfloat16* __restrict__ Ah_, const __nv_bfloat16* __restrict__ Al_,
              const __nv_bfloat16* __restrict__ Bh_, const __nv_bfloat16* __restrict__ Bl_,
              const float* __restrict__ bias, float* __restrict__ Cf)
{
    extern __shared__ char sm[];
    gemm_body(sm, Ah_, Al_, Bh_, Bl_, bias, Cf, nullptr, nullptr, 0);
}

// ---------------------------------------------------------------------------
// MMA attention core: uniform 20-tile pipelines; bucket-256 via exact fixups.
// PV v-tiles 1,2 pre-issued during softmax (slots provably free after scores).
// ---------------------------------------------------------------------------
#define SSP  4112u
#define WRP  1104u
#define Q_OFF   0u
#define KV_OFF  9216u
#define KV_BUF  18432u
#define SS_OFF  64512u
#define WR_OFF  196096u
#define ATTN_SMEM 231424

__global__ __launch_bounds__(512, 1)
void attn_mma(const float* __restrict__ rel_k, const float* __restrict__ rel_v)
{
    extern __shared__ char sm[];
    const uint32_t sb = smem_u32(sm);
    const int t = threadIdx.x, lane = t & 31, wid = t >> 5;
    const int bh = blockIdx.y;
    const int i0 = blockIdx.x * 32;

    auto issue_tile = [&](const __nv_bfloat16* sh, const __nv_bfloat16* sl,
                          size_t row0, uint32_t dst) {
#pragma unroll
        for (int it = 0; it < 2; it++) {
            int id = t + it * 512;
            int sel = id >> 9;
            int rid = id & 511;
            int row = rid >> 3, c16 = rid & 7;
            const __nv_bfloat16* s = (sel ? sl : sh) + (row0 + row) * 64 + c16 * 8;
            CP_ASYNC16(dst + (uint32_t)sel * (64 * 144) + row * 144 + c16 * 16, s);
        }
        CP_COMMIT();
    };
    auto issue_q = [&]() {
        int id = t;
        int sel = id >> 8;
        int rid = id & 255;
        int row = rid >> 3, c16 = rid & 7;
        const __nv_bfloat16* s = (sel ? g_ql : g_qh)
                               + ((size_t)bh * 1024 + i0 + row) * 64 + c16 * 8;
        CP_ASYNC16(sb + Q_OFF + (uint32_t)sel * (32 * 144) + row * 144 + c16 * 16, s);
        CP_COMMIT();
    };

    const size_t bhrow = (size_t)bh * 1024;

    issue_q();
    issue_tile(g_kh, g_kl, bhrow, sb + KV_OFF);
    issue_tile(g_kh, g_kl, bhrow + 64, sb + KV_OFF + KV_BUF);

    // ========= unified scores (g<16) + bias window (g>=16), 20 tiles =======
    {
        const int wq = wid >> 3;
        const int wk = wid & 7;
        uint32_t qhf[4][4], qlf[4][4];

        for (int g = 0; g < 20; g++) {
            if (g < 19) { CP_WAIT(1); } else { CP_WAIT(0); }
            __syncthreads();
            if (g + 2 < 20) {
                int tt = g + 2;
                uint32_t dst = sb + KV_OFF + (uint32_t)(tt % 3) * KV_BUF;
                if (tt < 16) issue_tile(g_kh, g_kl, bhrow + (size_t)tt * 64, dst);
                else         issue_tile(g_rkh, g_rkl, (size_t)(tt - 16) * 64, dst);
            }

            if (g == 0) {
#pragma unroll
                for (int s = 0; s < 4; s++) {
                    uint32_t a = sb + Q_OFF + (uint32_t)(wq * 16 + (lane & 15)) * 144
                               + (((lane >> 4) << 3) + s * 16) * 2;
                    LDMX4(qhf[s][0], qhf[s][1], qhf[s][2], qhf[s][3], a);
                    LDMX4(qlf[s][0], qlf[s][1], qlf[s][2], qlf[s][3], a + 4608);
                }
            }

            float a1[4] = {0.f,0.f,0.f,0.f}, a2[4] = {0.f,0.f,0.f,0.f}, a3[4] = {0.f,0.f,0.f,0.f};
            const uint32_t kb = sb + KV_OFF + (uint32_t)(g % 3) * KV_BUF;
#pragma unroll
            for (int s = 0; s < 4; s++) {
                uint32_t addr = kb + (uint32_t)(wk * 8 + (lane & 7)) * 144
                              + ((((lane >> 3) & 1) * 8) + s * 16) * 2;
                uint32_t bh2[2], bl2[2];
                LDMX2(bh2[0], bh2[1], addr);
                LDMX2(bl2[0], bl2[1], addr + 9216);
                MMA16816(a1, qhf[s], bh2);
                MMA16816(a2, qhf[s], bl2);
                MMA16816(a3, qlf[s], bh2);
            }
            int row = wq * 16 + (lane >> 2);
            if (g < 16) {
                int col = g * 64 + wk * 8 + (lane & 3) * 2;
                *(float2*)(sm + SS_OFF + (uint32_t)row * SSP + col * 4) =
                    make_float2(a1[0] + a2[0] + a3[0], a1[1] + a2[1] + a3[1]);
                *(float2*)(sm + SS_OFF + (uint32_t)(row + 8) * SSP + col * 4) =
                    make_float2(a1[2] + a2[2] + a3[2], a1[3] + a2[3] + a3[3]);
            } else {
                int col = (g - 16) * 64 + wk * 8 + (lane & 3) * 2;
                *(float2*)(sm + WR_OFF + (uint32_t)row * WRP + col * 4) =
                    make_float2(a1[0] + a2[0] + a3[0], a1[1] + a2[1] + a3[1]);
                *(float2*)(sm + WR_OFF + (uint32_t)(row + 8) * WRP + col * 4) =
                    make_float2(a1[2] + a2[2] + a3[2], a1[3] + a2[3] + a3[3]);
            }
        }
    }
    __syncthreads();

    // prefetch v tiles 0,1,2 (slots 2,0,1 all free after scores) -> overlap softmax
    issue_tile(g_vh, g_vl, bhrow,       sb + KV_OFF + 2u * KV_BUF);
    issue_tile(g_vh, g_vl, bhrow + 64,  sb + KV_OFF);
    issue_tile(g_vh, g_vl, bhrow + 128, sb + KV_OFF + KV_BUF);

    // ================= softmax (fused bias, reg-resident), 2 rows/warp =====
    float* s2f = (float*)(sm + Q_OFF);   // Q region dead after scores phase
    const float* rk256 = rel_k + 256 * 64;
    for (int rr = 0; rr < 2; rr++) {
        const int row = wid * 2 + rr;
        const int i = i0 + row;
        const float* rp = (const float*)(sm + SS_OFF + (uint32_t)row * SSP);
        const float* qwr = (const float*)(sm + WR_OFF + (uint32_t)row * WRP);

        // exact fixup: v256 = q_row . rel_k[256]
        float v256;
        {
            uint32_t qb = sb + Q_OFF + (uint32_t)row * 144;
            __nv_bfloat16 qh0, ql0, qh1, ql1;
            asm volatile("ld.shared.b16 %0, [%1];" : "=h"(*(uint16_t*)&qh0) : "r"(qb + lane * 2));
            asm volatile("ld.shared.b16 %0, [%1];" : "=h"(*(uint16_t*)&ql0) : "r"(qb + 4608 + lane * 2));
            asm volatile("ld.shared.b16 %0, [%1];" : "=h"(*(uint16_t*)&qh1) : "r"(qb + (lane + 32) * 2));
            asm volatile("ld.shared.b16 %0, [%1];" : "=h"(*(uint16_t*)&ql1) : "r"(qb + 4608 + (lane + 32) * 2));
            v256 = (__bfloat162float(qh0) + __bfloat162float(ql0)) * rk256[lane]
                 + (__bfloat162float(qh1) + __bfloat162float(ql1)) * rk256[lane + 32];
#pragma unroll
            for (int o = 16; o > 0; o >>= 1) v256 += __shfl_xor_sync(0xffffffffu, v256, o);
        }

        float tmp[32];
#pragma unroll
        for (int kk = 0; kk < 32; kk++) {
            int j = lane + kk * 32;
            int rel = j - i;
            rel = rel < -128 ? -128 : (rel > 128 ? 128 : rel);
            float b = (rel == 128) ? v256 : qwr[rel + 128];
            tmp[kk] = (rp[j] + b) * 0.125f;
        }
        float mx = -1e30f;
#pragma unroll
        for (int kk = 0; kk < 32; kk++) mx = fmaxf(mx, tmp[kk]);
#pragma unroll
        for (int o = 16; o > 0; o >>= 1) mx = fmaxf(mx, __shfl_xor_sync(0xffffffffu, mx, o));
        float sum = 0.f;
#pragma unroll
        for (int kk = 0; kk < 32; kk++) { tmp[kk] = __expf(tmp[kk] - mx); sum += tmp[kk]; }
#pragma unroll
        for (int o = 16; o > 0; o >>= 1) sum += __shfl_xor_sync(0xffffffffu, sum, o);
        const float inv = 1.f / sum;

        __syncwarp();
        uint32_t* wrz = (uint32_t*)(sm + WR_OFF + (uint32_t)row * WRP);
        for (int idx = lane; idx < 276; idx += 32) wrz[idx] = 0u;
        __syncwarp();

        __nv_bfloat16* wh_ = (__nv_bfloat16*)wrz;
        __nv_bfloat16* wl_ = wh_ + 280;
        float s0 = 0.f, s2 = 0.f;
#pragma unroll
        for (int kk = 0; kk < 32; kk++) {
            int j = lane + kk * 32;
            float w = tmp[kk] * inv;
            __nv_bfloat16 h = __float2bfloat16(w);
            __nv_bfloat16 l = __float2bfloat16(w - __bfloat162float(h));
            *(__nv_bfloat16*)(sm + SS_OFF + (uint32_t)row * SSP + j * 2) = h;
            *(__nv_bfloat16*)(sm + SS_OFF + (uint32_t)row * SSP + 2064 + j * 2) = l;
            int dlt = j - i;
            if (dlt <= -128)      s0 += w;
            else if (dlt >= 128)  s2 += w;
            else { wh_[dlt + 128] = h; wl_[dlt + 128] = l; }
        }
#pragma unroll
        for (int o = 16; o > 0; o >>= 1) s0 += __shfl_xor_sync(0xffffffffu, s0, o);
#pragma unroll
        for (int o = 16; o > 0; o >>= 1) s2 += __shfl_xor_sync(0xffffffffu, s2, o);
        __syncwarp();
        if (lane == 0) {
            __nv_bfloat16 h0 = __float2bfloat16(s0);
            wh_[0] = h0; wl_[0] = __float2bfloat16(s0 - __bfloat162float(h0));
            s2f[row] = s2;
        }
    }

    // ================= PV: 20 uniform tiles, warp (wm2, wn2 n32, ws4) ======
    const int wm = wid >> 3;
    const int wn = (wid >> 2) & 1;
    const int ws = wid & 3;

    auto issue_pv = [&](int tt) {
        uint32_t dst = sb + KV_OFF + (uint32_t)((tt + 2) % 3) * KV_BUF;
        if (tt < 16) issue_tile(g_vh, g_vl, bhrow + (size_t)tt * 64, dst);
        else         issue_tile(g_rvh, g_rvl, (size_t)(tt - 16) * 64, dst);
    };

    float o1[4][4], o2[4][4], o3[4][4];
#pragma unroll
    for (int nf = 0; nf < 4; nf++)
#pragma unroll
        for (int r = 0; r < 4; r++) { o1[nf][r] = 0.f; o2[nf][r] = 0.f; o3[nf][r] = 0.f; }

    for (int vt = 0; vt < 20; vt++) {
        if (vt == 0)       { CP_WAIT(2); }
        else if (vt < 19)  { CP_WAIT(1); }
        else               { CP_WAIT(0); }
        __syncthreads();
        if (vt >= 1 && vt + 2 <= 19) issue_pv(vt + 2);

        const uint32_t vb = sb + KV_OFF + (uint32_t)((vt + 2) % 3) * KV_BUF;
        uint32_t awh[4], awl[4];
        if (vt < 16) {
            uint32_t aaddr = sb + SS_OFF + (uint32_t)(wm * 16 + (lane & 15)) * SSP
                           + (((lane >> 4) << 3) + vt * 64 + ws * 16) * 2;
            LDMX4(awh[0], awh[1], awh[2], awh[3], aaddr);
            LDMX4(awl[0], awl[1], awl[2], awl[3], aaddr + 2064);
        } else {
            uint32_t abase = sb + WR_OFF + (uint32_t)(wm * 16 + (lane & 15)) * WRP;
            uint32_t acol = (((lane >> 4) << 3) + (vt - 16) * 64 + ws * 16) * 2;
            LDMX4(awh[0], awh[1], awh[2], awh[3], abase + acol);
            LDMX4(awl[0], awl[1], awl[2], awl[3], abase + 560 + acol);
        }
        uint32_t brow = (uint32_t)(ws * 16 + (lane & 7) + ((lane >> 3) & 1) * 8);
        uint32_t bcol = (uint32_t)(wn * 32 + ((lane >> 4) << 3)) * 2;
        uint32_t bvh[8], bvl[8];
        LDMX4T(bvh[0], bvh[1], bvh[2], bvh[3], vb + brow * 144 + bcol);
        LDMX4T(bvh[4], bvh[5], bvh[6], bvh[7], vb + brow * 144 + bcol + 32);
        LDMX4T(bvl[0], bvl[1], bvl[2], bvl[3], vb + 64u * 144u + brow * 144 + bcol);
        LDMX4T(bvl[4], bvl[5], bvl[6], bvl[7], vb + 64u * 144u + brow * 144 + bcol + 32);
#pragma unroll
        for (int nf = 0; nf < 4; nf++) {
            MMA16816(o1[nf], awh, (&bvh[nf * 2]));
            MMA16816(o2[nf], awh, (&bvl[nf * 2]));
            MMA16816(o3[nf], awl, (&bvh[nf * 2]));
        }
    }

    // merge chains
    float of[4][4];
#pragma unroll
    for (int nf = 0; nf < 4; nf++)
#pragma unroll
        for (int r = 0; r < 4; r++)
            of[nf][r] = o1[nf][r] + o2[nf][r] + o3[nf][r];

    // 4-way cross-warp k-reduction over ws; bucket-256 fixup; emit split bf16
    __syncthreads();
    float* red = (float*)(sm + KV_OFF);
    const int widx = wm * 2 + wn;
    if (ws != 0) {
#pragma unroll
        for (int nf = 0; nf < 4; nf++)
            *(float4*)&red[((((widx * 3 + (ws - 1)) * 4) + nf) * 32 + lane) * 4] =
                make_float4(of[nf][0], of[nf][1], of[nf][2], of[nf][3]);
    }
    __syncthreads();
    if (ws == 0) {
        const int bb = bh >> 4, h = bh & 15;
        const int rloc = wm * 16 + (lane >> 2);
        const int row = i0 + rloc;
        const float s2a = s2f[rloc], s2b = s2f[rloc + 8];
        const float* rv256 = rel_v + 256 * 64;
#pragma unroll
        for (int nf = 0; nf < 4; nf++) {
            float f0 = of[nf][0], f1 = of[nf][1], f2 = of[nf][2], f3 = of[nf][3];
#pragma unroll
            for (int e = 0; e < 3; e++) {
                float4 v = *(const float4*)&red[((((widx * 3 + e) * 4) + nf) * 32 + lane) * 4];
                f0 += v.x; f1 += v.y; f2 += v.z; f3 += v.w;
            }
            int dd = wn * 32 + nf * 8 + (lane & 3) * 2;
            float2 rv = *(const float2*)(rv256 + dd);
            f0 += s2a * rv.x; f1 += s2a * rv.y;
            f2 += s2b * rv.x; f3 += s2b * rv.y;
            int d = h * 64 + dd;
            size_t off0 = ((size_t)bb * 1024 + row) * 1024 + d;
            size_t off1 = off0 + 8 * 1024;
            __nv_bfloat16 h0 = __float2bfloat16(f0), h1 = __float2bfloat16(f1);
            __nv_bfloat16 h2 = __float2bfloat16(f2), h3 = __float2bfloat16(f3);
            *(__nv_bfloat162*)(g_xh + off0) = __nv_bfloat162(h0, h1);
            *(__nv_bfloat162*)(g_xh + off1) = __nv_bfloat162(h2, h3);
            __nv_bfloat16 l0 = __float2bfloat16(f0 - __bfloat162float(h0));
            __nv_bfloat16 l1 = __float2bfloat16(f1 - __bfloat162float(h1));
            __nv_bfloat16 l2 = __float2bfloat16(f2 - __bfloat162float(h2));
            __nv_bfloat16 l3 = __float2bfloat16(f3 - __bfloat162float(h3));
            *(__nv_bfloat162*)(g_xl + off0) = __nv_bfloat162(l0, l1);
            *(__nv_bfloat162*)(g_xl + off1) = __nv_bfloat162(l2, l3);
        }
    }
}

// ---------------------------------------------------------------------------
extern "C" void kernel_launch(void* const* d_in, const int* in_sizes, int n_in,
                              void* d_out, int out_size)
{
    const float* x     = (const float*)d_in[0];
    const float* Wq    = (const float*)d_in[1];
    const float* bq    = (const float*)d_in[2];
    const float* Wk    = (const float*)d_in[3];
    const float* bk    = (const float*)d_in[4];
    const float* Wv    = (const float*)d_in[5];
    const float* bv    = (const float*)d_in[6];
    const float* Wo    = (const float*)d_in[7];
    const float* bo    = (const float*)d_in[8];
    const float* rel_k = (const float*)d_in[9];
    const float* rel_v = (const float*)d_in[10];

    __nv_bfloat16 *xh, *xl, *woh, *wol;
    cudaGetSymbolAddress((void**)&xh,  g_xh);
    cudaGetSymbolAddress((void**)&xl,  g_xl);
    cudaGetSymbolAddress((void**)&woh, g_wsp);
    wol = woh + 7 * (size_t)Dd * Dd;
    woh = woh + 6 * (size_t)Dd * Dd;

    cudaFuncSetAttribute(gemm_qkv, cudaFuncAttributeMaxDynamicSharedMemorySize, GEMM_SMEM);
    cudaFuncSetAttribute(gemm_mma, cudaFuncAttributeMaxDynamicSharedMemorySize, GEMM_SMEM);
    cudaFuncSetAttribute(attn_mma, cudaFuncAttributeMaxDynamicSharedMemorySize, ATTN_SMEM);

    dim3 blk(256);

    // unified prep: x split + 4 weight splits + rel tables in one launch
    prep_all<<<4160, blk>>>(x, Wq, Wk, Wv, Wo, rel_k, rel_v);

    // merged QKV projections
    gemm_qkv<<<dim3(Dd / 128, NROW / 128, 3), blk, GEMM_SMEM>>>(bq, bk, bv);

    // attention core
    attn_mma<<<dim3(Ss / 32, Bv * Hh), 512, ATTN_SMEM>>>(rel_k, rel_v);

    // output projection -> d_out
    gemm_mma<<<dim3(Dd / 128, NROW / 128), blk, GEMM_SMEM>>>(xh, xl, woh, wol, bo, (float*)d_out);
}

// round 15
// speedup vs baseline: 1.4417x; 1.3278x over previous
#include <cuda_runtime.h>
#include <cuda_fp16.h>
#include <cstdint>

#define Bv 4
#define Hh 16
#define Ss 1024
#define Dd 1024
#define HDd 64
#define NROW (Bv*Ss)    // 4096
#define BHS (Bv*Hh*Ss)  // 65536

// ---------------- scratch (device globals: allocation-free) ----------------
__device__ __half g_qh[BHS * HDd];
__device__ __half g_ql[BHS * HDd];
__device__ __half g_kh[BHS * HDd];      // k hi only
__device__ __half g_vh[BHS * HDd];      // v hi only
__device__ __half g_rvh[256 * 64];
__device__ __half g_rkh[256 * 64];
__device__ __half g_xh[(size_t)NROW * Dd];
__device__ __half g_xl[(size_t)NROW * Dd];
__device__ __half g_wh4[4][(size_t)Dd * Dd];   // weights hi only: q,k,v,o

// ====================== PTX helpers (family-portable only) ======================
__device__ __forceinline__ uint32_t smem_u32(const void* p) {
    uint32_t a;
    asm("{ .reg .u64 t; cvta.to.shared.u64 t, %1; cvt.u32.u64 %0, t; }" : "=r"(a) : "l"(p));
    return a;
}

#define LDMX4(r0, r1, r2, r3, addr) \
    asm volatile("ldmatrix.sync.aligned.m8n8.x4.shared.b16 {%0,%1,%2,%3}, [%4];" \
                 : "=r"(r0), "=r"(r1), "=r"(r2), "=r"(r3) : "r"(addr))

#define LDMX2(r0, r1, addr) \
    asm volatile("ldmatrix.sync.aligned.m8n8.x2.shared.b16 {%0,%1}, [%2];" \
                 : "=r"(r0), "=r"(r1) : "r"(addr))

#define LDMX4T(r0, r1, r2, r3, addr) \
    asm volatile("ldmatrix.sync.aligned.m8n8.x4.trans.shared.b16 {%0,%1,%2,%3}, [%4];" \
                 : "=r"(r0), "=r"(r1), "=r"(r2), "=r"(r3) : "r"(addr))

#define MMA16816(c, a, b) \
    asm volatile("mma.sync.aligned.m16n8k16.row.col.f32.f16.f16.f32 " \
                 "{%0,%1,%2,%3}, {%4,%5,%6,%7}, {%8,%9}, {%0,%1,%2,%3};" \
                 : "+f"((c)[0]), "+f"((c)[1]), "+f"((c)[2]), "+f"((c)[3]) \
                 : "r"((a)[0]), "r"((a)[1]), "r"((a)[2]), "r"((a)[3]), \
                   "r"((b)[0]), "r"((b)[1]))

#define CP_ASYNC16(s, g) \
    asm volatile("cp.async.cg.shared.global [%0], [%1], 16;" :: "r"(s), "l"(g))
#define CP_COMMIT() asm volatile("cp.async.commit_group;" ::: "memory")
#define CP_WAIT(n)  asm volatile("cp.async.wait_group %0;" :: "n"(n) : "memory")

// ---------------------------------------------------------------------------
// unified prep: [0,2048) x h+l split; [2048,3072) weight hi-only; [3072,3136) rel
// ---------------------------------------------------------------------------
__global__ void prep_all(const float* __restrict__ x,
                         const float* __restrict__ W0, const float* __restrict__ W1,
                         const float* __restrict__ W2, const float* __restrict__ W3,
                         const float* __restrict__ rel_k, const float* __restrict__ rel_v)
{
    int b = blockIdx.x, t = threadIdx.x;
    if (b < 2048) {
        int i = b * 512 + t;
#pragma unroll
        for (int rep = 0; rep < 2; rep++, i += 256) {
            float4 v = ((const float4*)x)[i];
            float vv[4] = {v.x, v.y, v.z, v.w};
            __half h[4], l[4];
#pragma unroll
            for (int j = 0; j < 4; j++) {
                h[j] = __float2half_rn(vv[j]);
                l[j] = __float2half_rn(vv[j] - __half2float(h[j]));
            }
            ((__half2*)g_xh)[i * 2 + 0] = __halves2half2(h[0], h[1]);
            ((__half2*)g_xh)[i * 2 + 1] = __halves2half2(h[2], h[3]);
            ((__half2*)g_xl)[i * 2 + 0] = __halves2half2(l[0], l[1]);
            ((__half2*)g_xl)[i * 2 + 1] = __halves2half2(l[2], l[3]);
        }
    } else if (b < 3072) {
        int id = b - 2048;
        int z = id >> 8;
        const float* in = (z == 0 ? W0 : z == 1 ? W1 : z == 2 ? W2 : W3);
        __half* hi = g_wh4[z];
        int i = (id & 255) * 1024 + t;
#pragma unroll
        for (int rep = 0; rep < 4; rep++, i += 256) {
            float4 v = ((const float4*)in)[i];
            ((__half2*)hi)[i * 2 + 0] = __halves2half2(__float2half_rn(v.x), __float2half_rn(v.y));
            ((__half2*)hi)[i * 2 + 1] = __halves2half2(__float2half_rn(v.z), __float2half_rn(v.w));
        }
    } else {
        int idx = (b - 3072) * 256 + t;
        g_rkh[idx] = __float2half_rn(rel_k[idx]);
        g_rvh[idx] = __float2half_rn(rel_v[idx]);
    }
}

// ---------------------------------------------------------------------------
// GEMM body: 128x128 tile, BK=32, 8 warps (wm2 x wn4, each 64x32),
// fp16x2: A split (hi,lo), B hi only. 3 smem mats/buffer, 2 CTAs/SM.
// ---------------------------------------------------------------------------
#define SPB 80
#define MAT_SM (128 * SPB)          // 10240
#define BUF_SM (3 * MAT_SM)         // 30720
#define GEMM_SMEM (2 * BUF_SM)      // 61440

__device__ __forceinline__ void gemm_body(
    char* sm,
    const __half* __restrict__ Ah_, const __half* __restrict__ Al_,
    const __half* __restrict__ Bh_,
    const float* __restrict__ bias, float* __restrict__ Cf,
    __half* __restrict__ Ch, __half* __restrict__ Cl, int headed)
{
    const uint32_t sb = smem_u32(sm);
    const int t    = threadIdx.x;
    const int wid  = t >> 5;
    const int lane = t & 31;
    const int m0 = blockIdx.y * 128;
    const int n0 = blockIdx.x * 128;
    const int wm = wid >> 2;
    const int wn = wid & 3;

    const char* gb0 = (const char*)(Ah_ + (size_t)m0 * 1024);
    const char* gb1 = (const char*)(Al_ + (size_t)m0 * 1024);
    const char* gb2 = (const char*)(Bh_ + (size_t)n0 * 1024);

    auto issue = [&](int chunk, int buf) {
#pragma unroll
        for (int it = 0; it < 6; it++) {
            int id = t + it * 256;
            const char* g;
            uint32_t sa;
            if (id < 1024) {
                int mat = id >> 9;
                int row = (id >> 2) & 127;
                int c16 = id & 3;
                g = (mat ? gb1 : gb0) + (size_t)row * 2048 + chunk * 64 + c16 * 16;
                sa = sb + buf * BUF_SM + mat * MAT_SM + row * SPB + c16 * 16;
            } else {
                int idb = id - 1024;
                int row = idb >> 2;
                int c16 = idb & 3;
                g = gb2 + (size_t)row * 2048 + chunk * 64 + c16 * 16;
                sa = sb + buf * BUF_SM + 2 * MAT_SM + row * SPB + c16 * 16;
            }
            CP_ASYNC16(sa, g);
        }
        CP_COMMIT();
    };

    float acc[4][4][4];
#pragma unroll
    for (int i = 0; i < 4; i++)
#pragma unroll
        for (int j = 0; j < 4; j++)
#pragma unroll
            for (int r = 0; r < 4; r++) acc[i][j][r] = 0.f;

    issue(0, 0);
    for (int c = 0; c < 32; c++) {
        const int buf = c & 1;
        CP_WAIT(0);
        __syncthreads();
        if (c + 1 < 32) issue(c + 1, buf ^ 1);

        const uint32_t Ahb = sb + buf * BUF_SM;
        const uint32_t Alb = Ahb + MAT_SM;
        const uint32_t Bhb = Ahb + 2 * MAT_SM;

#pragma unroll
        for (int s = 0; s < 2; s++) {
            uint32_t ah[4][4], al[4][4];
            const int arow = wm * 64 + (lane & 15);
            const int acolB = (((lane >> 4) << 3) + s * 16) * 2;
#pragma unroll
            for (int mf = 0; mf < 4; mf++) {
                uint32_t ad = Ahb + (uint32_t)(arow + mf * 16) * SPB + acolB;
                LDMX4(ah[mf][0], ah[mf][1], ah[mf][2], ah[mf][3], ad);
                ad = Alb + (uint32_t)(arow + mf * 16) * SPB + acolB;
                LDMX4(al[mf][0], al[mf][1], al[mf][2], al[mf][3], ad);
            }
            uint32_t bh[4][2];
            const int brow = wn * 32 + (lane & 7) + ((lane >> 4) << 3);
            const int bcolB = ((((lane >> 3) & 1) << 3) + s * 16) * 2;
#pragma unroll
            for (int g = 0; g < 2; g++) {
                uint32_t r0, r1, r2, r3;
                uint32_t bd = Bhb + (uint32_t)(brow + g * 16) * SPB + bcolB;
                LDMX4(r0, r1, r2, r3, bd);
                bh[g * 2][0] = r0; bh[g * 2][1] = r1;
                bh[g * 2 + 1][0] = r2; bh[g * 2 + 1][1] = r3;
            }
#pragma unroll
            for (int mf = 0; mf < 4; mf++)
#pragma unroll
                for (int nf = 0; nf < 4; nf++) {
                    MMA16816(acc[mf][nf], ah[mf], bh[nf]);
                    MMA16816(acc[mf][nf], al[mf], bh[nf]);
                }
        }
    }

#pragma unroll
    for (int mf = 0; mf < 4; mf++) {
#pragma unroll
        for (int nf = 0; nf < 4; nf++) {
            int m = m0 + wm * 64 + mf * 16 + (lane >> 2);
            int n = n0 + wn * 32 + nf * 8 + (lane & 3) * 2;
            float p0 = acc[mf][nf][0] + bias[n];
            float p1 = acc[mf][nf][1] + bias[n + 1];
            float p2 = acc[mf][nf][2] + bias[n];
            float p3 = acc[mf][nf][3] + bias[n + 1];
            size_t off0, off1;
            if (headed) {
                int h = n >> 6, d = n & 63;
                int bb = m >> 10, s1 = m & 1023;
                off0 = ((((size_t)bb * Hh + h) << 10) + s1) * HDd + d;
                off1 = ((((size_t)bb * Hh + h) << 10) + s1 + 8) * HDd + d;
            } else {
                off0 = (size_t)m * 1024 + n;
                off1 = (size_t)(m + 8) * 1024 + n;
            }
            if (Cf) {
                *(float2*)(Cf + off0) = make_float2(p0, p1);
                *(float2*)(Cf + off1) = make_float2(p2, p3);
            }
            if (Ch) {
                __half h0 = __float2half_rn(p0), h1 = __float2half_rn(p1);
                __half h2 = __float2half_rn(p2), h3 = __float2half_rn(p3);
                *(__half2*)(Ch + off0) = __halves2half2(h0, h1);
                *(__half2*)(Ch + off1) = __halves2half2(h2, h3);
                if (Cl) {
                    __half l0 = __float2half_rn(p0 - __half2float(h0));
                    __half l1 = __float2half_rn(p1 - __half2float(h1));
                    __half l2 = __float2half_rn(p2 - __half2float(h2));
                    __half l3 = __float2half_rn(p3 - __half2float(h3));
                    *(__half2*)(Cl + off0) = __halves2half2(l0, l1);
                    *(__half2*)(Cl + off1) = __halves2half2(l2, l3);
                }
            }
        }
    }
}

__global__ __launch_bounds__(256, 2)
void gemm_qkv(const float* __restrict__ bq, const float* __restrict__ bk,
              const float* __restrict__ bv)
{
    extern __shared__ char sm[];
    int z = blockIdx.z;
    const float* bias = (z == 0 ? bq : z == 1 ? bk : bv);
    __half* Ch = (z == 0 ? g_qh : z == 1 ? g_kh : g_vh);
    __half* Cl = (z == 0 ? g_ql : nullptr);
    gemm_body(sm, g_xh, g_xl, g_wh4[z], bias, nullptr, Ch, Cl, 1);
}

__global__ __launch_bounds__(256, 2)
void gemm_out(const float* __restrict__ bo, float* __restrict__ Cf)
{
    extern __shared__ char sm[];
    gemm_body(sm, g_xh, g_xl, g_wh4[3], bo, Cf, nullptr, nullptr, 0);
}

// ---------------------------------------------------------------------------
// MMA attention core (fp16x2): uniform 20-tile pipelines, hi-only K/V tiles,
// bucket-256 via exact fp32 fixups, output emitted as fp16 h+l to g_xh/g_xl.
// smem: Q 9216 | KV 3x9216 | ss 32x4112 | wr 32x1104   = 203776 B
// ---------------------------------------------------------------------------
#define SSP  4112u
#define WRP  1104u
#define Q_OFF   0u
#define KV_OFF  9216u
#define KV_BUF  9216u
#define SS_OFF  36864u
#define WR_OFF  168448u
#define ATTN_SMEM 203776

__global__ __launch_bounds__(512, 1)
void attn_mma(const float* __restrict__ rel_k, const float* __restrict__ rel_v)
{
    extern __shared__ char sm[];
    const uint32_t sb = smem_u32(sm);
    const int t = threadIdx.x, lane = t & 31, wid = t >> 5;
    const int bh = blockIdx.y;
    const int i0 = blockIdx.x * 32;

    // 64-row hi-only tile: 512 chunks of 16B, one per thread
    auto issue_tile = [&](const __half* src, size_t row0, uint32_t dst) {
        int row = t >> 3, c16 = t & 7;
        CP_ASYNC16(dst + (uint32_t)row * 144 + c16 * 16,
                   src + (row0 + row) * 64 + c16 * 8);
        CP_COMMIT();
    };
    auto issue_q = [&]() {
        int sel = t >> 8;
        int rid = t & 255;
        int row = rid >> 3, c16 = rid & 7;
        const __half* s = (sel ? g_ql : g_qh)
                        + ((size_t)bh * 1024 + i0 + row) * 64 + c16 * 8;
        CP_ASYNC16(sb + Q_OFF + (uint32_t)sel * 4608 + row * 144 + c16 * 16, s);
        CP_COMMIT();
    };

    const size_t bhrow = (size_t)bh * 1024;

    issue_q();
    issue_tile(g_kh, bhrow, sb + KV_OFF);
    issue_tile(g_kh, bhrow + 64, sb + KV_OFF + KV_BUF);

    // ========= unified scores (g<16) + bias window (g>=16), 20 tiles =======
    {
        const int wq = wid >> 3;
        const int wk = wid & 7;
        uint32_t qhf[4][4], qlf[4][4];

        for (int g = 0; g < 20; g++) {
            if (g < 19) { CP_WAIT(1); } else { CP_WAIT(0); }
            __syncthreads();
            if (g + 2 < 20) {
                int tt = g + 2;
                uint32_t dst = sb + KV_OFF + (uint32_t)(tt % 3) * KV_BUF;
                if (tt < 16) issue_tile(g_kh, bhrow + (size_t)tt * 64, dst);
                else         issue_tile(g_rkh, (size_t)(tt - 16) * 64, dst);
            }

            if (g == 0) {
#pragma unroll
                for (int s = 0; s < 4; s++) {
                    uint32_t a = sb + Q_OFF + (uint32_t)(wq * 16 + (lane & 15)) * 144
                               + (((lane >> 4) << 3) + s * 16) * 2;
                    LDMX4(qhf[s][0], qhf[s][1], qhf[s][2], qhf[s][3], a);
                    LDMX4(qlf[s][0], qlf[s][1], qlf[s][2], qlf[s][3], a + 4608);
                }
            }

            float a1[4] = {0.f,0.f,0.f,0.f}, a2[4] = {0.f,0.f,0.f,0.f};
            const uint32_t kb = sb + KV_OFF + (uint32_t)(g % 3) * KV_BUF;
#pragma unroll
            for (int s = 0; s < 4; s++) {
                uint32_t addr = kb + (uint32_t)(wk * 8 + (lane & 7)) * 144
                              + ((((lane >> 3) & 1) * 8) + s * 16) * 2;
                uint32_t bh2[2];
                LDMX2(bh2[0], bh2[1], addr);
                MMA16816(a1, qhf[s], bh2);
                MMA16816(a2, qlf[s], bh2);
            }
            int row = wq * 16 + (lane >> 2);
            if (g < 16) {
                int col = g * 64 + wk * 8 + (lane & 3) * 2;
                *(float2*)(sm + SS_OFF + (uint32_t)row * SSP + col * 4) =
                    make_float2(a1[0] + a2[0], a1[1] + a2[1]);
                *(float2*)(sm + SS_OFF + (uint32_t)(row + 8) * SSP + col * 4) =
                    make_float2(a1[2] + a2[2], a1[3] + a2[3]);
            } else {
                int col = (g - 16) * 64 + wk * 8 + (lane & 3) * 2;
                *(float2*)(sm + WR_OFF + (uint32_t)row * WRP + col * 4) =
                    make_float2(a1[0] + a2[0], a1[1] + a2[1]);
                *(float2*)(sm + WR_OFF + (uint32_t)(row + 8) * WRP + col * 4) =
                    make_float2(a1[2] + a2[2], a1[3] + a2[3]);
            }
        }
    }
    __syncthreads();

    // prefetch v tiles 0,1,2 (slots 2,0,1 free after scores) -> overlap softmax
    issue_tile(g_vh, bhrow,       sb + KV_OFF + 2u * KV_BUF);
    issue_tile(g_vh, bhrow + 64,  sb + KV_OFF);
    issue_tile(g_vh, bhrow + 128, sb + KV_OFF + KV_BUF);

    // ================= softmax (fused bias, reg-resident), 2 rows/warp =====
    const float* rk256 = rel_k + 256 * 64;
    for (int rr = 0; rr < 2; rr++) {
        const int row = wid * 2 + rr;
        const int i = i0 + row;
        const float* rp = (const float*)(sm + SS_OFF + (uint32_t)row * SSP);
        const float* qwr = (const float*)(sm + WR_OFF + (uint32_t)row * WRP);

        // exact fixup: v256 = q_row . rel_k[256]   (fp32)
        float v256;
        {
            uint32_t qb = sb + Q_OFF + (uint32_t)row * 144;
            uint16_t qh0, ql0, qh1, ql1;
            asm volatile("ld.shared.b16 %0, [%1];" : "=h"(qh0) : "r"(qb + lane * 2));
            asm volatile("ld.shared.b16 %0, [%1];" : "=h"(ql0) : "r"(qb + 4608 + lane * 2));
            asm volatile("ld.shared.b16 %0, [%1];" : "=h"(qh1) : "r"(qb + (lane + 32) * 2));
            asm volatile("ld.shared.b16 %0, [%1];" : "=h"(ql1) : "r"(qb + 4608 + (lane + 32) * 2));
            v256 = (__half2float(*(__half*)&qh0) + __half2float(*(__half*)&ql0)) * rk256[lane]
                 + (__half2float(*(__half*)&qh1) + __half2float(*(__half*)&ql1)) * rk256[lane + 32];
#pragma unroll
            for (int o = 16; o > 0; o >>= 1) v256 += __shfl_xor_sync(0xffffffffu, v256, o);
        }

        float tmp[32];
#pragma unroll
        for (int kk = 0; kk < 32; kk++) {
            int j = lane + kk * 32;
            int rel = j - i;
            rel = rel < -128 ? -128 : (rel > 128 ? 128 : rel);
            float b = (rel == 128) ? v256 : qwr[rel + 128];
            tmp[kk] = (rp[j] + b) * 0.125f;
        }
        float mx = -1e30f;
#pragma unroll
        for (int kk = 0; kk < 32; kk++) mx = fmaxf(mx, tmp[kk]);
#pragma unroll
        for (int o = 16; o > 0; o >>= 1) mx = fmaxf(mx, __shfl_xor_sync(0xffffffffu, mx, o));
        float sum = 0.f;
#pragma unroll
        for (int kk = 0; kk < 32; kk++) { tmp[kk] = __expf(tmp[kk] - mx); sum += tmp[kk]; }
#pragma unroll
        for (int o = 16; o > 0; o >>= 1) sum += __shfl_xor_sync(0xffffffffu, sum, o);
        const float inv = 1.f / sum;

        __syncwarp();   // all qw reads of this row done before overwrite
        uint32_t* wrz = (uint32_t*)(sm + WR_OFF + (uint32_t)row * WRP);
        for (int idx = lane; idx < 276; idx += 32) wrz[idx] = 0u;
        __syncwarp();

        __half* wh_ = (__half*)wrz;          // buckets [0,272) at bytes [0,544)
        __half* wl_ = wh_ + 280;             // bytes [560,1104)
        float s0 = 0.f, s2 = 0.f;
#pragma unroll
        for (int kk = 0; kk < 32; kk++) {
            int j = lane + kk * 32;
            float w = tmp[kk] * inv;
            __half h = __float2half_rn(w);
            __half l = __float2half_rn(w - __half2float(h));
            *(__half*)(sm + SS_OFF + (uint32_t)row * SSP + j * 2) = h;
            *(__half*)(sm + SS_OFF + (uint32_t)row * SSP + 2064 + j * 2) = l;
            int dlt = j - i;
            if (dlt <= -128)      s0 += w;
            else if (dlt >= 128)  s2 += w;
            else { wh_[dlt + 128] = h; wl_[dlt + 128] = l; }
        }
#pragma unroll
        for (int o = 16; o > 0; o >>= 1) s0 += __shfl_xor_sync(0xffffffffu, s0, o);
#pragma unroll
        for (int o = 16; o > 0; o >>= 1) s2 += __shfl_xor_sync(0xffffffffu, s2, o);
        __syncwarp();
        if (lane == 0) {
            __half h0 = __float2half_rn(s0);
            wh_[0] = h0; wl_[0] = __float2half_rn(s0 - __half2float(h0));
            *(float*)(sm + WR_OFF + (uint32_t)row * WRP + 544) = s2;   // gap slot
        }
    }

    // ================= PV: 20 uniform tiles, warp (wm2, wn2 n32, ws4) ======
    const int wm = wid >> 3;
    const int wn = (wid >> 2) & 1;
    const int ws = wid & 3;

    auto issue_pv = [&](int tt) {
        uint32_t dst = sb + KV_OFF + (uint32_t)((tt + 2) % 3) * KV_BUF;
        if (tt < 16) issue_tile(g_vh, bhrow + (size_t)tt * 64, dst);
        else         issue_tile(g_rvh, (size_t)(tt - 16) * 64, dst);
    };

    float o1[4][4], o2[4][4];
#pragma unroll
    for (int nf = 0; nf < 4; nf++)
#pragma unroll
        for (int r = 0; r < 4; r++) { o1[nf][r] = 0.f; o2[nf][r] = 0.f; }

    for (int vt = 0; vt < 20; vt++) {
        if (vt == 0)       { CP_WAIT(2); }
        else if (vt < 19)  { CP_WAIT(1); }
        else               { CP_WAIT(0); }
        __syncthreads();
        if (vt >= 1 && vt + 2 <= 19) issue_pv(vt + 2);

        const uint32_t vb = sb + KV_OFF + (uint32_t)((vt + 2) % 3) * KV_BUF;
        uint32_t awh[4], awl[4];
        if (vt < 16) {
            uint32_t aaddr = sb + SS_OFF + (uint32_t)(wm * 16 + (lane & 15)) * SSP
                           + (((lane >> 4) << 3) + vt * 64 + ws * 16) * 2;
            LDMX4(awh[0], awh[1], awh[2], awh[3], aaddr);
            LDMX4(awl[0], awl[1], awl[2], awl[3], aaddr + 2064);
        } else {
            uint32_t abase = sb + WR_OFF + (uint32_t)(wm * 16 + (lane & 15)) * WRP;
            uint32_t acol = (((lane >> 4) << 3) + (vt - 16) * 64 + ws * 16) * 2;
            LDMX4(awh[0], awh[1], awh[2], awh[3], abase + acol);
            LDMX4(awl[0], awl[1], awl[2], awl[3], abase + 560 + acol);
        }
        uint32_t brow = (uint32_t)(ws * 16 + (lane & 7) + ((lane >> 3) & 1) * 8);
        uint32_t bcol = (uint32_t)(wn * 32 + ((lane >> 4) << 3)) * 2;
        uint32_t bvh[8];
        LDMX4T(bvh[0], bvh[1], bvh[2], bvh[3], vb + brow * 144 + bcol);
        LDMX4T(bvh[4], bvh[5], bvh[6], bvh[7], vb + brow * 144 + bcol + 32);
#pragma unroll
        for (int nf = 0; nf < 4; nf++) {
            MMA16816(o1[nf], awh, (&bvh[nf * 2]));
            MMA16816(o2[nf], awl, (&bvh[nf * 2]));
        }
    }

    // merge chains
    float of[4][4];
#pragma unroll
    for (int nf = 0; nf < 4; nf++)
#pragma unroll
        for (int r = 0; r < 4; r++)
            of[nf][r] = o1[nf][r] + o2[nf][r];

    // 4-way cross-warp k-reduction over ws; bucket-256 fixup; emit fp16 h+l
    __syncthreads();
    float* red = (float*)(sm + KV_OFF);      // 24KB scratch in KV region
    const int widx = wm * 2 + wn;
    if (ws != 0) {
#pragma unroll
        for (int nf = 0; nf < 4; nf++)
            *(float4*)&red[((((widx * 3 + (ws - 1)) * 4) + nf) * 32 + lane) * 4] =
                make_float4(of[nf][0], of[nf][1], of[nf][2], of[nf][3]);
    }
    __syncthreads();
    if (ws == 0) {
        const int bb = bh >> 4, h = bh & 15;
        const int rloc = wm * 16 + (lane >> 2);
        const int row = i0 + rloc;
        const float s2a = *(const float*)(sm + WR_OFF + (uint32_t)rloc * WRP + 544);
        const float s2b = *(const float*)(sm + WR_OFF + (uint32_t)(rloc + 8) * WRP + 544);
        const float* rv256 = rel_v + 256 * 64;
#pragma unroll
        for (int nf = 0; nf < 4; nf++) {
            float f0 = of[nf][0], f1 = of[nf][1], f2 = of[nf][2], f3 = of[nf][3];
#pragma unroll
            for (int e = 0; e < 3; e++) {
                float4 v = *(const float4*)&red[((((widx * 3 + e) * 4) + nf) * 32 + lane) * 4];
                f0 += v.x; f1 += v.y; f2 += v.z; f3 += v.w;
            }
            int dd = wn * 32 + nf * 8 + (lane & 3) * 2;
            float2 rv = *(const float2*)(rv256 + dd);
            f0 += s2a * rv.x; f1 += s2a * rv.y;
            f2 += s2b * rv.x; f3 += s2b * rv.y;
            int d = h * 64 + dd;
            size_t off0 = ((size_t)bb * 1024 + row) * 1024 + d;
            size_t off1 = off0 + 8 * 1024;
            __half h0 = __float2half_rn(f0), h1 = __float2half_rn(f1);
            __half h2 = __float2half_rn(f2), h3 = __float2half_rn(f3);
            *(__half2*)(g_xh + off0) = __halves2half2(h0, h1);
            *(__half2*)(g_xh + off1) = __halves2half2(h2, h3);
            __half l0 = __float2half_rn(f0 - __half2float(h0));
            __half l1 = __float2half_rn(f1 - __half2float(h1));
            __half l2 = __float2half_rn(f2 - __half2float(h2));
            __half l3 = __float2half_rn(f3 - __half2float(h3));
            *(__half2*)(g_xl + off0) = __halves2half2(l0, l1);
            *(__half2*)(g_xl + off1) = __halves2half2(l2, l3);
        }
    }
}

// ---------------------------------------------------------------------------
extern "C" void kernel_launch(void* const* d_in, const int* in_sizes, int n_in,
                              void* d_out, int out_size)
{
    const float* x     = (const float*)d_in[0];
    const float* Wq    = (const float*)d_in[1];
    const float* bq    = (const float*)d_in[2];
    const float* Wk    = (const float*)d_in[3];
    const float* bk    = (const float*)d_in[4];
    const float* Wv    = (const float*)d_in[5];
    const float* bv    = (const float*)d_in[6];
    const float* Wo    = (const float*)d_in[7];
    const float* bo    = (const float*)d_in[8];
    const float* rel_k = (const float*)d_in[9];
    const float* rel_v = (const float*)d_in[10];

    cudaFuncSetAttribute(gemm_qkv, cudaFuncAttributeMaxDynamicSharedMemorySize, GEMM_SMEM);
    cudaFuncSetAttribute(gemm_out, cudaFuncAttributeMaxDynamicSharedMemorySize, GEMM_SMEM);
    cudaFuncSetAttribute(attn_mma, cudaFuncAttributeMaxDynamicSharedMemorySize, ATTN_SMEM);

    dim3 blk(256);

    // unified prep: x h+l split + weight hi splits + rel tables
    prep_all<<<3136, blk>>>(x, Wq, Wk, Wv, Wo, rel_k, rel_v);

    // merged QKV projections (fp16x2)
    gemm_qkv<<<dim3(Dd / 128, NROW / 128, 3), blk, GEMM_SMEM>>>(bq, bk, bv);

    // attention core
    attn_mma<<<dim3(Ss / 32, Bv * Hh), 512, ATTN_SMEM>>>(rel_k, rel_v);

    // output projection -> d_out
    gemm_out<<<dim3(Dd / 128, NROW / 128), blk, GEMM_SMEM>>>(bo, (float*)d_out);
}

// round 16
// speedup vs baseline: 1.6726x; 1.1602x over previous
#include <cuda_runtime.h>
#include <cuda_fp16.h>
#include <cstdint>

#define Bv 4
#define Hh 16
#define Ss 1024
#define Dd 1024
#define HDd 64
#define NROW (Bv*Ss)    // 4096
#define BHS (Bv*Hh*Ss)  // 65536

// ---------------- scratch (device globals: allocation-free) ----------------
__device__ __half g_qh[BHS * HDd];
__device__ __half g_kh[BHS * HDd];
__device__ __half g_vh[BHS * HDd];
__device__ __half g_rvh[256 * 64];
__device__ __half g_rkh[256 * 64];
__device__ __half g_xh[(size_t)NROW * Dd];
__device__ __half g_xl[(size_t)NROW * Dd];
__device__ __half g_wh4[4][(size_t)Dd * Dd];   // weights hi only: q,k,v,o

// ====================== PTX helpers (family-portable only) ======================
__device__ __forceinline__ uint32_t smem_u32(const void* p) {
    uint32_t a;
    asm("{ .reg .u64 t; cvta.to.shared.u64 t, %1; cvt.u32.u64 %0, t; }" : "=r"(a) : "l"(p));
    return a;
}

#define LDMX4(r0, r1, r2, r3, addr) \
    asm volatile("ldmatrix.sync.aligned.m8n8.x4.shared.b16 {%0,%1,%2,%3}, [%4];" \
                 : "=r"(r0), "=r"(r1), "=r"(r2), "=r"(r3) : "r"(addr))

#define LDMX2(r0, r1, addr) \
    asm volatile("ldmatrix.sync.aligned.m8n8.x2.shared.b16 {%0,%1}, [%2];" \
                 : "=r"(r0), "=r"(r1) : "r"(addr))

#define LDMX4T(r0, r1, r2, r3, addr) \
    asm volatile("ldmatrix.sync.aligned.m8n8.x4.trans.shared.b16 {%0,%1,%2,%3}, [%4];" \
                 : "=r"(r0), "=r"(r1), "=r"(r2), "=r"(r3) : "r"(addr))

#define MMA16816(c, a, b) \
    asm volatile("mma.sync.aligned.m16n8k16.row.col.f32.f16.f16.f32 " \
                 "{%0,%1,%2,%3}, {%4,%5,%6,%7}, {%8,%9}, {%0,%1,%2,%3};" \
                 : "+f"((c)[0]), "+f"((c)[1]), "+f"((c)[2]), "+f"((c)[3]) \
                 : "r"((a)[0]), "r"((a)[1]), "r"((a)[2]), "r"((a)[3]), \
                   "r"((b)[0]), "r"((b)[1]))

#define CP_ASYNC16(s, g) \
    asm volatile("cp.async.cg.shared.global [%0], [%1], 16;" :: "r"(s), "l"(g))
#define CP_COMMIT() asm volatile("cp.async.commit_group;" ::: "memory")
#define CP_WAIT(n)  asm volatile("cp.async.wait_group %0;" :: "n"(n) : "memory")

// ---------------------------------------------------------------------------
// unified prep: [0,2048) x h+l split; [2048,3072) weight hi-only; [3072,3136) rel
// ---------------------------------------------------------------------------
__global__ void prep_all(const float* __restrict__ x,
                         const float* __restrict__ W0, const float* __restrict__ W1,
                         const float* __restrict__ W2, const float* __restrict__ W3,
                         const float* __restrict__ rel_k, const float* __restrict__ rel_v)
{
    int b = blockIdx.x, t = threadIdx.x;
    if (b < 2048) {
        int i = b * 512 + t;
#pragma unroll
        for (int rep = 0; rep < 2; rep++, i += 256) {
            float4 v = ((const float4*)x)[i];
            float vv[4] = {v.x, v.y, v.z, v.w};
            __half h[4], l[4];
#pragma unroll
            for (int j = 0; j < 4; j++) {
                h[j] = __float2half_rn(vv[j]);
                l[j] = __float2half_rn(vv[j] - __half2float(h[j]));
            }
            ((__half2*)g_xh)[i * 2 + 0] = __halves2half2(h[0], h[1]);
            ((__half2*)g_xh)[i * 2 + 1] = __halves2half2(h[2], h[3]);
            ((__half2*)g_xl)[i * 2 + 0] = __halves2half2(l[0], l[1]);
            ((__half2*)g_xl)[i * 2 + 1] = __halves2half2(l[2], l[3]);
        }
    } else if (b < 3072) {
        int id = b - 2048;
        int z = id >> 8;
        const float* in = (z == 0 ? W0 : z == 1 ? W1 : z == 2 ? W2 : W3);
        __half* hi = g_wh4[z];
        int i = (id & 255) * 1024 + t;
#pragma unroll
        for (int rep = 0; rep < 4; rep++, i += 256) {
            float4 v = ((const float4*)in)[i];
            ((__half2*)hi)[i * 2 + 0] = __halves2half2(__float2half_rn(v.x), __float2half_rn(v.y));
            ((__half2*)hi)[i * 2 + 1] = __halves2half2(__float2half_rn(v.z), __float2half_rn(v.w));
        }
    } else {
        int idx = (b - 3072) * 256 + t;
        g_rkh[idx] = __float2half_rn(rel_k[idx]);
        g_rvh[idx] = __float2half_rn(rel_v[idx]);
    }
}

// ---------------------------------------------------------------------------
// GEMM body: 128x128 tile, BK=32, 8 warps (wm2 x wn4, each 64x32).
// SPLIT_A: (Ah+Al)*Bh (3 smem mats). else Ah*Bh (2 mats). 2 CTAs/SM.
// ---------------------------------------------------------------------------
#define SPB 80
#define MAT_SM (128 * SPB)               // 10240

template <bool SPLIT_A>
__device__ __forceinline__ void gemm_body(
    char* sm,
    const __half* __restrict__ Ah_, const __half* __restrict__ Al_,
    const __half* __restrict__ Bh_,
    const float* __restrict__ bias, float* __restrict__ Cf,
    __half* __restrict__ Ch, int headed)
{
    constexpr int NM = SPLIT_A ? 3 : 2;
    constexpr uint32_t BUF = NM * MAT_SM;
    const uint32_t sb = smem_u32(sm);
    const int t    = threadIdx.x;
    const int wid  = t >> 5;
    const int lane = t & 31;
    const int m0 = blockIdx.y * 128;
    const int n0 = blockIdx.x * 128;
    const int wm = wid >> 2;
    const int wn = wid & 3;

    const char* gb0 = (const char*)(Ah_ + (size_t)m0 * 1024);
    const char* gb1 = SPLIT_A ? (const char*)(Al_ + (size_t)m0 * 1024) : nullptr;
    const char* gb2 = (const char*)(Bh_ + (size_t)n0 * 1024);

    auto issue = [&](int chunk, int buf) {
#pragma unroll
        for (int it = 0; it < NM * 2; it++) {
            int id = t + it * 256;
            const char* g;
            uint32_t sa;
            int mat = id >> 9;               // 0..NM-1
            int row = (id >> 2) & 127;
            int c16 = id & 3;
            const char* base = (mat == 0 ? gb0 : (SPLIT_A && mat == 1) ? gb1 : gb2);
            g = base + (size_t)row * 2048 + chunk * 64 + c16 * 16;
            sa = sb + buf * BUF + mat * MAT_SM + row * SPB + c16 * 16;
            CP_ASYNC16(sa, g);
        }
        CP_COMMIT();
    };

    float acc[4][4][4];
#pragma unroll
    for (int i = 0; i < 4; i++)
#pragma unroll
        for (int j = 0; j < 4; j++)
#pragma unroll
            for (int r = 0; r < 4; r++) acc[i][j][r] = 0.f;

    issue(0, 0);
    for (int c = 0; c < 32; c++) {
        const int buf = c & 1;
        CP_WAIT(0);
        __syncthreads();
        if (c + 1 < 32) issue(c + 1, buf ^ 1);

        const uint32_t Ahb = sb + buf * BUF;
        const uint32_t Alb = Ahb + MAT_SM;
        const uint32_t Bhb = Ahb + (NM - 1) * MAT_SM;

#pragma unroll
        for (int s = 0; s < 2; s++) {
            uint32_t ah[4][4], al[4][4];
            const int arow = wm * 64 + (lane & 15);
            const int acolB = (((lane >> 4) << 3) + s * 16) * 2;
#pragma unroll
            for (int mf = 0; mf < 4; mf++) {
                uint32_t ad = Ahb + (uint32_t)(arow + mf * 16) * SPB + acolB;
                LDMX4(ah[mf][0], ah[mf][1], ah[mf][2], ah[mf][3], ad);
                if (SPLIT_A) {
                    ad = Alb + (uint32_t)(arow + mf * 16) * SPB + acolB;
                    LDMX4(al[mf][0], al[mf][1], al[mf][2], al[mf][3], ad);
                }
            }
            uint32_t bh[4][2];
            const int brow = wn * 32 + (lane & 7) + ((lane >> 4) << 3);
            const int bcolB = ((((lane >> 3) & 1) << 3) + s * 16) * 2;
#pragma unroll
            for (int g = 0; g < 2; g++) {
                uint32_t r0, r1, r2, r3;
                uint32_t bd = Bhb + (uint32_t)(brow + g * 16) * SPB + bcolB;
                LDMX4(r0, r1, r2, r3, bd);
                bh[g * 2][0] = r0; bh[g * 2][1] = r1;
                bh[g * 2 + 1][0] = r2; bh[g * 2 + 1][1] = r3;
            }
#pragma unroll
            for (int mf = 0; mf < 4; mf++)
#pragma unroll
                for (int nf = 0; nf < 4; nf++) {
                    MMA16816(acc[mf][nf], ah[mf], bh[nf]);
                    if (SPLIT_A) MMA16816(acc[mf][nf], al[mf], bh[nf]);
                }
        }
    }

#pragma unroll
    for (int mf = 0; mf < 4; mf++) {
#pragma unroll
        for (int nf = 0; nf < 4; nf++) {
            int m = m0 + wm * 64 + mf * 16 + (lane >> 2);
            int n = n0 + wn * 32 + nf * 8 + (lane & 3) * 2;
            float p0 = acc[mf][nf][0] + bias[n];
            float p1 = acc[mf][nf][1] + bias[n + 1];
            float p2 = acc[mf][nf][2] + bias[n];
            float p3 = acc[mf][nf][3] + bias[n + 1];
            size_t off0, off1;
            if (headed) {
                int h = n >> 6, d = n & 63;
                int bb = m >> 10, s1 = m & 1023;
                off0 = ((((size_t)bb * Hh + h) << 10) + s1) * HDd + d;
                off1 = ((((size_t)bb * Hh + h) << 10) + s1 + 8) * HDd + d;
            } else {
                off0 = (size_t)m * 1024 + n;
                off1 = (size_t)(m + 8) * 1024 + n;
            }
            if (Cf) {
                *(float2*)(Cf + off0) = make_float2(p0, p1);
                *(float2*)(Cf + off1) = make_float2(p2, p3);
            }
            if (Ch) {
                *(__half2*)(Ch + off0) = __halves2half2(__float2half_rn(p0), __float2half_rn(p1));
                *(__half2*)(Ch + off1) = __halves2half2(__float2half_rn(p2), __float2half_rn(p3));
            }
        }
    }
}

#define GEMM_SMEM_QKV (2 * 3 * MAT_SM)   // 61440
#define GEMM_SMEM_OUT (2 * 2 * MAT_SM)   // 40960

__global__ __launch_bounds__(256, 2)
void gemm_qkv(const float* __restrict__ bq, const float* __restrict__ bk,
              const float* __restrict__ bv)
{
    extern __shared__ char sm[];
    int z = blockIdx.z;
    const float* bias = (z == 0 ? bq : z == 1 ? bk : bv);
    __half* Ch = (z == 0 ? g_qh : z == 1 ? g_kh : g_vh);
    gemm_body<true>(sm, g_xh, g_xl, g_wh4[z], bias, nullptr, Ch, 1);
}

__global__ __launch_bounds__(256, 2)
void gemm_out(const float* __restrict__ bo, float* __restrict__ Cf)
{
    extern __shared__ char sm[];
    gemm_body<false>(sm, g_xh, nullptr, g_wh4[3], bo, Cf, nullptr, 0);
}

// ---------------------------------------------------------------------------
// MMA attention core (fp16, single-product chains): q/w hi-only.
// smem: Q 4608 | KV 3x9216 | ss 32x4112 | wr 32x1104  = 199168 B
// ---------------------------------------------------------------------------
#define SSP  4112u
#define WRP  1104u
#define Q_OFF   0u
#define KV_OFF  4608u
#define KV_BUF  9216u
#define SS_OFF  32256u
#define WR_OFF  163840u
#define ATTN_SMEM 199168

__global__ __launch_bounds__(512, 1)
void attn_mma(const float* __restrict__ rel_k, const float* __restrict__ rel_v)
{
    extern __shared__ char sm[];
    const uint32_t sb = smem_u32(sm);
    const int t = threadIdx.x, lane = t & 31, wid = t >> 5;
    const int bh = blockIdx.y;
    const int i0 = blockIdx.x * 32;

    auto issue_tile = [&](const __half* src, size_t row0, uint32_t dst) {
        int row = t >> 3, c16 = t & 7;
        CP_ASYNC16(dst + (uint32_t)row * 144 + c16 * 16,
                   src + (row0 + row) * 64 + c16 * 8);
        CP_COMMIT();
    };
    auto issue_q = [&]() {
        if (t < 256) {
            int row = t >> 3, c16 = t & 7;
            const __half* s = g_qh + ((size_t)bh * 1024 + i0 + row) * 64 + c16 * 8;
            CP_ASYNC16(sb + Q_OFF + (uint32_t)row * 144 + c16 * 16, s);
        }
        CP_COMMIT();
    };

    const size_t bhrow = (size_t)bh * 1024;

    issue_q();
    issue_tile(g_kh, bhrow, sb + KV_OFF);
    issue_tile(g_kh, bhrow + 64, sb + KV_OFF + KV_BUF);

    // ========= unified scores (g<16) + bias window (g>=16), 20 tiles =======
    {
        const int wq = wid >> 3;
        const int wk = wid & 7;
        uint32_t qhf[4][4];

        for (int g = 0; g < 20; g++) {
            if (g < 19) { CP_WAIT(1); } else { CP_WAIT(0); }
            __syncthreads();
            if (g + 2 < 20) {
                int tt = g + 2;
                uint32_t dst = sb + KV_OFF + (uint32_t)(tt % 3) * KV_BUF;
                if (tt < 16) issue_tile(g_kh, bhrow + (size_t)tt * 64, dst);
                else         issue_tile(g_rkh, (size_t)(tt - 16) * 64, dst);
            }

            if (g == 0) {
#pragma unroll
                for (int s = 0; s < 4; s++) {
                    uint32_t a = sb + Q_OFF + (uint32_t)(wq * 16 + (lane & 15)) * 144
                               + (((lane >> 4) << 3) + s * 16) * 2;
                    LDMX4(qhf[s][0], qhf[s][1], qhf[s][2], qhf[s][3], a);
                }
            }

            float a1[4] = {0.f,0.f,0.f,0.f};
            const uint32_t kb = sb + KV_OFF + (uint32_t)(g % 3) * KV_BUF;
#pragma unroll
            for (int s = 0; s < 4; s++) {
                uint32_t addr = kb + (uint32_t)(wk * 8 + (lane & 7)) * 144
                              + ((((lane >> 3) & 1) * 8) + s * 16) * 2;
                uint32_t bh2[2];
                LDMX2(bh2[0], bh2[1], addr);
                MMA16816(a1, qhf[s], bh2);
            }
            int row = wq * 16 + (lane >> 2);
            if (g < 16) {
                int col = g * 64 + wk * 8 + (lane & 3) * 2;
                *(float2*)(sm + SS_OFF + (uint32_t)row * SSP + col * 4) =
                    make_float2(a1[0], a1[1]);
                *(float2*)(sm + SS_OFF + (uint32_t)(row + 8) * SSP + col * 4) =
                    make_float2(a1[2], a1[3]);
            } else {
                int col = (g - 16) * 64 + wk * 8 + (lane & 3) * 2;
                *(float2*)(sm + WR_OFF + (uint32_t)row * WRP + col * 4) =
                    make_float2(a1[0], a1[1]);
                *(float2*)(sm + WR_OFF + (uint32_t)(row + 8) * WRP + col * 4) =
                    make_float2(a1[2], a1[3]);
            }
        }
    }
    __syncthreads();

    // prefetch v tiles 0,1,2 -> overlap softmax
    issue_tile(g_vh, bhrow,       sb + KV_OFF + 2u * KV_BUF);
    issue_tile(g_vh, bhrow + 64,  sb + KV_OFF);
    issue_tile(g_vh, bhrow + 128, sb + KV_OFF + KV_BUF);

    // ================= softmax (fused bias, reg-resident), 2 rows/warp =====
    const float* rk256 = rel_k + 256 * 64;
    for (int rr = 0; rr < 2; rr++) {
        const int row = wid * 2 + rr;
        const int i = i0 + row;
        const float* rp = (const float*)(sm + SS_OFF + (uint32_t)row * SSP);
        const float* qwr = (const float*)(sm + WR_OFF + (uint32_t)row * WRP);

        // fixup: v256 = q_row . rel_k[256]   (fp32, q hi)
        float v256;
        {
            uint32_t qb = sb + Q_OFF + (uint32_t)row * 144;
            uint16_t qh0, qh1;
            asm volatile("ld.shared.b16 %0, [%1];" : "=h"(qh0) : "r"(qb + lane * 2));
            asm volatile("ld.shared.b16 %0, [%1];" : "=h"(qh1) : "r"(qb + (lane + 32) * 2));
            v256 = __half2float(*(__half*)&qh0) * rk256[lane]
                 + __half2float(*(__half*)&qh1) * rk256[lane + 32];
#pragma unroll
            for (int o = 16; o > 0; o >>= 1) v256 += __shfl_xor_sync(0xffffffffu, v256, o);
        }

        float tmp[32];
#pragma unroll
        for (int kk = 0; kk < 32; kk++) {
            int j = lane + kk * 32;
            int rel = j - i;
            rel = rel < -128 ? -128 : (rel > 128 ? 128 : rel);
            float b = (rel == 128) ? v256 : qwr[rel + 128];
            tmp[kk] = (rp[j] + b) * 0.125f;
        }
        float mx = -1e30f;
#pragma unroll
        for (int kk = 0; kk < 32; kk++) mx = fmaxf(mx, tmp[kk]);
#pragma unroll
        for (int o = 16; o > 0; o >>= 1) mx = fmaxf(mx, __shfl_xor_sync(0xffffffffu, mx, o));
        float sum = 0.f;
#pragma unroll
        for (int kk = 0; kk < 32; kk++) { tmp[kk] = __expf(tmp[kk] - mx); sum += tmp[kk]; }
#pragma unroll
        for (int o = 16; o > 0; o >>= 1) sum += __shfl_xor_sync(0xffffffffu, sum, o);
        const float inv = 1.f / sum;

        __syncwarp();   // all qw reads of this row done before overwrite
        uint32_t* wrz = (uint32_t*)(sm + WR_OFF + (uint32_t)row * WRP);
        for (int idx = lane; idx < 136; idx += 32) wrz[idx] = 0u;
        __syncwarp();

        __half* wh_ = (__half*)wrz;          // buckets [0,272) at bytes [0,544)
        float s0 = 0.f, s2 = 0.f;
#pragma unroll
        for (int kk = 0; kk < 32; kk++) {
            int j = lane + kk * 32;
            float w = tmp[kk] * inv;
            __half h = __float2half_rn(w);
            *(__half*)(sm + SS_OFF + (uint32_t)row * SSP + j * 2) = h;
            int dlt = j - i;
            if (dlt <= -128)      s0 += w;
            else if (dlt >= 128)  s2 += w;
            else wh_[dlt + 128] = h;
        }
#pragma unroll
        for (int o = 16; o > 0; o >>= 1) s0 += __shfl_xor_sync(0xffffffffu, s0, o);
#pragma unroll
        for (int o = 16; o > 0; o >>= 1) s2 += __shfl_xor_sync(0xffffffffu, s2, o);
        __syncwarp();
        if (lane == 0) {
            wh_[0] = __float2half_rn(s0);
            *(float*)(sm + WR_OFF + (uint32_t)row * WRP + 544) = s2;   // gap slot
        }
    }

    // ================= PV: 20 uniform tiles, warp (wm2, wn2 n32, ws4) ======
    const int wm = wid >> 3;
    const int wn = (wid >> 2) & 1;
    const int ws = wid & 3;

    auto issue_pv = [&](int tt) {
        uint32_t dst = sb + KV_OFF + (uint32_t)((tt + 2) % 3) * KV_BUF;
        if (tt < 16) issue_tile(g_vh, bhrow + (size_t)tt * 64, dst);
        else         issue_tile(g_rvh, (size_t)(tt - 16) * 64, dst);
    };

    float o1[4][4];
#pragma unroll
    for (int nf = 0; nf < 4; nf++)
#pragma unroll
        for (int r = 0; r < 4; r++) o1[nf][r] = 0.f;

    for (int vt = 0; vt < 20; vt++) {
        if (vt == 0)       { CP_WAIT(2); }
        else if (vt < 19)  { CP_WAIT(1); }
        else               { CP_WAIT(0); }
        __syncthreads();
        if (vt >= 1 && vt + 2 <= 19) issue_pv(vt + 2);

        const uint32_t vb = sb + KV_OFF + (uint32_t)((vt + 2) % 3) * KV_BUF;
        uint32_t awh[4];
        if (vt < 16) {
            uint32_t aaddr = sb + SS_OFF + (uint32_t)(wm * 16 + (lane & 15)) * SSP
                           + (((lane >> 4) << 3) + vt * 64 + ws * 16) * 2;
            LDMX4(awh[0], awh[1], awh[2], awh[3], aaddr);
        } else {
            uint32_t abase = sb + WR_OFF + (uint32_t)(wm * 16 + (lane & 15)) * WRP;
            uint32_t acol = (((lane >> 4) << 3) + (vt - 16) * 64 + ws * 16) * 2;
            LDMX4(awh[0], awh[1], awh[2], awh[3], abase + acol);
        }
        uint32_t brow = (uint32_t)(ws * 16 + (lane & 7) + ((lane >> 3) & 1) * 8);
        uint32_t bcol = (uint32_t)(wn * 32 + ((lane >> 4) << 3)) * 2;
        uint32_t bvh[8];
        LDMX4T(bvh[0], bvh[1], bvh[2], bvh[3], vb + brow * 144 + bcol);
        LDMX4T(bvh[4], bvh[5], bvh[6], bvh[7], vb + brow * 144 + bcol + 32);
#pragma unroll
        for (int nf = 0; nf < 4; nf++)
            MMA16816(o1[nf], awh, (&bvh[nf * 2]));
    }

    // 4-way cross-warp k-reduction over ws; bucket-256 fixup; emit fp16 hi
    __syncthreads();
    float* red = (float*)(sm + KV_OFF);
    const int widx = wm * 2 + wn;
    if (ws != 0) {
#pragma unroll
        for (int nf = 0; nf < 4; nf++)
            *(float4*)&red[((((widx * 3 + (ws - 1)) * 4) + nf) * 32 + lane) * 4] =
                make_float4(o1[nf][0], o1[nf][1], o1[nf][2], o1[nf][3]);
    }
    __syncthreads();
    if (ws == 0) {
        const int bb = bh >> 4, h = bh & 15;
        const int rloc = wm * 16 + (lane >> 2);
        const int row = i0 + rloc;
        const float s2a = *(const float*)(sm + WR_OFF + (uint32_t)rloc * WRP + 544);
        const float s2b = *(const float*)(sm + WR_OFF + (uint32_t)(rloc + 8) * WRP + 544);
        const float* rv256 = rel_v + 256 * 64;
#pragma unroll
        for (int nf = 0; nf < 4; nf++) {
            float f0 = o1[nf][0], f1 = o1[nf][1], f2 = o1[nf][2], f3 = o1[nf][3];
#pragma unroll
            for (int e = 0; e < 3; e++) {
                float4 v = *(const float4*)&red[((((widx * 3 + e) * 4) + nf) * 32 + lane) * 4];
                f0 += v.x; f1 += v.y; f2 += v.z; f3 += v.w;
            }
            int dd = wn * 32 + nf * 8 + (lane & 3) * 2;
            float2 rv = *(const float2*)(rv256 + dd);
            f0 += s2a * rv.x; f1 += s2a * rv.y;
            f2 += s2b * rv.x; f3 += s2b * rv.y;
            int d = h * 64 + dd;
            size_t off0 = ((size_t)bb * 1024 + row) * 1024 + d;
            size_t off1 = off0 + 8 * 1024;
            *(__half2*)(g_xh + off0) = __halves2half2(__float2half_rn(f0), __float2half_rn(f1));
            *(__half2*)(g_xh + off1) = __halves2half2(__float2half_rn(f2), __float2half_rn(f3));
        }
    }
}

// ---------------------------------------------------------------------------
extern "C" void kernel_launch(void* const* d_in, const int* in_sizes, int n_in,
                              void* d_out, int out_size)
{
    const float* x     = (const float*)d_in[0];
    const float* Wq    = (const float*)d_in[1];
    const float* bq    = (const float*)d_in[2];
    const float* Wk    = (const float*)d_in[3];
    const float* bk    = (const float*)d_in[4];
    const float* Wv    = (const float*)d_in[5];
    const float* bv    = (const float*)d_in[6];
    const float* Wo    = (const float*)d_in[7];
    const float* bo    = (const float*)d_in[8];
    const float* rel_k = (const float*)d_in[9];
    const float* rel_v = (const float*)d_in[10];

    cudaFuncSetAttribute(gemm_qkv, cudaFuncAttributeMaxDynamicSharedMemorySize, GEMM_SMEM_QKV);
    cudaFuncSetAttribute(gemm_out, cudaFuncAttributeMaxDynamicSharedMemorySize, GEMM_SMEM_OUT);
    cudaFuncSetAttribute(attn_mma, cudaFuncAttributeMaxDynamicSharedMemorySize, ATTN_SMEM);

    dim3 blk(256);

    // unified prep: x h+l split + weight hi splits + rel tables
    prep_all<<<3136, blk>>>(x, Wq, Wk, Wv, Wo, rel_k, rel_v);

    // merged QKV projections (fp16, (xh+xl)*Wh)
    gemm_qkv<<<dim3(Dd / 128, NROW / 128, 3), blk, GEMM_SMEM_QKV>>>(bq, bk, bv);

    // attention core
    attn_mma<<<dim3(Ss / 32, Bv * Hh), 512, ATTN_SMEM>>>(rel_k, rel_v);

    // output projection -> d_out (single product)
    gemm_out<<<dim3(Dd / 128, NROW / 128), blk, GEMM_SMEM_OUT>>>(bo, (float*)d_out);
}

// round 17
// speedup vs baseline: 1.9942x; 1.1923x over previous
#include <cuda_runtime.h>
#include <cuda_fp16.h>
#include <cstdint>

#define Bv 4
#define Hh 16
#define Ss 1024
#define Dd 1024
#define HDd 64
#define NROW (Bv*Ss)    // 4096
#define BHS (Bv*Hh*Ss)  // 65536

// ---------------- scratch (device globals: allocation-free) ----------------
__device__ __half g_qh[BHS * HDd];
__device__ __half g_kh[BHS * HDd];
__device__ __half g_vh[BHS * HDd];
__device__ __half g_rvh[256 * 64];
__device__ __half g_rkh[256 * 64];
__device__ __half g_xh[(size_t)NROW * Dd];
__device__ __half g_wh4[4][(size_t)Dd * Dd];   // weights hi only: q,k,v,o

// ====================== PTX helpers (family-portable only) ======================
__device__ __forceinline__ uint32_t smem_u32(const void* p) {
    uint32_t a;
    asm("{ .reg .u64 t; cvta.to.shared.u64 t, %1; cvt.u32.u64 %0, t; }" : "=r"(a) : "l"(p));
    return a;
}

#define LDMX4(r0, r1, r2, r3, addr) \
    asm volatile("ldmatrix.sync.aligned.m8n8.x4.shared.b16 {%0,%1,%2,%3}, [%4];" \
                 : "=r"(r0), "=r"(r1), "=r"(r2), "=r"(r3) : "r"(addr))

#define LDMX2(r0, r1, addr) \
    asm volatile("ldmatrix.sync.aligned.m8n8.x2.shared.b16 {%0,%1}, [%2];" \
                 : "=r"(r0), "=r"(r1) : "r"(addr))

#define LDMX4T(r0, r1, r2, r3, addr) \
    asm volatile("ldmatrix.sync.aligned.m8n8.x4.trans.shared.b16 {%0,%1,%2,%3}, [%4];" \
                 : "=r"(r0), "=r"(r1), "=r"(r2), "=r"(r3) : "r"(addr))

#define MMA16816(c, a, b) \
    asm volatile("mma.sync.aligned.m16n8k16.row.col.f32.f16.f16.f32 " \
                 "{%0,%1,%2,%3}, {%4,%5,%6,%7}, {%8,%9}, {%0,%1,%2,%3};" \
                 : "+f"((c)[0]), "+f"((c)[1]), "+f"((c)[2]), "+f"((c)[3]) \
                 : "r"((a)[0]), "r"((a)[1]), "r"((a)[2]), "r"((a)[3]), \
                   "r"((b)[0]), "r"((b)[1]))

#define CP_ASYNC16(s, g) \
    asm volatile("cp.async.cg.shared.global [%0], [%1], 16;" :: "r"(s), "l"(g))
#define CP_COMMIT() asm volatile("cp.async.commit_group;" ::: "memory")
#define CP_WAIT(n)  asm volatile("cp.async.wait_group %0;" :: "n"(n) : "memory")

// ---------------------------------------------------------------------------
// unified prep: [0,1024) x hi; [1024,2048) weights hi; [2048,2112) rel
// ---------------------------------------------------------------------------
__global__ void prep_all(const float* __restrict__ x,
                         const float* __restrict__ W0, const float* __restrict__ W1,
                         const float* __restrict__ W2, const float* __restrict__ W3,
                         const float* __restrict__ rel_k, const float* __restrict__ rel_v)
{
    int b = blockIdx.x, t = threadIdx.x;
    if (b < 2048) {
        const float* in;
        __half* hi;
        int i;
        if (b < 1024) {
            in = x; hi = g_xh; i = b * 1024 + t;
        } else {
            int id = b - 1024;
            int z = id >> 8;
            in = (z == 0 ? W0 : z == 1 ? W1 : z == 2 ? W2 : W3);
            hi = g_wh4[z];
            i = (id & 255) * 1024 + t;
        }
#pragma unroll
        for (int rep = 0; rep < 4; rep++, i += 256) {
            float4 v = ((const float4*)in)[i];
            ((__half2*)hi)[i * 2 + 0] = __halves2half2(__float2half_rn(v.x), __float2half_rn(v.y));
            ((__half2*)hi)[i * 2 + 1] = __halves2half2(__float2half_rn(v.z), __float2half_rn(v.w));
        }
    } else {
        int idx = (b - 2048) * 256 + t;
        g_rkh[idx] = __float2half_rn(rel_k[idx]);
        g_rvh[idx] = __float2half_rn(rel_v[idx]);
    }
}

// ---------------------------------------------------------------------------
// GEMM body: 128x128 tile, BK=32, 8 warps (wm2 x wn4, each 64x32),
// single fp16 product Ah*Bh, 2 smem mats/buffer, 2 CTAs/SM.
// ---------------------------------------------------------------------------
#define SPB 80
#define MAT_SM (128 * SPB)          // 10240
#define BUF_SM (2 * MAT_SM)         // 20480
#define GEMM_SMEM (2 * BUF_SM)      // 40960

__device__ __forceinline__ void gemm_body(
    char* sm,
    const __half* __restrict__ Ah_, const __half* __restrict__ Bh_,
    const float* __restrict__ bias, float* __restrict__ Cf,
    __half* __restrict__ Ch, int headed)
{
    const uint32_t sb = smem_u32(sm);
    const int t    = threadIdx.x;
    const int wid  = t >> 5;
    const int lane = t & 31;
    const int m0 = blockIdx.y * 128;
    const int n0 = blockIdx.x * 128;
    const int wm = wid >> 2;
    const int wn = wid & 3;

    const char* gb0 = (const char*)(Ah_ + (size_t)m0 * 1024);
    const char* gb1 = (const char*)(Bh_ + (size_t)n0 * 1024);

    auto issue = [&](int chunk, int buf) {
#pragma unroll
        for (int it = 0; it < 4; it++) {
            int id = t + it * 256;
            int mat = id >> 9;
            int row = (id >> 2) & 127;
            int c16 = id & 3;
            const char* g = (mat ? gb1 : gb0) + (size_t)row * 2048 + chunk * 64 + c16 * 16;
            uint32_t sa = sb + buf * BUF_SM + mat * MAT_SM + row * SPB + c16 * 16;
            CP_ASYNC16(sa, g);
        }
        CP_COMMIT();
    };

    float acc[4][4][4];
#pragma unroll
    for (int i = 0; i < 4; i++)
#pragma unroll
        for (int j = 0; j < 4; j++)
#pragma unroll
            for (int r = 0; r < 4; r++) acc[i][j][r] = 0.f;

    issue(0, 0);
    for (int c = 0; c < 32; c++) {
        const int buf = c & 1;
        CP_WAIT(0);
        __syncthreads();
        if (c + 1 < 32) issue(c + 1, buf ^ 1);

        const uint32_t Ahb = sb + buf * BUF_SM;
        const uint32_t Bhb = Ahb + MAT_SM;

#pragma unroll
        for (int s = 0; s < 2; s++) {
            uint32_t ah[4][4];
            const int arow = wm * 64 + (lane & 15);
            const int acolB = (((lane >> 4) << 3) + s * 16) * 2;
#pragma unroll
            for (int mf = 0; mf < 4; mf++) {
                uint32_t ad = Ahb + (uint32_t)(arow + mf * 16) * SPB + acolB;
                LDMX4(ah[mf][0], ah[mf][1], ah[mf][2], ah[mf][3], ad);
            }
            uint32_t bh[4][2];
            const int brow = wn * 32 + (lane & 7) + ((lane >> 4) << 3);
            const int bcolB = ((((lane >> 3) & 1) << 3) + s * 16) * 2;
#pragma unroll
            for (int g = 0; g < 2; g++) {
                uint32_t r0, r1, r2, r3;
                uint32_t bd = Bhb + (uint32_t)(brow + g * 16) * SPB + bcolB;
                LDMX4(r0, r1, r2, r3, bd);
                bh[g * 2][0] = r0; bh[g * 2][1] = r1;
                bh[g * 2 + 1][0] = r2; bh[g * 2 + 1][1] = r3;
            }
#pragma unroll
            for (int mf = 0; mf < 4; mf++)
#pragma unroll
                for (int nf = 0; nf < 4; nf++)
                    MMA16816(acc[mf][nf], ah[mf], bh[nf]);
        }
    }

#pragma unroll
    for (int mf = 0; mf < 4; mf++) {
#pragma unroll
        for (int nf = 0; nf < 4; nf++) {
            int m = m0 + wm * 64 + mf * 16 + (lane >> 2);
            int n = n0 + wn * 32 + nf * 8 + (lane & 3) * 2;
            float p0 = acc[mf][nf][0] + bias[n];
            float p1 = acc[mf][nf][1] + bias[n + 1];
            float p2 = acc[mf][nf][2] + bias[n];
            float p3 = acc[mf][nf][3] + bias[n + 1];
            size_t off0, off1;
            if (headed) {
                int h = n >> 6, d = n & 63;
                int bb = m >> 10, s1 = m & 1023;
                off0 = ((((size_t)bb * Hh + h) << 10) + s1) * HDd + d;
                off1 = ((((size_t)bb * Hh + h) << 10) + s1 + 8) * HDd + d;
            } else {
                off0 = (size_t)m * 1024 + n;
                off1 = (size_t)(m + 8) * 1024 + n;
            }
            if (Cf) {
                *(float2*)(Cf + off0) = make_float2(p0, p1);
                *(float2*)(Cf + off1) = make_float2(p2, p3);
            }
            if (Ch) {
                *(__half2*)(Ch + off0) = __halves2half2(__float2half_rn(p0), __float2half_rn(p1));
                *(__half2*)(Ch + off1) = __halves2half2(__float2half_rn(p2), __float2half_rn(p3));
            }
        }
    }
}

__global__ __launch_bounds__(256, 2)
void gemm_qkv(const float* __restrict__ bq, const float* __restrict__ bk,
              const float* __restrict__ bv)
{
    extern __shared__ char sm[];
    int z = blockIdx.z;
    const float* bias = (z == 0 ? bq : z == 1 ? bk : bv);
    __half* Ch = (z == 0 ? g_qh : z == 1 ? g_kh : g_vh);
    gemm_body(sm, g_xh, g_wh4[z], bias, nullptr, Ch, 1);
}

__global__ __launch_bounds__(256, 2)
void gemm_out(const float* __restrict__ bo, float* __restrict__ Cf)
{
    extern __shared__ char sm[];
    gemm_body(sm, g_xh, g_wh4[3], bo, Cf, nullptr, 0);
}

// ---------------------------------------------------------------------------
// MMA attention core (fp16, single-product chains). Unchanged from R16.
// smem: Q 4608 | KV 3x9216 | ss 32x4112 | wr 32x1104  = 199168 B
// ---------------------------------------------------------------------------
#define SSP  4112u
#define WRP  1104u
#define Q_OFF   0u
#define KV_OFF  4608u
#define KV_BUF  9216u
#define SS_OFF  32256u
#define WR_OFF  163840u
#define ATTN_SMEM 199168

__global__ __launch_bounds__(512, 1)
void attn_mma(const float* __restrict__ rel_k, const float* __restrict__ rel_v)
{
    extern __shared__ char sm[];
    const uint32_t sb = smem_u32(sm);
    const int t = threadIdx.x, lane = t & 31, wid = t >> 5;
    const int bh = blockIdx.y;
    const int i0 = blockIdx.x * 32;

    auto issue_tile = [&](const __half* src, size_t row0, uint32_t dst) {
        int row = t >> 3, c16 = t & 7;
        CP_ASYNC16(dst + (uint32_t)row * 144 + c16 * 16,
                   src + (row0 + row) * 64 + c16 * 8);
        CP_COMMIT();
    };
    auto issue_q = [&]() {
        if (t < 256) {
            int row = t >> 3, c16 = t & 7;
            const __half* s = g_qh + ((size_t)bh * 1024 + i0 + row) * 64 + c16 * 8;
            CP_ASYNC16(sb + Q_OFF + (uint32_t)row * 144 + c16 * 16, s);
        }
        CP_COMMIT();
    };

    const size_t bhrow = (size_t)bh * 1024;

    issue_q();
    issue_tile(g_kh, bhrow, sb + KV_OFF);
    issue_tile(g_kh, bhrow + 64, sb + KV_OFF + KV_BUF);

    // ========= unified scores (g<16) + bias window (g>=16), 20 tiles =======
    {
        const int wq = wid >> 3;
        const int wk = wid & 7;
        uint32_t qhf[4][4];

        for (int g = 0; g < 20; g++) {
            if (g < 19) { CP_WAIT(1); } else { CP_WAIT(0); }
            __syncthreads();
            if (g + 2 < 20) {
                int tt = g + 2;
                uint32_t dst = sb + KV_OFF + (uint32_t)(tt % 3) * KV_BUF;
                if (tt < 16) issue_tile(g_kh, bhrow + (size_t)tt * 64, dst);
                else         issue_tile(g_rkh, (size_t)(tt - 16) * 64, dst);
            }

            if (g == 0) {
#pragma unroll
                for (int s = 0; s < 4; s++) {
                    uint32_t a = sb + Q_OFF + (uint32_t)(wq * 16 + (lane & 15)) * 144
                               + (((lane >> 4) << 3) + s * 16) * 2;
                    LDMX4(qhf[s][0], qhf[s][1], qhf[s][2], qhf[s][3], a);
                }
            }

            float a1[4] = {0.f,0.f,0.f,0.f};
            const uint32_t kb = sb + KV_OFF + (uint32_t)(g % 3) * KV_BUF;
#pragma unroll
            for (int s = 0; s < 4; s++) {
                uint32_t addr = kb + (uint32_t)(wk * 8 + (lane & 7)) * 144
                              + ((((lane >> 3) & 1) * 8) + s * 16) * 2;
                uint32_t bh2[2];
                LDMX2(bh2[0], bh2[1], addr);
                MMA16816(a1, qhf[s], bh2);
            }
            int row = wq * 16 + (lane >> 2);
            if (g < 16) {
                int col = g * 64 + wk * 8 + (lane & 3) * 2;
                *(float2*)(sm + SS_OFF + (uint32_t)row * SSP + col * 4) =
                    make_float2(a1[0], a1[1]);
                *(float2*)(sm + SS_OFF + (uint32_t)(row + 8) * SSP + col * 4) =
                    make_float2(a1[2], a1[3]);
            } else {
                int col = (g - 16) * 64 + wk * 8 + (lane & 3) * 2;
                *(float2*)(sm + WR_OFF + (uint32_t)row * WRP + col * 4) =
                    make_float2(a1[0], a1[1]);
                *(float2*)(sm + WR_OFF + (uint32_t)(row + 8) * WRP + col * 4) =
                    make_float2(a1[2], a1[3]);
            }
        }
    }
    __syncthreads();

    // prefetch v tiles 0,1,2 -> overlap softmax
    issue_tile(g_vh, bhrow,       sb + KV_OFF + 2u * KV_BUF);
    issue_tile(g_vh, bhrow + 64,  sb + KV_OFF);
    issue_tile(g_vh, bhrow + 128, sb + KV_OFF + KV_BUF);

    // ================= softmax (fused bias, reg-resident), 2 rows/warp =====
    const float* rk256 = rel_k + 256 * 64;
    for (int rr = 0; rr < 2; rr++) {
        const int row = wid * 2 + rr;
        const int i = i0 + row;
        const float* rp = (const float*)(sm + SS_OFF + (uint32_t)row * SSP);
        const float* qwr = (const float*)(sm + WR_OFF + (uint32_t)row * WRP);

        // fixup: v256 = q_row . rel_k[256]   (fp32, q hi)
        float v256;
        {
            uint32_t qb = sb + Q_OFF + (uint32_t)row * 144;
            uint16_t qh0, qh1;
            asm volatile("ld.shared.b16 %0, [%1];" : "=h"(qh0) : "r"(qb + lane * 2));
            asm volatile("ld.shared.b16 %0, [%1];" : "=h"(qh1) : "r"(qb + (lane + 32) * 2));
            v256 = __half2float(*(__half*)&qh0) * rk256[lane]
                 + __half2float(*(__half*)&qh1) * rk256[lane + 32];
#pragma unroll
            for (int o = 16; o > 0; o >>= 1) v256 += __shfl_xor_sync(0xffffffffu, v256, o);
        }

        float tmp[32];
#pragma unroll
        for (int kk = 0; kk < 32; kk++) {
            int j = lane + kk * 32;
            int rel = j - i;
            rel = rel < -128 ? -128 : (rel > 128 ? 128 : rel);
            float b = (rel == 128) ? v256 : qwr[rel + 128];
            tmp[kk] = (rp[j] + b) * 0.125f;
        }
        float mx = -1e30f;
#pragma unroll
        for (int kk = 0; kk < 32; kk++) mx = fmaxf(mx, tmp[kk]);
#pragma unroll
        for (int o = 16; o > 0; o >>= 1) mx = fmaxf(mx, __shfl_xor_sync(0xffffffffu, mx, o));
        float sum = 0.f;
#pragma unroll
        for (int kk = 0; kk < 32; kk++) { tmp[kk] = __expf(tmp[kk] - mx); sum += tmp[kk]; }
#pragma unroll
        for (int o = 16; o > 0; o >>= 1) sum += __shfl_xor_sync(0xffffffffu, sum, o);
        const float inv = 1.f / sum;

        __syncwarp();   // all qw reads of this row done before overwrite
        uint32_t* wrz = (uint32_t*)(sm + WR_OFF + (uint32_t)row * WRP);
        for (int idx = lane; idx < 136; idx += 32) wrz[idx] = 0u;
        __syncwarp();

        __half* wh_ = (__half*)wrz;          // buckets [0,272) at bytes [0,544)
        float s0 = 0.f, s2 = 0.f;
#pragma unroll
        for (int kk = 0; kk < 32; kk++) {
            int j = lane + kk * 32;
            float w = tmp[kk] * inv;
            __half h = __float2half_rn(w);
            *(__half*)(sm + SS_OFF + (uint32_t)row * SSP + j * 2) = h;
            int dlt = j - i;
            if (dlt <= -128)      s0 += w;
            else if (dlt >= 128)  s2 += w;
            else wh_[dlt + 128] = h;
        }
#pragma unroll
        for (int o = 16; o > 0; o >>= 1) s0 += __shfl_xor_sync(0xffffffffu, s0, o);
#pragma unroll
        for (int o = 16; o > 0; o >>= 1) s2 += __shfl_xor_sync(0xffffffffu, s2, o);
        __syncwarp();
        if (lane == 0) {
            wh_[0] = __float2half_rn(s0);
            *(float*)(sm + WR_OFF + (uint32_t)row * WRP + 544) = s2;   // gap slot
        }
    }

    // ================= PV: 20 uniform tiles, warp (wm2, wn2 n32, ws4) ======
    const int wm = wid >> 3;
    const int wn = (wid >> 2) & 1;
    const int ws = wid & 3;

    auto issue_pv = [&](int tt) {
        uint32_t dst = sb + KV_OFF + (uint32_t)((tt + 2) % 3) * KV_BUF;
        if (tt < 16) issue_tile(g_vh, bhrow + (size_t)tt * 64, dst);
        else         issue_tile(g_rvh, (size_t)(tt - 16) * 64, dst);
    };

    float o1[4][4];
#pragma unroll
    for (int nf = 0; nf < 4; nf++)
#pragma unroll
        for (int r = 0; r < 4; r++) o1[nf][r] = 0.f;

    for (int vt = 0; vt < 20; vt++) {
        if (vt == 0)       { CP_WAIT(2); }
        else if (vt < 19)  { CP_WAIT(1); }
        else               { CP_WAIT(0); }
        __syncthreads();
        if (vt >= 1 && vt + 2 <= 19) issue_pv(vt + 2);

        const uint32_t vb = sb + KV_OFF + (uint32_t)((vt + 2) % 3) * KV_BUF;
        uint32_t awh[4];
        if (vt < 16) {
            uint32_t aaddr = sb + SS_OFF + (uint32_t)(wm * 16 + (lane & 15)) * SSP
                           + (((lane >> 4) << 3) + vt * 64 + ws * 16) * 2;
            LDMX4(awh[0], awh[1], awh[2], awh[3], aaddr);
        } else {
            uint32_t abase = sb + WR_OFF + (uint32_t)(wm * 16 + (lane & 15)) * WRP;
            uint32_t acol = (((lane >> 4) << 3) + (vt - 16) * 64 + ws * 16) * 2;
            LDMX4(awh[0], awh[1], awh[2], awh[3], abase + acol);
        }
        uint32_t brow = (uint32_t)(ws * 16 + (lane & 7) + ((lane >> 3) & 1) * 8);
        uint32_t bcol = (uint32_t)(wn * 32 + ((lane >> 4) << 3)) * 2;
        uint32_t bvh[8];
        LDMX4T(bvh[0], bvh[1], bvh[2], bvh[3], vb + brow * 144 + bcol);
        LDMX4T(bvh[4], bvh[5], bvh[6], bvh[7], vb + brow * 144 + bcol + 32);
#pragma unroll
        for (int nf = 0; nf < 4; nf++)
            MMA16816(o1[nf], awh, (&bvh[nf * 2]));
    }

    // 4-way cross-warp k-reduction over ws; bucket-256 fixup; emit fp16 hi
    __syncthreads();
    float* red = (float*)(sm + KV_OFF);
    const int widx = wm * 2 + wn;
    if (ws != 0) {
#pragma unroll
        for (int nf = 0; nf < 4; nf++)
            *(float4*)&red[((((widx * 3 + (ws - 1)) * 4) + nf) * 32 + lane) * 4] =
                make_float4(o1[nf][0], o1[nf][1], o1[nf][2], o1[nf][3]);
    }
    __syncthreads();
    if (ws == 0) {
        const int bb = bh >> 4, h = bh & 15;
        const int rloc = wm * 16 + (lane >> 2);
        const int row = i0 + rloc;
        const float s2a = *(const float*)(sm + WR_OFF + (uint32_t)rloc * WRP + 544);
        const float s2b = *(const float*)(sm + WR_OFF + (uint32_t)(rloc + 8) * WRP + 544);
        const float* rv256 = rel_v + 256 * 64;
#pragma unroll
        for (int nf = 0; nf < 4; nf++) {
            float f0 = o1[nf][0], f1 = o1[nf][1], f2 = o1[nf][2], f3 = o1[nf][3];
#pragma unroll
            for (int e = 0; e < 3; e++) {
                float4 v = *(const float4*)&red[((((widx * 3 + e) * 4) + nf) * 32 + lane) * 4];
                f0 += v.x; f1 += v.y; f2 += v.z; f3 += v.w;
            }
            int dd = wn * 32 + nf * 8 + (lane & 3) * 2;
            float2 rv = *(const float2*)(rv256 + dd);
            f0 += s2a * rv.x; f1 += s2a * rv.y;
            f2 += s2b * rv.x; f3 += s2b * rv.y;
            int d = h * 64 + dd;
            size_t off0 = ((size_t)bb * 1024 + row) * 1024 + d;
            size_t off1 = off0 + 8 * 1024;
            *(__half2*)(g_xh + off0) = __halves2half2(__float2half_rn(f0), __float2half_rn(f1));
            *(__half2*)(g_xh + off1) = __halves2half2(__float2half_rn(f2), __float2half_rn(f3));
        }
    }
}

// ---------------------------------------------------------------------------
extern "C" void kernel_launch(void* const* d_in, const int* in_sizes, int n_in,
                              void* d_out, int out_size)
{
    const float* x     = (const float*)d_in[0];
    const float* Wq    = (const float*)d_in[1];
    const float* bq    = (const float*)d_in[2];
    const float* Wk    = (const float*)d_in[3];
    const float* bk    = (const float*)d_in[4];
    const float* Wv    = (const float*)d_in[5];
    const float* bv    = (const float*)d_in[6];
    const float* Wo    = (const float*)d_in[7];
    const float* bo    = (const float*)d_in[8];
    const float* rel_k = (const float*)d_in[9];
    const float* rel_v = (const float*)d_in[10];

    cudaFuncSetAttribute(gemm_qkv, cudaFuncAttributeMaxDynamicSharedMemorySize, GEMM_SMEM);
    cudaFuncSetAttribute(gemm_out, cudaFuncAttributeMaxDynamicSharedMemorySize, GEMM_SMEM);
    cudaFuncSetAttribute(attn_mma, cudaFuncAttributeMaxDynamicSharedMemorySize, ATTN_SMEM);

    dim3 blk(256);

    // unified prep: x hi + weight hi + rel tables
    prep_all<<<2112, blk>>>(x, Wq, Wk, Wv, Wo, rel_k, rel_v);

    // merged QKV projections (fp16 single product)
    gemm_qkv<<<dim3(Dd / 128, NROW / 128, 3), blk, GEMM_SMEM>>>(bq, bk, bv);

    // attention core
    attn_mma<<<dim3(Ss / 32, Bv * Hh), 512, ATTN_SMEM>>>(rel_k, rel_v);

    // output projection -> d_out
    gemm_out<<<dim3(Dd / 128, NROW / 128), blk, GEMM_SMEM>>>(bo, (float*)d_out);
}